// round 1
// baseline (speedup 1.0000x reference)
#include <cuda_runtime.h>
#include <math.h>

#define T_SEQ  2048
#define HIDDEN 4096
#define NH     32
#define NKV    8
#define HD     128
#define Q_SIZE  (NH * HD)              // 4096
#define KV_SIZE (NKV * HD)             // 1024
#define QKV_N   (Q_SIZE + 2 * KV_SIZE) // 6144
#define SCALE   0.08838834764831845f   // 128^-0.5

// Scratch (no cudaMalloc allowed)
__device__ float g_qkv[(size_t)T_SEQ * QKV_N];   // ~50 MB
__device__ float g_attn[(size_t)T_SEQ * HIDDEN]; // ~32 MB

// ---------------------------------------------------------------------------
// SGEMM: C[M,N] = A[M,K] @ B[K,N], row-major fp32.
// 128x128 block tile, BK=8, 256 threads, 8x8 microtile per thread
// (split quadrants: rows {ty*4..+3, 64+ty*4..+3}, cols likewise for tx).
// ---------------------------------------------------------------------------
__global__ __launch_bounds__(256) void sgemm_kernel(
    const float* __restrict__ A, const float* __restrict__ B,
    float* __restrict__ C, int M, int N, int K)
{
    __shared__ float As[8][132];  // padded: conflict-free transposed stores
    __shared__ float Bs[8][128];

    const int tid = threadIdx.x;
    const int tx = tid & 15;     // 0..15 (cols)
    const int ty = tid >> 4;     // 0..15 (rows)
    const int m0 = blockIdx.y * 128;
    const int n0 = blockIdx.x * 128;

    const int a_row = tid >> 1;      // 0..127
    const int a_k4  = tid & 1;       // 0..1
    const int b_k   = tid >> 5;      // 0..7
    const int b_n4  = tid & 31;      // 0..31

    float acc[8][8];
    #pragma unroll
    for (int i = 0; i < 8; i++)
        #pragma unroll
        for (int j = 0; j < 8; j++) acc[i][j] = 0.f;

    for (int k0 = 0; k0 < K; k0 += 8) {
        // A tile 128x8 -> As[k][m] (transposed)
        float4 a = *(const float4*)&A[(size_t)(m0 + a_row) * K + k0 + a_k4 * 4];
        As[a_k4 * 4 + 0][a_row] = a.x;
        As[a_k4 * 4 + 1][a_row] = a.y;
        As[a_k4 * 4 + 2][a_row] = a.z;
        As[a_k4 * 4 + 3][a_row] = a.w;
        // B tile 8x128
        *(float4*)&Bs[b_k][b_n4 * 4] =
            *(const float4*)&B[(size_t)(k0 + b_k) * N + n0 + b_n4 * 4];
        __syncthreads();

        #pragma unroll
        for (int k = 0; k < 8; k++) {
            float ar[8], br[8];
            float4 t0 = *(const float4*)&As[k][ty * 4];
            float4 t1 = *(const float4*)&As[k][64 + ty * 4];
            ar[0]=t0.x; ar[1]=t0.y; ar[2]=t0.z; ar[3]=t0.w;
            ar[4]=t1.x; ar[5]=t1.y; ar[6]=t1.z; ar[7]=t1.w;
            float4 u0 = *(const float4*)&Bs[k][tx * 4];
            float4 u1 = *(const float4*)&Bs[k][64 + tx * 4];
            br[0]=u0.x; br[1]=u0.y; br[2]=u0.z; br[3]=u0.w;
            br[4]=u1.x; br[5]=u1.y; br[6]=u1.z; br[7]=u1.w;
            #pragma unroll
            for (int i = 0; i < 8; i++)
                #pragma unroll
                for (int j = 0; j < 8; j++)
                    acc[i][j] = fmaf(ar[i], br[j], acc[i][j]);
        }
        __syncthreads();
    }

    #pragma unroll
    for (int i = 0; i < 8; i++) {
        int row = m0 + ((i < 4) ? (ty * 4 + i) : (64 + ty * 4 + i - 4));
        float4 v0 = make_float4(acc[i][0], acc[i][1], acc[i][2], acc[i][3]);
        float4 v1 = make_float4(acc[i][4], acc[i][5], acc[i][6], acc[i][7]);
        *(float4*)&C[(size_t)row * N + n0 + tx * 4]      = v0;
        *(float4*)&C[(size_t)row * N + n0 + 64 + tx * 4] = v1;
    }
}

// ---------------------------------------------------------------------------
// RoPE (interleaved) applied in-place to Q and K regions of qkv.
// One block per token; threads cover (NH+NKV)*64 pairs.
// ---------------------------------------------------------------------------
__global__ __launch_bounds__(256) void rope_kernel(
    float* __restrict__ qkv, const int* __restrict__ positions)
{
    const int t = blockIdx.x;
    const float p = (float)positions[t];
    const int npairs = (NH + NKV) * (HD / 2);  // 2560

    for (int idx = threadIdx.x; idx < npairs; idx += blockDim.x) {
        const int head = idx >> 6;     // /64
        const int i = idx & 63;
        // inv_freq computed in double to minimize our-side error vs reference
        double e = (double)(2 * i) / (double)HD;
        float inv_freq = (float)pow(500000.0, -e);
        float ang = p * inv_freq;
        float s, c;
        sincosf(ang, &s, &c);

        size_t base;
        if (head < NH)
            base = (size_t)t * QKV_N + head * HD;
        else
            base = (size_t)t * QKV_N + Q_SIZE + (head - NH) * HD;

        float x1 = qkv[base + 2 * i];
        float x2 = qkv[base + 2 * i + 1];
        qkv[base + 2 * i]     = x1 * c - x2 * s;
        qkv[base + 2 * i + 1] = x2 * c + x1 * s;
    }
}

// ---------------------------------------------------------------------------
// Causal GQA flash attention.
// Block: 64 q-rows of one q-head. 256 threads: thread = (row = tid/4,
// slice = tid&3 owning 32 of the 128 head dims). Online softmax with lazy
// rescale; K/V tiles of 32 rows staged in smem.
// ---------------------------------------------------------------------------
#define AT_BM 64
#define AT_BN 32

__global__ __launch_bounds__(256) void attn_kernel(
    const float* __restrict__ qkv, float* __restrict__ attn_out)
{
    __shared__ float Ks[AT_BN][HD];
    __shared__ float Vs[AT_BN][HD];

    const int tid = threadIdx.x;
    const int r = tid >> 2;        // 0..63
    const int slice = tid & 3;     // 0..3
    const int h = blockIdx.y;      // 0..31
    const int kh = h >> 2;         // GQA: 4 q heads per kv head
    const int m0 = blockIdx.x * AT_BM;
    const int qrow = m0 + r;

    // Load q slice, pre-scaled by 1/sqrt(HD)
    float q[32];
    {
        const float* qp = qkv + (size_t)qrow * QKV_N + h * HD + slice * 32;
        #pragma unroll
        for (int d4 = 0; d4 < 8; d4++) {
            float4 v = *(const float4*)(qp + d4 * 4);
            q[d4*4+0] = v.x * SCALE; q[d4*4+1] = v.y * SCALE;
            q[d4*4+2] = v.z * SCALE; q[d4*4+3] = v.w * SCALE;
        }
    }

    float o[32];
    #pragma unroll
    for (int d = 0; d < 32; d++) o[d] = 0.f;
    float mval = -1e30f, lsum = 0.f;

    for (int n0 = 0; n0 < m0 + AT_BM; n0 += AT_BN) {
        // Cooperative K/V tile load: 32x128 each, 1024 float4s, 4 per thread
        #pragma unroll
        for (int i = 0; i < 4; i++) {
            int l4 = tid + i * 256;
            int row = l4 >> 5;
            int c4 = l4 & 31;
            const float* kp = qkv + (size_t)(n0 + row) * QKV_N + Q_SIZE + kh * HD;
            *(float4*)&Ks[row][c4 * 4] = *(const float4*)(kp + c4 * 4);
            *(float4*)&Vs[row][c4 * 4] = *(const float4*)(kp + KV_SIZE + c4 * 4);
        }
        __syncthreads();

        #pragma unroll 1
        for (int j = 0; j < AT_BN; j++) {
            // partial dot over this slice's 32 dims
            float s = 0.f;
            const float* krow = &Ks[j][slice * 32];
            #pragma unroll
            for (int d4 = 0; d4 < 8; d4++) {
                float4 kv4 = *(const float4*)(krow + d4 * 4);
                s = fmaf(q[d4*4+0], kv4.x, s);
                s = fmaf(q[d4*4+1], kv4.y, s);
                s = fmaf(q[d4*4+2], kv4.z, s);
                s = fmaf(q[d4*4+3], kv4.w, s);
            }
            // reduce across the 4 slice lanes (contiguous in warp)
            s += __shfl_xor_sync(0xffffffffu, s, 1);
            s += __shfl_xor_sync(0xffffffffu, s, 2);

            if (n0 + j > qrow) s = -1e30f;  // causal mask (positions = arange)

            if (s > mval) {   // lazy rescale: only on new max
                float sc = __expf(mval - s);
                lsum *= sc;
                #pragma unroll
                for (int d = 0; d < 32; d++) o[d] *= sc;
                mval = s;
            }
            float pw = __expf(s - mval);  // masked: exp(-huge) -> 0
            lsum += pw;
            const float* vrow = &Vs[j][slice * 32];
            #pragma unroll
            for (int d4 = 0; d4 < 8; d4++) {
                float4 vv = *(const float4*)(vrow + d4 * 4);
                o[d4*4+0] = fmaf(pw, vv.x, o[d4*4+0]);
                o[d4*4+1] = fmaf(pw, vv.y, o[d4*4+1]);
                o[d4*4+2] = fmaf(pw, vv.z, o[d4*4+2]);
                o[d4*4+3] = fmaf(pw, vv.w, o[d4*4+3]);
            }
        }
        __syncthreads();
    }

    const float inv_l = 1.0f / lsum;
    float* op = attn_out + (size_t)qrow * HIDDEN + h * HD + slice * 32;
    #pragma unroll
    for (int d4 = 0; d4 < 8; d4++) {
        float4 v = make_float4(o[d4*4+0] * inv_l, o[d4*4+1] * inv_l,
                               o[d4*4+2] * inv_l, o[d4*4+3] * inv_l);
        *(float4*)(op + d4 * 4) = v;
    }
}

// ---------------------------------------------------------------------------
extern "C" void kernel_launch(void* const* d_in, const int* in_sizes, int n_in,
                              void* d_out, int out_size)
{
    const int*   positions = (const int*)d_in[0];
    const float* hidden    = (const float*)d_in[1];
    const float* w_qkv     = (const float*)d_in[2];
    const float* w_o       = (const float*)d_in[3];
    float* out = (float*)d_out;

    float *qkv = nullptr, *attn = nullptr;
    cudaGetSymbolAddress((void**)&qkv,  g_qkv);
    cudaGetSymbolAddress((void**)&attn, g_attn);

    // 1) QKV projection: [2048,4096] @ [4096,6144]
    sgemm_kernel<<<dim3(QKV_N / 128, T_SEQ / 128), 256>>>(
        hidden, w_qkv, qkv, T_SEQ, QKV_N, HIDDEN);

    // 2) RoPE on Q and K regions
    rope_kernel<<<T_SEQ, 256>>>(qkv, positions);

    // 3) Causal GQA attention -> [2048, 4096]
    attn_kernel<<<dim3(T_SEQ / AT_BM, NH), 256>>>(qkv, attn);

    // 4) Output projection: [2048,4096] @ [4096,4096]
    sgemm_kernel<<<dim3(HIDDEN / 128, T_SEQ / 128), 256>>>(
        attn, w_o, out, T_SEQ, HIDDEN, HIDDEN);
}

// round 3
// speedup vs baseline: 1.0467x; 1.0467x over previous
#include <cuda_runtime.h>
#include <math.h>
#include <stdint.h>

#define T_SEQ  2048
#define HIDDEN 4096
#define NH     32
#define NKV    8
#define HD     128
#define Q_SIZE  (NH * HD)              // 4096
#define KV_SIZE (NKV * HD)             // 1024
#define QKV_N   (Q_SIZE + 2 * KV_SIZE) // 6144
#define SCALE   0.08838834764831845f   // 128^-0.5

// Scratch (no cudaMalloc allowed)
__device__ float g_qkv[(size_t)T_SEQ * QKV_N];     // 50 MB
__device__ float g_attn[(size_t)T_SEQ * HIDDEN];   // 32 MB

// ============================================================================
// Helpers
// ============================================================================
__device__ __forceinline__ float tf32_rna(float x) {
    uint32_t u;
    asm("cvt.rna.tf32.f32 %0, %1;" : "=r"(u) : "f"(x));
    return __uint_as_float(u);
}

// m16n8k8 TF32 MMA (sm_80+ portable): D = A(16x8,row) * B(8x8,col) + D
__device__ __forceinline__ void mma8(float* c, const uint32_t* a,
                                     const uint32_t* b) {
    asm volatile(
        "mma.sync.aligned.m16n8k8.row.col.f32.tf32.tf32.f32 "
        "{%0,%1,%2,%3}, {%4,%5,%6,%7}, {%8,%9}, {%0,%1,%2,%3};"
        : "+f"(c[0]), "+f"(c[1]), "+f"(c[2]), "+f"(c[3])
        : "r"(a[0]), "r"(a[1]), "r"(a[2]), "r"(a[3]), "r"(b[0]), "r"(b[1]));
}

// f32x2 packed fp32 math
typedef unsigned long long u64;
__device__ __forceinline__ u64 pack2(float lo, float hi) {
    u64 r;
    asm("mov.b64 %0, {%1, %2};" : "=l"(r) : "f"(lo), "f"(hi));
    return r;
}
__device__ __forceinline__ float2 unpack2(u64 v) {
    float lo, hi;
    asm("mov.b64 {%0, %1}, %2;" : "=f"(lo), "=f"(hi) : "l"(v));
    return make_float2(lo, hi);
}
__device__ __forceinline__ void fma2(u64& d, u64 a, u64 b) {
    asm("fma.rn.f32x2 %0, %1, %2, %3;" : "=l"(d) : "l"(a), "l"(b), "l"(d));
}
__device__ __forceinline__ void mul2(u64& d, u64 a, u64 b) {
    asm("mul.rn.f32x2 %0, %1, %2;" : "=l"(d) : "l"(a), "l"(b));
}

// ============================================================================
// TF32(3x) tensor-core GEMM: C[M,N] = A[M,K] @ B[K,N], all row-major fp32.
// CTA: 128x128 tile, BK=32, 256 threads (8 warps, warp tile 64x32).
// smem holds hi/lo tf32 splits; dynamic smem ~69 KB.
// ============================================================================
#define BK 32
#define AS_STRIDE 36   // 32 + 4 pad (conflict-free for fragment loads)
#define BS_STRIDE 132  // 128 + 4 pad

#define SM_AH 0
#define SM_AL (128 * AS_STRIDE)            // floats
#define SM_BH (2 * 128 * AS_STRIDE)
#define SM_BL (2 * 128 * AS_STRIDE + BK * BS_STRIDE)
#define SM_FLOATS (2 * 128 * AS_STRIDE + 2 * BK * BS_STRIDE)

__global__ __launch_bounds__(256, 1) void gemm_tc_kernel(
    const float* __restrict__ A, const float* __restrict__ B,
    float* __restrict__ C, int M, int N, int K)
{
    extern __shared__ float sm[];

    const int tid  = threadIdx.x;
    const int wid  = tid >> 5;
    const int lane = tid & 31;
    const int g    = lane >> 2;   // group id 0..7
    const int tg   = lane & 3;    // thread in group 0..3
    const int wm   = (wid >> 2) * 64;  // warp m offset within tile
    const int wn   = (wid & 3) * 32;   // warp n offset within tile
    const int m0 = blockIdx.y * 128;
    const int n0 = blockIdx.x * 128;

    // loader indices (coalesced 128B per warp)
    const int a_row = tid >> 3;        // 0..31 (+i*32)
    const int a_col = (tid & 7) * 4;   // 0..28
    const int b_row = tid >> 3;        // 0..31
    // b cols: (tid&7)*4 + j*32

    float acc[4][4][4];
    #pragma unroll
    for (int i = 0; i < 4; i++)
        #pragma unroll
        for (int j = 0; j < 4; j++)
            #pragma unroll
            for (int q = 0; q < 4; q++) acc[i][j][q] = 0.f;

    const int KT = K / BK;

    // prefetch tile 0
    float4 pa[4], pb[4];
    #pragma unroll
    for (int i = 0; i < 4; i++)
        pa[i] = *(const float4*)&A[(size_t)(m0 + a_row + i * 32) * K + a_col];
    #pragma unroll
    for (int j = 0; j < 4; j++)
        pb[j] = *(const float4*)&B[(size_t)b_row * N + n0 + (tid & 7) * 4 + j * 32];

    for (int kt = 0; kt < KT; kt++) {
        // store prefetched tile (split hi/lo) into smem
        #pragma unroll
        for (int i = 0; i < 4; i++) {
            float4 v = pa[i];
            float4 hi, lo;
            hi.x = tf32_rna(v.x); lo.x = tf32_rna(v.x - hi.x);
            hi.y = tf32_rna(v.y); lo.y = tf32_rna(v.y - hi.y);
            hi.z = tf32_rna(v.z); lo.z = tf32_rna(v.z - hi.z);
            hi.w = tf32_rna(v.w); lo.w = tf32_rna(v.w - hi.w);
            int off = (a_row + i * 32) * AS_STRIDE + a_col;
            *(float4*)&sm[SM_AH + off] = hi;
            *(float4*)&sm[SM_AL + off] = lo;
        }
        #pragma unroll
        for (int j = 0; j < 4; j++) {
            float4 v = pb[j];
            float4 hi, lo;
            hi.x = tf32_rna(v.x); lo.x = tf32_rna(v.x - hi.x);
            hi.y = tf32_rna(v.y); lo.y = tf32_rna(v.y - hi.y);
            hi.z = tf32_rna(v.z); lo.z = tf32_rna(v.z - hi.z);
            hi.w = tf32_rna(v.w); lo.w = tf32_rna(v.w - hi.w);
            int off = b_row * BS_STRIDE + (tid & 7) * 4 + j * 32;
            *(float4*)&sm[SM_BH + off] = hi;
            *(float4*)&sm[SM_BL + off] = lo;
        }
        __syncthreads();

        // prefetch next tile
        if (kt + 1 < KT) {
            const int kk = (kt + 1) * BK;
            #pragma unroll
            for (int i = 0; i < 4; i++)
                pa[i] = *(const float4*)
                    &A[(size_t)(m0 + a_row + i * 32) * K + kk + a_col];
            #pragma unroll
            for (int j = 0; j < 4; j++)
                pb[j] = *(const float4*)
                    &B[(size_t)(kk + b_row) * N + n0 + (tid & 7) * 4 + j * 32];
        }

        // compute: 4 k-steps of 8
        #pragma unroll
        for (int ks = 0; ks < 4; ks++) {
            uint32_t ah[4][4], al[4][4];
            #pragma unroll
            for (int mt = 0; mt < 4; mt++) {
                int r = wm + mt * 16 + g;
                int c = ks * 8 + tg;
                ah[mt][0] = __float_as_uint(sm[SM_AH + r * AS_STRIDE + c]);
                ah[mt][1] = __float_as_uint(sm[SM_AH + (r + 8) * AS_STRIDE + c]);
                ah[mt][2] = __float_as_uint(sm[SM_AH + r * AS_STRIDE + c + 4]);
                ah[mt][3] = __float_as_uint(sm[SM_AH + (r + 8) * AS_STRIDE + c + 4]);
                al[mt][0] = __float_as_uint(sm[SM_AL + r * AS_STRIDE + c]);
                al[mt][1] = __float_as_uint(sm[SM_AL + (r + 8) * AS_STRIDE + c]);
                al[mt][2] = __float_as_uint(sm[SM_AL + r * AS_STRIDE + c + 4]);
                al[mt][3] = __float_as_uint(sm[SM_AL + (r + 8) * AS_STRIDE + c + 4]);
            }
            uint32_t bh[4][2], bl[4][2];
            #pragma unroll
            for (int nt = 0; nt < 4; nt++) {
                int n = wn + nt * 8 + g;
                int k = ks * 8 + tg;
                bh[nt][0] = __float_as_uint(sm[SM_BH + k * BS_STRIDE + n]);
                bh[nt][1] = __float_as_uint(sm[SM_BH + (k + 4) * BS_STRIDE + n]);
                bl[nt][0] = __float_as_uint(sm[SM_BL + k * BS_STRIDE + n]);
                bl[nt][1] = __float_as_uint(sm[SM_BL + (k + 4) * BS_STRIDE + n]);
            }
            #pragma unroll
            for (int mt = 0; mt < 4; mt++)
                #pragma unroll
                for (int nt = 0; nt < 4; nt++) {
                    mma8(acc[mt][nt], ah[mt], bh[nt]);
                    mma8(acc[mt][nt], al[mt], bh[nt]);
                    mma8(acc[mt][nt], ah[mt], bl[nt]);
                }
        }
        __syncthreads();
    }

    // epilogue
    #pragma unroll
    for (int mt = 0; mt < 4; mt++) {
        int row = m0 + wm + mt * 16 + g;
        #pragma unroll
        for (int nt = 0; nt < 4; nt++) {
            int col = n0 + wn + nt * 8 + tg * 2;
            *(float2*)&C[(size_t)row * N + col] =
                make_float2(acc[mt][nt][0], acc[mt][nt][1]);
            *(float2*)&C[(size_t)(row + 8) * N + col] =
                make_float2(acc[mt][nt][2], acc[mt][nt][3]);
        }
    }
}

// ============================================================================
// RoPE (interleaved), in-place on Q and K regions of qkv.
// ============================================================================
__global__ __launch_bounds__(256) void rope_kernel(
    float* __restrict__ qkv, const int* __restrict__ positions)
{
    const int t = blockIdx.x;
    const float p = (float)positions[t];
    const int npairs = (NH + NKV) * (HD / 2);  // 2560

    for (int idx = threadIdx.x; idx < npairs; idx += blockDim.x) {
        const int head = idx >> 6;
        const int i = idx & 63;
        double e = (double)(2 * i) / (double)HD;
        float inv_freq = (float)pow(500000.0, -e);
        float ang = p * inv_freq;
        float s, c;
        sincosf(ang, &s, &c);

        size_t base;
        if (head < NH)
            base = (size_t)t * QKV_N + head * HD;
        else
            base = (size_t)t * QKV_N + Q_SIZE + (head - NH) * HD;

        float x1 = qkv[base + 2 * i];
        float x2 = qkv[base + 2 * i + 1];
        qkv[base + 2 * i]     = x1 * c - x2 * s;
        qkv[base + 2 * i + 1] = x2 * c + x1 * s;
    }
}

// ============================================================================
// Causal GQA flash attention with packed f32x2 inner loops.
// Block: 64 q-rows of one head; 256 threads (row = tid/4, 32-dim slice).
// ============================================================================
#define AT_BM 64
#define AT_BN 32

__global__ __launch_bounds__(256) void attn_kernel(
    const float* __restrict__ qkv, float* __restrict__ attn_out)
{
    __shared__ float Ks[AT_BN][HD];
    __shared__ float Vs[AT_BN][HD];

    const int tid = threadIdx.x;
    const int r = tid >> 2;
    const int slice = tid & 3;
    const int h = blockIdx.y;
    const int kh = h >> 2;
    const int m0 = blockIdx.x * AT_BM;
    const int qrow = m0 + r;

    u64 q2[16];
    {
        const float* qp = qkv + (size_t)qrow * QKV_N + h * HD + slice * 32;
        #pragma unroll
        for (int d4 = 0; d4 < 8; d4++) {
            float4 v = *(const float4*)(qp + d4 * 4);
            q2[d4 * 2 + 0] = pack2(v.x * SCALE, v.y * SCALE);
            q2[d4 * 2 + 1] = pack2(v.z * SCALE, v.w * SCALE);
        }
    }

    u64 o2[16];
    #pragma unroll
    for (int d = 0; d < 16; d++) o2[d] = 0ull;
    float mval = -1e30f, lsum = 0.f;

    for (int n0 = 0; n0 < m0 + AT_BM; n0 += AT_BN) {
        #pragma unroll
        for (int i = 0; i < 4; i++) {
            int l4 = tid + i * 256;
            int row = l4 >> 5;
            int c4 = l4 & 31;
            const float* kp = qkv + (size_t)(n0 + row) * QKV_N + Q_SIZE + kh * HD;
            *(float4*)&Ks[row][c4 * 4] = *(const float4*)(kp + c4 * 4);
            *(float4*)&Vs[row][c4 * 4] = *(const float4*)(kp + KV_SIZE + c4 * 4);
        }
        __syncthreads();

        #pragma unroll 1
        for (int j = 0; j < AT_BN; j++) {
            u64 acc = 0ull;
            const float* krow = &Ks[j][slice * 32];
            #pragma unroll
            for (int d4 = 0; d4 < 8; d4++) {
                float4 kv4 = *(const float4*)(krow + d4 * 4);
                fma2(acc, q2[d4 * 2 + 0], pack2(kv4.x, kv4.y));
                fma2(acc, q2[d4 * 2 + 1], pack2(kv4.z, kv4.w));
            }
            float2 ac = unpack2(acc);
            float s = ac.x + ac.y;
            s += __shfl_xor_sync(0xffffffffu, s, 1);
            s += __shfl_xor_sync(0xffffffffu, s, 2);

            if (n0 + j > qrow) s = -1e30f;

            if (s > mval) {
                float sc = __expf(mval - s);
                lsum *= sc;
                u64 sc2 = pack2(sc, sc);
                #pragma unroll
                for (int d = 0; d < 16; d++) mul2(o2[d], o2[d], sc2);
                mval = s;
            }
            float pw = __expf(s - mval);
            lsum += pw;
            u64 pw2 = pack2(pw, pw);
            const float* vrow = &Vs[j][slice * 32];
            #pragma unroll
            for (int d4 = 0; d4 < 8; d4++) {
                float4 vv = *(const float4*)(vrow + d4 * 4);
                fma2(o2[d4 * 2 + 0], pw2, pack2(vv.x, vv.y));
                fma2(o2[d4 * 2 + 1], pw2, pack2(vv.z, vv.w));
            }
        }
        __syncthreads();
    }

    const float inv_l = 1.0f / lsum;
    float* op = attn_out + (size_t)qrow * HIDDEN + h * HD + slice * 32;
    #pragma unroll
    for (int d4 = 0; d4 < 8; d4++) {
        float2 a = unpack2(o2[d4 * 2 + 0]);
        float2 b = unpack2(o2[d4 * 2 + 1]);
        float4 v = make_float4(a.x * inv_l, a.y * inv_l, b.x * inv_l, b.y * inv_l);
        *(float4*)(op + d4 * 4) = v;
    }
}

// ============================================================================
extern "C" void kernel_launch(void* const* d_in, const int* in_sizes, int n_in,
                              void* d_out, int out_size)
{
    const int*   positions = (const int*)d_in[0];
    const float* hidden    = (const float*)d_in[1];
    const float* w_qkv     = (const float*)d_in[2];
    const float* w_o       = (const float*)d_in[3];
    float* out = (float*)d_out;

    float *qkv = nullptr, *attn = nullptr;
    cudaGetSymbolAddress((void**)&qkv,  g_qkv);
    cudaGetSymbolAddress((void**)&attn, g_attn);

    const int GSM = SM_FLOATS * 4;  // ~69 KB
    cudaFuncSetAttribute(gemm_tc_kernel,
                         cudaFuncAttributeMaxDynamicSharedMemorySize, GSM);

    // 1) QKV projection (tensor cores, 3xTF32): [2048,4096] @ [4096,6144]
    gemm_tc_kernel<<<dim3(QKV_N / 128, T_SEQ / 128), 256, GSM>>>(
        hidden, w_qkv, qkv, T_SEQ, QKV_N, HIDDEN);

    // 2) RoPE
    rope_kernel<<<T_SEQ, 256>>>(qkv, positions);

    // 3) Attention
    attn_kernel<<<dim3(T_SEQ / AT_BM, NH), 256>>>(qkv, attn);

    // 4) Output projection: [2048,4096] @ [4096,4096]
    gemm_tc_kernel<<<dim3(HIDDEN / 128, T_SEQ / 128), 256, GSM>>>(
        attn, w_o, out, T_SEQ, HIDDEN, HIDDEN);
}

// round 4
// speedup vs baseline: 1.2444x; 1.1890x over previous
#include <cuda_runtime.h>
#include <cuda_bf16.h>
#include <math.h>
#include <stdint.h>

#define T_SEQ  2048
#define HIDDEN 4096
#define NH     32
#define NKV    8
#define HD     128
#define Q_SIZE  (NH * HD)              // 4096
#define KV_SIZE (NKV * HD)             // 1024
#define QKV_N   (Q_SIZE + 2 * KV_SIZE) // 6144
#define SCALE   0.08838834764831845f   // 128^-0.5

// Scratch (no cudaMalloc allowed)
__device__ float g_qkv[(size_t)T_SEQ * QKV_N];     // 50 MB
__device__ float g_attn[(size_t)T_SEQ * HIDDEN];   // 32 MB

// ============================================================================
// Helpers
// ============================================================================
__device__ __forceinline__ uint32_t smem_u32(const void* p) {
    uint32_t a;
    asm("{ .reg .u64 t; cvta.to.shared.u64 t, %1; cvt.u32.u64 %0, t; }"
        : "=r"(a) : "l"(p));
    return a;
}

// m16n8k16 BF16 MMA: D += A(16x16,row) * B(16x8,col)
__device__ __forceinline__ void mma16(float* c, const uint32_t* a,
                                      const uint32_t* b) {
    asm volatile(
        "mma.sync.aligned.m16n8k16.row.col.f32.bf16.bf16.f32 "
        "{%0,%1,%2,%3}, {%4,%5,%6,%7}, {%8,%9}, {%0,%1,%2,%3};"
        : "+f"(c[0]), "+f"(c[1]), "+f"(c[2]), "+f"(c[3])
        : "r"(a[0]), "r"(a[1]), "r"(a[2]), "r"(a[3]), "r"(b[0]), "r"(b[1]));
}

__device__ __forceinline__ void ldmx4(uint32_t* r, uint32_t addr) {
    asm volatile(
        "ldmatrix.sync.aligned.m8n8.x4.shared.b16 {%0,%1,%2,%3}, [%4];"
        : "=r"(r[0]), "=r"(r[1]), "=r"(r[2]), "=r"(r[3]) : "r"(addr));
}
__device__ __forceinline__ void ldmx4t(uint32_t* r, uint32_t addr) {
    asm volatile(
        "ldmatrix.sync.aligned.m8n8.x4.trans.shared.b16 {%0,%1,%2,%3}, [%4];"
        : "=r"(r[0]), "=r"(r[1]), "=r"(r[2]), "=r"(r[3]) : "r"(addr));
}

// split two fp32 into bf16 hi/lo pairs (packed u32 each)
__device__ __forceinline__ void split2(float x, float y,
                                       uint32_t& hi, uint32_t& lo) {
    __nv_bfloat162 h = __floats2bfloat162_rn(x, y);
    float hx = __bfloat162float(h.x);
    float hy = __bfloat162float(h.y);
    __nv_bfloat162 l = __floats2bfloat162_rn(x - hx, y - hy);
    hi = *(uint32_t*)&h;
    lo = *(uint32_t*)&l;
}

// f32x2 packed fp32 math
typedef unsigned long long u64;
__device__ __forceinline__ u64 pack2(float lo, float hi) {
    u64 r;
    asm("mov.b64 %0, {%1, %2};" : "=l"(r) : "f"(lo), "f"(hi));
    return r;
}
__device__ __forceinline__ float2 unpack2(u64 v) {
    float lo, hi;
    asm("mov.b64 {%0, %1}, %2;" : "=f"(lo), "=f"(hi) : "l"(v));
    return make_float2(lo, hi);
}
__device__ __forceinline__ void fma2(u64& d, u64 a, u64 b) {
    asm("fma.rn.f32x2 %0, %1, %2, %3;" : "=l"(d) : "l"(a), "l"(b), "l"(d));
}
__device__ __forceinline__ void mul2(u64& d, u64 a, u64 b) {
    asm("mul.rn.f32x2 %0, %1, %2;" : "=l"(d) : "l"(a), "l"(b));
}

// ============================================================================
// BF16(3x) tensor-core GEMM: C[M,N] = A[M,K] @ B[K,N], row-major fp32 I/O.
// CTA 128x128, BK=32, 256 threads (8 warps, warp tile 64x32), 2 CTAs/SM.
// A smem [m][k] bf16 (hi|lo), stride 40; B smem [k][n] bf16, stride 136.
// Fragments via ldmatrix (A non-trans, B trans).
// ============================================================================
#define BK  32
#define AST 40    // A row stride in bf16 elems (80B: ldmatrix conflict-free)
#define BST 136   // B k-row stride in bf16 elems (272B: conflict-free)
#define OFF_AH 0
#define OFF_AL (128 * AST)
#define OFF_BH (2 * 128 * AST)
#define OFF_BL (2 * 128 * AST + BK * BST)
#define SM_BF16 (2 * 128 * AST + 2 * BK * BST)   // 18944 elems = 37888 B

__global__ __launch_bounds__(256, 2) void gemm_bf16x3(
    const float* __restrict__ A, const float* __restrict__ B,
    float* __restrict__ C, int M, int N, int K)
{
    extern __shared__ __align__(16) __nv_bfloat16 sm[];
    const uint32_t smb = smem_u32(sm);

    const int tid  = threadIdx.x;
    const int wid  = tid >> 5;
    const int lane = tid & 31;
    const int g    = lane >> 2;
    const int tg   = lane & 3;
    const int wm   = (wid >> 2) * 64;
    const int wn   = (wid & 3) * 32;
    const int m0 = blockIdx.y * 128;
    const int n0 = blockIdx.x * 128;

    // loader indices
    const int a_row = tid >> 3;        // 0..31 (+i*32)
    const int xcol  = (tid & 7) * 4;   // 0..28
    const int b_row = tid >> 3;        // 0..31 (k)

    // ldmatrix lane-address components (bytes)
    const int l7  = lane & 7;
    const int l8  = (lane >> 3) & 1;
    const int l16 = lane >> 4;
    // A: row = wm + mt*16 + l7 + l8*8 ; kcol = ks*16 + l16*8
    const uint32_t aAddr0 = smb +
        (uint32_t)(((wm + l7 + l8 * 8) * AST + l16 * 8) * 2);
    // B: krow = ks*16 + l7 + l8*8 ; ncol = wn + pair*16 + l16*8
    const uint32_t bAddr0 = smb + (uint32_t)(OFF_BH * 2) +
        (uint32_t)(((l7 + l8 * 8) * BST + wn + l16 * 8) * 2);

    float acc[4][4][4];
    #pragma unroll
    for (int i = 0; i < 4; i++)
        #pragma unroll
        for (int j = 0; j < 4; j++)
            #pragma unroll
            for (int q = 0; q < 4; q++) acc[i][j][q] = 0.f;

    const int KT = K / BK;

    for (int kt = 0; kt < KT; kt++) {
        const int kk = kt * BK;
        // ---- load + convert A tile (128x32) ----
        #pragma unroll
        for (int i = 0; i < 4; i++) {
            const int row = a_row + i * 32;
            float4 v = *(const float4*)&A[(size_t)(m0 + row) * K + kk + xcol];
            uint32_t h0, l0, h1, l1;
            split2(v.x, v.y, h0, l0);
            split2(v.z, v.w, h1, l1);
            const int e = row * AST + xcol;
            *(uint32_t*)&sm[OFF_AH + e]     = h0;
            *(uint32_t*)&sm[OFF_AH + e + 2] = h1;
            *(uint32_t*)&sm[OFF_AL + e]     = l0;
            *(uint32_t*)&sm[OFF_AL + e + 2] = l1;
        }
        // ---- load + convert B tile (32x128) ----
        #pragma unroll
        for (int j = 0; j < 4; j++) {
            const int col = xcol + j * 32;
            float4 v = *(const float4*)&B[(size_t)(kk + b_row) * N + n0 + col];
            uint32_t h0, l0, h1, l1;
            split2(v.x, v.y, h0, l0);
            split2(v.z, v.w, h1, l1);
            const int e = b_row * BST + col;
            *(uint32_t*)&sm[OFF_BH + e]     = h0;
            *(uint32_t*)&sm[OFF_BH + e + 2] = h1;
            *(uint32_t*)&sm[OFF_BL + e]     = l0;
            *(uint32_t*)&sm[OFF_BL + e + 2] = l1;
        }
        __syncthreads();

        // ---- compute: 2 k16 steps ----
        #pragma unroll
        for (int ks = 0; ks < 2; ks++) {
            uint32_t ah[4][4], al[4][4];
            #pragma unroll
            for (int mt = 0; mt < 4; mt++) {
                const uint32_t base = aAddr0 + mt * (16 * AST * 2) + ks * 32;
                ldmx4(ah[mt], base);
                ldmx4(al[mt], base + OFF_AL * 2);
            }
            uint32_t bh[2][4], bl[2][4];
            #pragma unroll
            for (int p = 0; p < 2; p++) {
                const uint32_t base = bAddr0 + ks * (16 * BST * 2) + p * 32;
                ldmx4t(bh[p], base);
                ldmx4t(bl[p], base + (OFF_BL - OFF_BH) * 2);
            }
            #pragma unroll
            for (int mt = 0; mt < 4; mt++)
                #pragma unroll
                for (int nt = 0; nt < 4; nt++) {
                    const uint32_t* bhf = &bh[nt >> 1][(nt & 1) * 2];
                    const uint32_t* blf = &bl[nt >> 1][(nt & 1) * 2];
                    mma16(acc[mt][nt], ah[mt], bhf);
                    mma16(acc[mt][nt], al[mt], bhf);
                    mma16(acc[mt][nt], ah[mt], blf);
                }
        }
        __syncthreads();
    }

    // epilogue
    #pragma unroll
    for (int mt = 0; mt < 4; mt++) {
        const int row = m0 + wm + mt * 16 + g;
        #pragma unroll
        for (int nt = 0; nt < 4; nt++) {
            const int col = n0 + wn + nt * 8 + tg * 2;
            *(float2*)&C[(size_t)row * N + col] =
                make_float2(acc[mt][nt][0], acc[mt][nt][1]);
            *(float2*)&C[(size_t)(row + 8) * N + col] =
                make_float2(acc[mt][nt][2], acc[mt][nt][3]);
        }
    }
}

// ============================================================================
// RoPE (interleaved), in-place on Q and K regions of qkv.
// inv_freq hoisted to a per-block smem table (fp64 pow computed once/block).
// ============================================================================
__global__ __launch_bounds__(256) void rope_kernel(
    float* __restrict__ qkv, const int* __restrict__ positions)
{
    __shared__ float s_if[64];
    const int t = blockIdx.x;
    if (threadIdx.x < 64) {
        double e = (double)(2 * threadIdx.x) / (double)HD;
        s_if[threadIdx.x] = (float)pow(500000.0, -e);
    }
    __syncthreads();

    const float p = (float)positions[t];
    const int npairs = (NH + NKV) * (HD / 2);  // 2560

    for (int idx = threadIdx.x; idx < npairs; idx += blockDim.x) {
        const int head = idx >> 6;
        const int i = idx & 63;
        float ang = p * s_if[i];
        float s, c;
        sincosf(ang, &s, &c);

        size_t base;
        if (head < NH)
            base = (size_t)t * QKV_N + head * HD;
        else
            base = (size_t)t * QKV_N + Q_SIZE + (head - NH) * HD;

        float2 x = *(float2*)&qkv[base + 2 * i];
        float2 o;
        o.x = x.x * c - x.y * s;
        o.y = x.y * c + x.x * s;
        *(float2*)&qkv[base + 2 * i] = o;
    }
}

// ============================================================================
// Causal GQA flash attention, f32x2 inner loops with direct b64 smem loads.
// Block: 64 q-rows of one head; 256 threads (row = tid/4, 32-dim slice).
// ============================================================================
#define AT_BM 64
#define AT_BN 32

__global__ __launch_bounds__(256) void attn_kernel(
    const float* __restrict__ qkv, float* __restrict__ attn_out)
{
    __shared__ float Ks[AT_BN][HD];
    __shared__ float Vs[AT_BN][HD];

    const int tid = threadIdx.x;
    const int r = tid >> 2;
    const int slice = tid & 3;
    const int h = blockIdx.y;
    const int kh = h >> 2;
    const int m0 = blockIdx.x * AT_BM;
    const int qrow = m0 + r;

    u64 q2[16];
    {
        const float* qp = qkv + (size_t)qrow * QKV_N + h * HD + slice * 32;
        #pragma unroll
        for (int d4 = 0; d4 < 8; d4++) {
            float4 v = *(const float4*)(qp + d4 * 4);
            q2[d4 * 2 + 0] = pack2(v.x * SCALE, v.y * SCALE);
            q2[d4 * 2 + 1] = pack2(v.z * SCALE, v.w * SCALE);
        }
    }

    u64 o2[16];
    #pragma unroll
    for (int d = 0; d < 16; d++) o2[d] = 0ull;
    float mval = -1e30f, lsum = 0.f;

    for (int n0 = 0; n0 < m0 + AT_BM; n0 += AT_BN) {
        #pragma unroll
        for (int i = 0; i < 4; i++) {
            int l4 = tid + i * 256;
            int row = l4 >> 5;
            int c4 = l4 & 31;
            const float* kp = qkv + (size_t)(n0 + row) * QKV_N + Q_SIZE + kh * HD;
            *(float4*)&Ks[row][c4 * 4] = *(const float4*)(kp + c4 * 4);
            *(float4*)&Vs[row][c4 * 4] = *(const float4*)(kp + KV_SIZE + c4 * 4);
        }
        __syncthreads();

        #pragma unroll 1
        for (int j = 0; j < AT_BN; j++) {
            const u64* krow = (const u64*)&Ks[j][slice * 32];
            u64 a0 = 0ull, a1 = 0ull;
            #pragma unroll
            for (int d = 0; d < 16; d += 2) {
                fma2(a0, q2[d],     krow[d]);
                fma2(a1, q2[d + 1], krow[d + 1]);
            }
            float2 c0 = unpack2(a0), c1 = unpack2(a1);
            float s = (c0.x + c0.y) + (c1.x + c1.y);
            s += __shfl_xor_sync(0xffffffffu, s, 1);
            s += __shfl_xor_sync(0xffffffffu, s, 2);

            if (n0 + j > qrow) s = -1e30f;

            if (s > mval) {
                float sc = __expf(mval - s);
                lsum *= sc;
                u64 sc2 = pack2(sc, sc);
                #pragma unroll
                for (int d = 0; d < 16; d++) mul2(o2[d], o2[d], sc2);
                mval = s;
            }
            float pw = __expf(s - mval);
            lsum += pw;
            u64 pw2 = pack2(pw, pw);
            const u64* vrow = (const u64*)&Vs[j][slice * 32];
            #pragma unroll
            for (int d = 0; d < 16; d++) fma2(o2[d], pw2, vrow[d]);
        }
        __syncthreads();
    }

    const float inv_l = 1.0f / lsum;
    float* op = attn_out + (size_t)qrow * HIDDEN + h * HD + slice * 32;
    #pragma unroll
    for (int d4 = 0; d4 < 8; d4++) {
        float2 a = unpack2(o2[d4 * 2 + 0]);
        float2 b = unpack2(o2[d4 * 2 + 1]);
        float4 v = make_float4(a.x * inv_l, a.y * inv_l, b.x * inv_l, b.y * inv_l);
        *(float4*)(op + d4 * 4) = v;
    }
}

// ============================================================================
extern "C" void kernel_launch(void* const* d_in, const int* in_sizes, int n_in,
                              void* d_out, int out_size)
{
    const int*   positions = (const int*)d_in[0];
    const float* hidden    = (const float*)d_in[1];
    const float* w_qkv     = (const float*)d_in[2];
    const float* w_o       = (const float*)d_in[3];
    float* out = (float*)d_out;

    float *qkv = nullptr, *attn = nullptr;
    cudaGetSymbolAddress((void**)&qkv,  g_qkv);
    cudaGetSymbolAddress((void**)&attn, g_attn);

    const int GSM = SM_BF16 * 2;  // 37888 bytes
    cudaFuncSetAttribute(gemm_bf16x3,
                         cudaFuncAttributeMaxDynamicSharedMemorySize, GSM);

    // 1) QKV projection (3xBF16 tensor cores): [2048,4096] @ [4096,6144]
    gemm_bf16x3<<<dim3(QKV_N / 128, T_SEQ / 128), 256, GSM>>>(
        hidden, w_qkv, qkv, T_SEQ, QKV_N, HIDDEN);

    // 2) RoPE
    rope_kernel<<<T_SEQ, 256>>>(qkv, positions);

    // 3) Attention
    attn_kernel<<<dim3(T_SEQ / AT_BM, NH), 256>>>(qkv, attn);

    // 4) Output projection: [2048,4096] @ [4096,4096]
    gemm_bf16x3<<<dim3(HIDDEN / 128, T_SEQ / 128), 256, GSM>>>(
        attn, w_o, out, T_SEQ, HIDDEN, HIDDEN);
}

// round 5
// speedup vs baseline: 6.5655x; 5.2759x over previous
#include <cuda_runtime.h>
#include <cuda_bf16.h>
#include <math.h>
#include <stdint.h>

#define T_SEQ  2048
#define HIDDEN 4096
#define NH     32
#define NKV    8
#define HD     128
#define Q_SIZE  (NH * HD)              // 4096
#define KV_SIZE (NKV * HD)             // 1024
#define QKV_N   (Q_SIZE + 2 * KV_SIZE) // 6144
#define SCALE   0.08838834764831845f   // 128^-0.5

// Scratch (no cudaMalloc allowed)
__device__ float g_qkv[(size_t)T_SEQ * QKV_N];     // 50 MB
__device__ float g_attn[(size_t)T_SEQ * HIDDEN];   // 32 MB

// ============================================================================
// Helpers
// ============================================================================
__device__ __forceinline__ uint32_t smem_u32(const void* p) {
    uint32_t a;
    asm("{ .reg .u64 t; cvta.to.shared.u64 t, %1; cvt.u32.u64 %0, t; }"
        : "=r"(a) : "l"(p));
    return a;
}

// m16n8k16 BF16 MMA: D += A(16x16,row) * B(16x8,col)
__device__ __forceinline__ void mma16(float* c, const uint32_t* a,
                                      const uint32_t* b) {
    asm volatile(
        "mma.sync.aligned.m16n8k16.row.col.f32.bf16.bf16.f32 "
        "{%0,%1,%2,%3}, {%4,%5,%6,%7}, {%8,%9}, {%0,%1,%2,%3};"
        : "+f"(c[0]), "+f"(c[1]), "+f"(c[2]), "+f"(c[3])
        : "r"(a[0]), "r"(a[1]), "r"(a[2]), "r"(a[3]), "r"(b[0]), "r"(b[1]));
}

__device__ __forceinline__ void ldmx4(uint32_t* r, uint32_t addr) {
    asm volatile(
        "ldmatrix.sync.aligned.m8n8.x4.shared.b16 {%0,%1,%2,%3}, [%4];"
        : "=r"(r[0]), "=r"(r[1]), "=r"(r[2]), "=r"(r[3]) : "r"(addr));
}
__device__ __forceinline__ void ldmx4t(uint32_t* r, uint32_t addr) {
    asm volatile(
        "ldmatrix.sync.aligned.m8n8.x4.trans.shared.b16 {%0,%1,%2,%3}, [%4];"
        : "=r"(r[0]), "=r"(r[1]), "=r"(r[2]), "=r"(r[3]) : "r"(addr));
}

// split two fp32 into bf16 hi/lo pairs (packed u32 each)
__device__ __forceinline__ void split2(float x, float y,
                                       uint32_t& hi, uint32_t& lo) {
    __nv_bfloat162 h = __floats2bfloat162_rn(x, y);
    float hx = __bfloat162float(h.x);
    float hy = __bfloat162float(h.y);
    __nv_bfloat162 l = __floats2bfloat162_rn(x - hx, y - hy);
    hi = *(uint32_t*)&h;
    lo = *(uint32_t*)&l;
}

// ============================================================================
// BF16(3x) tensor-core GEMM: C[M,N] = A[M,K] @ B[K,N], row-major fp32 I/O.
// (unchanged from R4 — measured 676us for QKV proj)
// ============================================================================
#define BK  32
#define AST 40
#define BST 136
#define OFF_AH 0
#define OFF_AL (128 * AST)
#define OFF_BH (2 * 128 * AST)
#define OFF_BL (2 * 128 * AST + BK * BST)
#define SM_BF16 (2 * 128 * AST + 2 * BK * BST)

__global__ __launch_bounds__(256, 2) void gemm_bf16x3(
    const float* __restrict__ A, const float* __restrict__ B,
    float* __restrict__ C, int M, int N, int K)
{
    extern __shared__ __align__(16) __nv_bfloat16 sm[];
    const uint32_t smb = smem_u32(sm);

    const int tid  = threadIdx.x;
    const int wid  = tid >> 5;
    const int lane = tid & 31;
    const int g    = lane >> 2;
    const int tg   = lane & 3;
    const int wm   = (wid >> 2) * 64;
    const int wn   = (wid & 3) * 32;
    const int m0 = blockIdx.y * 128;
    const int n0 = blockIdx.x * 128;

    const int a_row = tid >> 3;
    const int xcol  = (tid & 7) * 4;
    const int b_row = tid >> 3;

    const int l7  = lane & 7;
    const int l8  = (lane >> 3) & 1;
    const int l16 = lane >> 4;
    const uint32_t aAddr0 = smb +
        (uint32_t)(((wm + l7 + l8 * 8) * AST + l16 * 8) * 2);
    const uint32_t bAddr0 = smb + (uint32_t)(OFF_BH * 2) +
        (uint32_t)(((l7 + l8 * 8) * BST + wn + l16 * 8) * 2);

    float acc[4][4][4];
    #pragma unroll
    for (int i = 0; i < 4; i++)
        #pragma unroll
        for (int j = 0; j < 4; j++)
            #pragma unroll
            for (int q = 0; q < 4; q++) acc[i][j][q] = 0.f;

    const int KT = K / BK;

    for (int kt = 0; kt < KT; kt++) {
        const int kk = kt * BK;
        #pragma unroll
        for (int i = 0; i < 4; i++) {
            const int row = a_row + i * 32;
            float4 v = *(const float4*)&A[(size_t)(m0 + row) * K + kk + xcol];
            uint32_t h0, l0, h1, l1;
            split2(v.x, v.y, h0, l0);
            split2(v.z, v.w, h1, l1);
            const int e = row * AST + xcol;
            *(uint32_t*)&sm[OFF_AH + e]     = h0;
            *(uint32_t*)&sm[OFF_AH + e + 2] = h1;
            *(uint32_t*)&sm[OFF_AL + e]     = l0;
            *(uint32_t*)&sm[OFF_AL + e + 2] = l1;
        }
        #pragma unroll
        for (int j = 0; j < 4; j++) {
            const int col = xcol + j * 32;
            float4 v = *(const float4*)&B[(size_t)(kk + b_row) * N + n0 + col];
            uint32_t h0, l0, h1, l1;
            split2(v.x, v.y, h0, l0);
            split2(v.z, v.w, h1, l1);
            const int e = b_row * BST + col;
            *(uint32_t*)&sm[OFF_BH + e]     = h0;
            *(uint32_t*)&sm[OFF_BH + e + 2] = h1;
            *(uint32_t*)&sm[OFF_BL + e]     = l0;
            *(uint32_t*)&sm[OFF_BL + e + 2] = l1;
        }
        __syncthreads();

        #pragma unroll
        for (int ks = 0; ks < 2; ks++) {
            uint32_t ah[4][4], al[4][4];
            #pragma unroll
            for (int mt = 0; mt < 4; mt++) {
                const uint32_t base = aAddr0 + mt * (16 * AST * 2) + ks * 32;
                ldmx4(ah[mt], base);
                ldmx4(al[mt], base + OFF_AL * 2);
            }
            uint32_t bh[2][4], bl[2][4];
            #pragma unroll
            for (int p = 0; p < 2; p++) {
                const uint32_t base = bAddr0 + ks * (16 * BST * 2) + p * 32;
                ldmx4t(bh[p], base);
                ldmx4t(bl[p], base + (OFF_BL - OFF_BH) * 2);
            }
            #pragma unroll
            for (int mt = 0; mt < 4; mt++)
                #pragma unroll
                for (int nt = 0; nt < 4; nt++) {
                    const uint32_t* bhf = &bh[nt >> 1][(nt & 1) * 2];
                    const uint32_t* blf = &bl[nt >> 1][(nt & 1) * 2];
                    mma16(acc[mt][nt], ah[mt], bhf);
                    mma16(acc[mt][nt], al[mt], bhf);
                    mma16(acc[mt][nt], ah[mt], blf);
                }
        }
        __syncthreads();
    }

    #pragma unroll
    for (int mt = 0; mt < 4; mt++) {
        const int row = m0 + wm + mt * 16 + g;
        #pragma unroll
        for (int nt = 0; nt < 4; nt++) {
            const int col = n0 + wn + nt * 8 + tg * 2;
            *(float2*)&C[(size_t)row * N + col] =
                make_float2(acc[mt][nt][0], acc[mt][nt][1]);
            *(float2*)&C[(size_t)(row + 8) * N + col] =
                make_float2(acc[mt][nt][2], acc[mt][nt][3]);
        }
    }
}

// ============================================================================
// RoPE (interleaved), in-place on Q and K regions of qkv.
// ============================================================================
__global__ __launch_bounds__(256) void rope_kernel(
    float* __restrict__ qkv, const int* __restrict__ positions)
{
    __shared__ float s_if[64];
    const int t = blockIdx.x;
    if (threadIdx.x < 64) {
        double e = (double)(2 * threadIdx.x) / (double)HD;
        s_if[threadIdx.x] = (float)pow(500000.0, -e);
    }
    __syncthreads();

    const float p = (float)positions[t];
    const int npairs = (NH + NKV) * (HD / 2);

    for (int idx = threadIdx.x; idx < npairs; idx += blockDim.x) {
        const int head = idx >> 6;
        const int i = idx & 63;
        float ang = p * s_if[i];
        float s, c;
        sincosf(ang, &s, &c);

        size_t base;
        if (head < NH)
            base = (size_t)t * QKV_N + head * HD;
        else
            base = (size_t)t * QKV_N + Q_SIZE + (head - NH) * HD;

        float2 x = *(float2*)&qkv[base + 2 * i];
        float2 o;
        o.x = x.x * c - x.y * s;
        o.y = x.y * c + x.x * s;
        *(float2*)&qkv[base + 2 * i] = o;
    }
}

// ============================================================================
// Tensor-core causal GQA flash attention (bf16x3, FA2 structure).
// CTA: 128 q-rows x 1 head. 8 warps; warp owns 16 rows, full kv width.
// kv tile = 64. Q[128x128] smem hi/lo; K transposed [d][kv]; V [kv][d].
// ============================================================================
#define FBM 128
#define FBN 64
#define QST 136
#define KST 72
#define VST 136
// smem elem offsets (bf16)
#define OQH 0
#define OQL (128 * QST)                       // 17408
#define OKH (2 * 128 * QST)                   // 34816
#define OKL (OKH + 128 * KST)                 // 44032
#define OVH (OKH + 2 * 128 * KST)             // 53248
#define OVL (OVH + 64 * VST)                  // 61952
#define ATT_SMEM_ELEMS (OVL + 64 * VST)       // 70656 elems = 141312 B

__global__ __launch_bounds__(256, 1) void attn_tc_kernel(
    const float* __restrict__ qkv, float* __restrict__ attn_out)
{
    extern __shared__ __align__(16) __nv_bfloat16 asmem[];
    const uint32_t smb = smem_u32(asmem);

    const int tid  = threadIdx.x;
    const int wid  = tid >> 5;
    const int lane = tid & 31;
    const int g    = lane >> 2;
    const int tg   = lane & 3;
    const int mt   = (gridDim.x - 1) - blockIdx.x;   // heavy blocks first
    const int m0   = mt * FBM;
    const int h    = blockIdx.y;
    const int kh   = h >> 2;

    // ---- load Q block (128x128), scale, split hi/lo ----
    #pragma unroll
    for (int i = 0; i < 16; i++) {
        int lin = tid + i * 256;
        int row = lin >> 5;
        int c4  = (lin & 31) * 4;
        float4 v = *(const float4*)&qkv[(size_t)(m0 + row) * QKV_N + h * HD + c4];
        v.x *= SCALE; v.y *= SCALE; v.z *= SCALE; v.w *= SCALE;
        uint32_t h0, l0, h1, l1;
        split2(v.x, v.y, h0, l0);
        split2(v.z, v.w, h1, l1);
        int e = row * QST + c4;
        *(uint32_t*)&asmem[OQH + e]     = h0;
        *(uint32_t*)&asmem[OQH + e + 2] = h1;
        *(uint32_t*)&asmem[OQL + e]     = l0;
        *(uint32_t*)&asmem[OQL + e + 2] = l1;
    }

    float o[16][4];
    #pragma unroll
    for (int n = 0; n < 16; n++)
        #pragma unroll
        for (int q = 0; q < 4; q++) o[n][q] = 0.f;
    float m_0 = -1e30f, m_1 = -1e30f, l_0 = 0.f, l_1 = 0.f;

    // ldmatrix base addresses
    const int l7  = lane & 7;
    const int l8  = (lane >> 3) & 1;
    const int l16 = lane >> 4;
    const uint32_t qA = smb +
        (uint32_t)(((wid * 16 + l7 + l8 * 8) * QST + l16 * 8) * 2);
    const uint32_t kB = smb + (uint32_t)(OKH * 2) +
        (uint32_t)(((l7 + l8 * 8) * KST + l16 * 8) * 2);
    const uint32_t vB = smb + (uint32_t)(OVH * 2) +
        (uint32_t)(((l7 + l8 * 8) * VST + l16 * 8) * 2);

    const int ntiles = m0 / FBN + 2;

    for (int jt = 0; jt < ntiles; jt++) {
        const int j0 = jt * FBN;
        __syncthreads();   // prior compute done before K/V overwrite; Q visible

        // ---- K tile: load [kv][d], store transposed [d][kv] hi/lo ----
        // 2x2 element blocks -> conflict-free STS.32
        #pragma unroll
        for (int i = 0; i < 8; i++) {
            int lin = tid + i * 256;          // 0..2047
            int kv  = (lin & 31) * 2;
            int d   = (lin >> 5) * 2;
            const float* kp =
                &qkv[(size_t)(j0 + kv) * QKV_N + Q_SIZE + kh * HD + d];
            float2 r0 = *(const float2*)kp;          // row kv,   dims d,d+1
            float2 r1 = *(const float2*)(kp + QKV_N); // row kv+1, dims d,d+1
            uint32_t h0, l0, h1, l1;
            split2(r0.x, r1.x, h0, l0);   // Kt[d][kv], Kt[d][kv+1]
            split2(r0.y, r1.y, h1, l1);   // Kt[d+1][kv..]
            int e0 = d * KST + kv;
            int e1 = e0 + KST;
            *(uint32_t*)&asmem[OKH + e0] = h0;
            *(uint32_t*)&asmem[OKL + e0] = l0;
            *(uint32_t*)&asmem[OKH + e1] = h1;
            *(uint32_t*)&asmem[OKL + e1] = l1;
        }
        // ---- V tile: natural [kv][d] hi/lo ----
        #pragma unroll
        for (int i = 0; i < 8; i++) {
            int lin = tid + i * 256;
            int row = lin >> 5;                // 0..63
            int c4  = (lin & 31) * 4;
            float4 v = *(const float4*)
                &qkv[(size_t)(j0 + row) * QKV_N + Q_SIZE + KV_SIZE + kh * HD + c4];
            uint32_t h0, l0, h1, l1;
            split2(v.x, v.y, h0, l0);
            split2(v.z, v.w, h1, l1);
            int e = row * VST + c4;
            *(uint32_t*)&asmem[OVH + e]     = h0;
            *(uint32_t*)&asmem[OVH + e + 2] = h1;
            *(uint32_t*)&asmem[OVL + e]     = l0;
            *(uint32_t*)&asmem[OVL + e + 2] = l1;
        }
        __syncthreads();

        // ---- S = Q K^T  (warp: 16 x 64), bf16x3 ----
        float s[8][4];
        #pragma unroll
        for (int n = 0; n < 8; n++)
            #pragma unroll
            for (int q = 0; q < 4; q++) s[n][q] = 0.f;

        #pragma unroll
        for (int kt = 0; kt < 8; kt++) {
            uint32_t ah[4], al[4];
            ldmx4(ah, qA + kt * 32);
            ldmx4(al, qA + (OQL - OQH) * 2 + kt * 32);
            #pragma unroll
            for (int p = 0; p < 4; p++) {
                uint32_t bh[4], bl[4];
                const uint32_t kaddr = kB + kt * (16 * KST * 2) + p * 32;
                ldmx4t(bh, kaddr);
                ldmx4t(bl, kaddr + (OKL - OKH) * 2);
                mma16(s[2 * p],     ah, &bh[0]);
                mma16(s[2 * p],     al, &bh[0]);
                mma16(s[2 * p],     ah, &bl[0]);
                mma16(s[2 * p + 1], ah, &bh[2]);
                mma16(s[2 * p + 1], al, &bh[2]);
                mma16(s[2 * p + 1], ah, &bl[2]);
            }
        }

        // ---- causal mask on diagonal tiles ----
        const int row0 = m0 + wid * 16 + g;
        const int row1 = row0 + 8;
        if (j0 + FBN - 1 > row0) {
            #pragma unroll
            for (int n = 0; n < 8; n++) {
                int col = j0 + n * 8 + 2 * tg;
                if (col     > row0) s[n][0] = -1e30f;
                if (col + 1 > row0) s[n][1] = -1e30f;
                if (col     > row1) s[n][2] = -1e30f;
                if (col + 1 > row1) s[n][3] = -1e30f;
            }
        }

        // ---- online softmax ----
        float rmax0 = -1e30f, rmax1 = -1e30f;
        #pragma unroll
        for (int n = 0; n < 8; n++) {
            rmax0 = fmaxf(rmax0, fmaxf(s[n][0], s[n][1]));
            rmax1 = fmaxf(rmax1, fmaxf(s[n][2], s[n][3]));
        }
        rmax0 = fmaxf(rmax0, __shfl_xor_sync(0xffffffffu, rmax0, 1));
        rmax0 = fmaxf(rmax0, __shfl_xor_sync(0xffffffffu, rmax0, 2));
        rmax1 = fmaxf(rmax1, __shfl_xor_sync(0xffffffffu, rmax1, 1));
        rmax1 = fmaxf(rmax1, __shfl_xor_sync(0xffffffffu, rmax1, 2));

        float mn0 = fmaxf(m_0, rmax0), mn1 = fmaxf(m_1, rmax1);
        float f0 = __expf(m_0 - mn0), f1 = __expf(m_1 - mn1);
        m_0 = mn0; m_1 = mn1;

        float rs0 = 0.f, rs1 = 0.f;
        #pragma unroll
        for (int n = 0; n < 8; n++) {
            s[n][0] = __expf(s[n][0] - mn0);
            s[n][1] = __expf(s[n][1] - mn0);
            s[n][2] = __expf(s[n][2] - mn1);
            s[n][3] = __expf(s[n][3] - mn1);
            rs0 += s[n][0] + s[n][1];
            rs1 += s[n][2] + s[n][3];
        }
        rs0 += __shfl_xor_sync(0xffffffffu, rs0, 1);
        rs0 += __shfl_xor_sync(0xffffffffu, rs0, 2);
        rs1 += __shfl_xor_sync(0xffffffffu, rs1, 1);
        rs1 += __shfl_xor_sync(0xffffffffu, rs1, 2);
        l_0 = l_0 * f0 + rs0;
        l_1 = l_1 * f1 + rs1;

        #pragma unroll
        for (int n = 0; n < 16; n++) {
            o[n][0] *= f0; o[n][1] *= f0;
            o[n][2] *= f1; o[n][3] *= f1;
        }

        // ---- O += P V  (P hi/lo from S regs; V bf16 hi/lo) ----
        #pragma unroll
        for (int kt = 0; kt < 4; kt++) {
            uint32_t ph[4], pl[4];
            split2(s[2 * kt][0],     s[2 * kt][1],     ph[0], pl[0]);
            split2(s[2 * kt][2],     s[2 * kt][3],     ph[1], pl[1]);
            split2(s[2 * kt + 1][0], s[2 * kt + 1][1], ph[2], pl[2]);
            split2(s[2 * kt + 1][2], s[2 * kt + 1][3], ph[3], pl[3]);
            #pragma unroll
            for (int p = 0; p < 8; p++) {
                uint32_t bh[4], bl[4];
                const uint32_t vaddr = vB + kt * (16 * VST * 2) + p * 32;
                ldmx4t(bh, vaddr);
                ldmx4t(bl, vaddr + (OVL - OVH) * 2);
                mma16(o[2 * p],     ph, &bh[0]);
                mma16(o[2 * p],     pl, &bh[0]);
                mma16(o[2 * p],     ph, &bl[0]);
                mma16(o[2 * p + 1], ph, &bh[2]);
                mma16(o[2 * p + 1], pl, &bh[2]);
                mma16(o[2 * p + 1], ph, &bl[2]);
            }
        }
    }

    // ---- epilogue ----
    const float il0 = 1.0f / l_0;
    const float il1 = 1.0f / l_1;
    const int row0 = m0 + wid * 16 + g;
    float* op0 = &attn_out[(size_t)row0 * HIDDEN + h * HD];
    float* op1 = op0 + (size_t)8 * HIDDEN;
    #pragma unroll
    for (int n = 0; n < 16; n++) {
        int col = n * 8 + 2 * tg;
        *(float2*)&op0[col] = make_float2(o[n][0] * il0, o[n][1] * il0);
        *(float2*)&op1[col] = make_float2(o[n][2] * il1, o[n][3] * il1);
    }
}

// ============================================================================
extern "C" void kernel_launch(void* const* d_in, const int* in_sizes, int n_in,
                              void* d_out, int out_size)
{
    const int*   positions = (const int*)d_in[0];
    const float* hidden    = (const float*)d_in[1];
    const float* w_qkv     = (const float*)d_in[2];
    const float* w_o       = (const float*)d_in[3];
    float* out = (float*)d_out;

    float *qkv = nullptr, *attn = nullptr;
    cudaGetSymbolAddress((void**)&qkv,  g_qkv);
    cudaGetSymbolAddress((void**)&attn, g_attn);

    const int GSM = SM_BF16 * 2;
    cudaFuncSetAttribute(gemm_bf16x3,
                         cudaFuncAttributeMaxDynamicSharedMemorySize, GSM);
    const int ASM_BYTES = ATT_SMEM_ELEMS * 2;   // 141312
    cudaFuncSetAttribute(attn_tc_kernel,
                         cudaFuncAttributeMaxDynamicSharedMemorySize, ASM_BYTES);

    // 1) QKV projection (3xBF16 tensor cores)
    gemm_bf16x3<<<dim3(QKV_N / 128, T_SEQ / 128), 256, GSM>>>(
        hidden, w_qkv, qkv, T_SEQ, QKV_N, HIDDEN);

    // 2) RoPE
    rope_kernel<<<T_SEQ, 256>>>(qkv, positions);

    // 3) Tensor-core flash attention
    attn_tc_kernel<<<dim3(T_SEQ / FBM, NH), 256, ASM_BYTES>>>(qkv, attn);

    // 4) Output projection
    gemm_bf16x3<<<dim3(HIDDEN / 128, T_SEQ / 128), 256, GSM>>>(
        attn, w_o, out, T_SEQ, HIDDEN, HIDDEN);
}

// round 6
// speedup vs baseline: 6.8841x; 1.0485x over previous
#include <cuda_runtime.h>
#include <cuda_bf16.h>
#include <math.h>
#include <stdint.h>

#define T_SEQ  2048
#define HIDDEN 4096
#define NH     32
#define NKV    8
#define HD     128
#define Q_SIZE  (NH * HD)              // 4096
#define KV_SIZE (NKV * HD)             // 1024
#define QKV_N   (Q_SIZE + 2 * KV_SIZE) // 6144
#define SCALE   0.08838834764831845f   // 128^-0.5

// ---------------------------------------------------------------------------
// Global scratch (u32 = packed bf16x2). No cudaMalloc allowed.
// ---------------------------------------------------------------------------
__device__ float    g_qkv[(size_t)T_SEQ * QKV_N];              // fp32 QKV
__device__ uint32_t g_hid_h[(size_t)T_SEQ * HIDDEN / 2];
__device__ uint32_t g_hid_l[(size_t)T_SEQ * HIDDEN / 2];
__device__ uint32_t g_wqkv_h[(size_t)HIDDEN * QKV_N / 2];
__device__ uint32_t g_wqkv_l[(size_t)HIDDEN * QKV_N / 2];
__device__ uint32_t g_wo_h[(size_t)HIDDEN * HIDDEN / 2];
__device__ uint32_t g_wo_l[(size_t)HIDDEN * HIDDEN / 2];
__device__ uint32_t g_qh[(size_t)T_SEQ * Q_SIZE / 2];
__device__ uint32_t g_ql[(size_t)T_SEQ * Q_SIZE / 2];
__device__ uint32_t g_kh[(size_t)T_SEQ * KV_SIZE / 2];
__device__ uint32_t g_kl[(size_t)T_SEQ * KV_SIZE / 2];
__device__ uint32_t g_vh[(size_t)T_SEQ * KV_SIZE / 2];
__device__ uint32_t g_vl[(size_t)T_SEQ * KV_SIZE / 2];
__device__ uint32_t g_ah[(size_t)T_SEQ * Q_SIZE / 2];
__device__ uint32_t g_al[(size_t)T_SEQ * Q_SIZE / 2];

// ---------------------------------------------------------------------------
// Helpers
// ---------------------------------------------------------------------------
__device__ __forceinline__ uint32_t smem_u32(const void* p) {
    uint32_t a;
    asm("{ .reg .u64 t; cvta.to.shared.u64 t, %1; cvt.u32.u64 %0, t; }"
        : "=r"(a) : "l"(p));
    return a;
}
__device__ __forceinline__ void mma16(float* c, const uint32_t* a,
                                      const uint32_t* b) {
    asm volatile(
        "mma.sync.aligned.m16n8k16.row.col.f32.bf16.bf16.f32 "
        "{%0,%1,%2,%3}, {%4,%5,%6,%7}, {%8,%9}, {%0,%1,%2,%3};"
        : "+f"(c[0]), "+f"(c[1]), "+f"(c[2]), "+f"(c[3])
        : "r"(a[0]), "r"(a[1]), "r"(a[2]), "r"(a[3]), "r"(b[0]), "r"(b[1]));
}
__device__ __forceinline__ void ldmx4(uint32_t* r, uint32_t addr) {
    asm volatile(
        "ldmatrix.sync.aligned.m8n8.x4.shared.b16 {%0,%1,%2,%3}, [%4];"
        : "=r"(r[0]), "=r"(r[1]), "=r"(r[2]), "=r"(r[3]) : "r"(addr));
}
__device__ __forceinline__ void ldmx4t(uint32_t* r, uint32_t addr) {
    asm volatile(
        "ldmatrix.sync.aligned.m8n8.x4.trans.shared.b16 {%0,%1,%2,%3}, [%4];"
        : "=r"(r[0]), "=r"(r[1]), "=r"(r[2]), "=r"(r[3]) : "r"(addr));
}
__device__ __forceinline__ void split2(float x, float y,
                                       uint32_t& hi, uint32_t& lo) {
    __nv_bfloat162 h = __floats2bfloat162_rn(x, y);
    float hx = __bfloat162float(h.x);
    float hy = __bfloat162float(h.y);
    __nv_bfloat162 l = __floats2bfloat162_rn(x - hx, y - hy);
    hi = *(uint32_t*)&h;
    lo = *(uint32_t*)&l;
}
__device__ __forceinline__ void cpa16(uint32_t dst, const void* src) {
    asm volatile("cp.async.cg.shared.global [%0], [%1], 16;"
                 :: "r"(dst), "l"(src));
}
__device__ __forceinline__ void cpa_commit() {
    asm volatile("cp.async.commit_group;");
}
template <int N>
__device__ __forceinline__ void cpa_wait() {
    asm volatile("cp.async.wait_group %0;" :: "n"(N));
}

// ---------------------------------------------------------------------------
// fp32 -> bf16 hi/lo split conversion (grid-stride, float4 granularity)
// ---------------------------------------------------------------------------
__global__ __launch_bounds__(256) void convert_split(
    const float4* __restrict__ src, uint2* __restrict__ dh,
    uint2* __restrict__ dl, int n4)
{
    for (int i = blockIdx.x * blockDim.x + threadIdx.x; i < n4;
         i += gridDim.x * blockDim.x) {
        float4 v = src[i];
        uint32_t h0, l0, h1, l1;
        split2(v.x, v.y, h0, l0);
        split2(v.z, v.w, h1, l1);
        dh[i] = make_uint2(h0, h1);
        dl[i] = make_uint2(h0 = l0, l1);  // (h0 reused as tmp)
    }
}

// ---------------------------------------------------------------------------
// RoPE + split: read fp32 qkv, rotate Q (scaled) and K, passthrough V,
// write bf16 hi/lo arrays. One block per token.
// ---------------------------------------------------------------------------
__global__ __launch_bounds__(256) void rope_split_kernel(
    const float* __restrict__ qkv, const int* __restrict__ positions,
    uint32_t* __restrict__ qh, uint32_t* __restrict__ ql,
    uint32_t* __restrict__ kh, uint32_t* __restrict__ kl,
    uint32_t* __restrict__ vh, uint32_t* __restrict__ vl)
{
    __shared__ float s_if[64];
    const int t = blockIdx.x;
    if (threadIdx.x < 64) {
        double e = (double)(2 * threadIdx.x) / (double)HD;
        s_if[threadIdx.x] = (float)pow(500000.0, -e);
    }
    __syncthreads();

    const float p = (float)positions[t];
    const size_t base = (size_t)t * QKV_N;

    for (int idx = threadIdx.x; idx < QKV_N / 2; idx += blockDim.x) {
        uint32_t uh, ul;
        if (idx < (NH + NKV) * 64) {           // Q or K: rope pairs
            const int head = idx >> 6;
            const int i = idx & 63;
            float s, c;
            sincosf(p * s_if[i], &s, &c);
            if (head < NH) {
                float2 x = *(const float2*)&qkv[base + head * HD + 2 * i];
                float o1 = (x.x * c - x.y * s) * SCALE;
                float o2 = (x.y * c + x.x * s) * SCALE;
                split2(o1, o2, uh, ul);
                int d = (t * Q_SIZE + head * HD + 2 * i) >> 1;
                qh[d] = uh; ql[d] = ul;
            } else {
                const int kk = head - NH;
                float2 x = *(const float2*)&qkv[base + Q_SIZE + kk * HD + 2 * i];
                float o1 = x.x * c - x.y * s;
                float o2 = x.y * c + x.x * s;
                split2(o1, o2, uh, ul);
                int d = (t * KV_SIZE + kk * HD + 2 * i) >> 1;
                kh[d] = uh; kl[d] = ul;
            }
        } else {                                // V passthrough
            const int off = idx - (NH + NKV) * 64;   // 0..511
            float2 x = *(const float2*)&qkv[base + Q_SIZE + KV_SIZE + 2 * off];
            split2(x.x, x.y, uh, ul);
            int d = (t * KV_SIZE + 2 * off) >> 1;
            vh[d] = uh; vl[d] = ul;
        }
    }
}

// ---------------------------------------------------------------------------
// BF16(3x) GEMM with pre-split inputs + cp.async double buffering.
// C[M,N] = (Ah+Al)[M,K] @ (Bh+Bl)[K,N].  CTA 128x128, BK=32, 256 thr.
// ---------------------------------------------------------------------------
#define BK  32
#define AST 40
#define BST 136
#define STG_A_L 5120            // elem offsets within a stage
#define STG_B_H 10240
#define STG_B_L 14592
#define STG_ELEMS 18944         // per stage

__global__ __launch_bounds__(256, 2) void gemm_pre(
    const __nv_bfloat16* __restrict__ Ah, const __nv_bfloat16* __restrict__ Al,
    const __nv_bfloat16* __restrict__ Bh, const __nv_bfloat16* __restrict__ Bl,
    float* __restrict__ C, int M, int N, int K)
{
    extern __shared__ __align__(16) __nv_bfloat16 sm[];
    const uint32_t smb = smem_u32(sm);

    const int tid  = threadIdx.x;
    const int wid  = tid >> 5;
    const int lane = tid & 31;
    const int g    = lane >> 2;
    const int tg   = lane & 3;
    const int wm   = (wid >> 2) * 64;
    const int wn   = (wid & 3) * 32;
    const int m0 = blockIdx.y * 128;
    const int n0 = blockIdx.x * 128;

    const int l7  = lane & 7;
    const int l8  = (lane >> 3) & 1;
    const int l16 = lane >> 4;
    const uint32_t aFrag = (uint32_t)(((wm + l7 + l8 * 8) * AST + l16 * 8) * 2);
    const uint32_t bFrag = (uint32_t)(STG_B_H * 2) +
        (uint32_t)(((l7 + l8 * 8) * BST + wn + l16 * 8) * 2);

    // loader indices
    const int ar = tid >> 2, ac = tid & 3;          // A: 2 chunks (rows ar, ar+64)
    const int br = tid >> 4, bc = tid & 15;         // B: 2 chunks (rows br, br+16)

    float acc[4][4][4];
    #pragma unroll
    for (int i = 0; i < 4; i++)
        #pragma unroll
        for (int j = 0; j < 4; j++)
            #pragma unroll
            for (int q = 0; q < 4; q++) acc[i][j][q] = 0.f;

    const int KT = K / BK;

    auto issue = [&](int kt, int s) {
        const int kk = kt * BK;
        const uint32_t sb = smb + (uint32_t)(s * STG_ELEMS * 2);
        #pragma unroll
        for (int i = 0; i < 2; i++) {
            const int row = ar + i * 64;
            cpa16(sb + (row * AST + ac * 8) * 2,
                  Ah + (size_t)(m0 + row) * K + kk + ac * 8);
            cpa16(sb + (STG_A_L + row * AST + ac * 8) * 2,
                  Al + (size_t)(m0 + row) * K + kk + ac * 8);
        }
        #pragma unroll
        for (int i = 0; i < 2; i++) {
            const int row = br + i * 16;
            cpa16(sb + (STG_B_H + row * BST + bc * 8) * 2,
                  Bh + (size_t)(kk + row) * N + n0 + bc * 8);
            cpa16(sb + (STG_B_L + row * BST + bc * 8) * 2,
                  Bl + (size_t)(kk + row) * N + n0 + bc * 8);
        }
    };

    issue(0, 0);
    cpa_commit();

    for (int kt = 0; kt < KT; kt++) {
        if (kt + 1 < KT) issue(kt + 1, (kt + 1) & 1);
        cpa_commit();
        cpa_wait<1>();
        __syncthreads();

        const uint32_t sb = smb + (uint32_t)((kt & 1) * STG_ELEMS * 2);
        const uint32_t aA = sb + aFrag;
        const uint32_t bA = sb + bFrag;
        #pragma unroll
        for (int ks = 0; ks < 2; ks++) {
            uint32_t ah[4][4], al[4][4];
            #pragma unroll
            for (int mt = 0; mt < 4; mt++) {
                const uint32_t a = aA + mt * (16 * AST * 2) + ks * 32;
                ldmx4(ah[mt], a);
                ldmx4(al[mt], a + STG_A_L * 2);
            }
            uint32_t bh[2][4], bl[2][4];
            #pragma unroll
            for (int pp = 0; pp < 2; pp++) {
                const uint32_t b = bA + ks * (16 * BST * 2) + pp * 32;
                ldmx4t(bh[pp], b);
                ldmx4t(bl[pp], b + (STG_B_L - STG_B_H) * 2);
            }
            #pragma unroll
            for (int mt = 0; mt < 4; mt++)
                #pragma unroll
                for (int nt = 0; nt < 4; nt++) {
                    const uint32_t* bhf = &bh[nt >> 1][(nt & 1) * 2];
                    const uint32_t* blf = &bl[nt >> 1][(nt & 1) * 2];
                    mma16(acc[mt][nt], ah[mt], bhf);
                    mma16(acc[mt][nt], al[mt], bhf);
                    mma16(acc[mt][nt], ah[mt], blf);
                }
        }
        __syncthreads();
    }

    #pragma unroll
    for (int mt = 0; mt < 4; mt++) {
        const int row = m0 + wm + mt * 16 + g;
        #pragma unroll
        for (int nt = 0; nt < 4; nt++) {
            const int col = n0 + wn + nt * 8 + tg * 2;
            *(float2*)&C[(size_t)row * N + col] =
                make_float2(acc[mt][nt][0], acc[mt][nt][1]);
            *(float2*)&C[(size_t)(row + 8) * N + col] =
                make_float2(acc[mt][nt][2], acc[mt][nt][3]);
        }
    }
}

// ---------------------------------------------------------------------------
// Tensor-core causal GQA flash attention, pre-split bf16 inputs, cp.async
// double-buffered K/V.  CTA: 128 q-rows x 1 head, 8 warps.
// Q smem [128][136] hi/lo; K,V [64][136] hi/lo x 2 stages.
// Output written as bf16 hi/lo (feeds O-proj GEMM).
// ---------------------------------------------------------------------------
#define FBM 128
#define FBN 64
#define KVST 136
#define OQL_E   17408                    // 128*136
#define KVB_E   34816                    // after Q hi+lo
#define KV_STG  34816                    // per-stage elems (Kh,Kl,Vh,Vl)
#define SK_L    8704
#define SV_H    17408
#define SV_L    26112
#define ATT_SMEM_BYTES ((KVB_E + 2 * KV_STG) * 2)   // 208896

__global__ __launch_bounds__(256, 1) void attn_tc2_kernel(
    const __nv_bfloat16* __restrict__ Qh, const __nv_bfloat16* __restrict__ Ql,
    const __nv_bfloat16* __restrict__ Kh, const __nv_bfloat16* __restrict__ Kl,
    const __nv_bfloat16* __restrict__ Vh, const __nv_bfloat16* __restrict__ Vl,
    uint32_t* __restrict__ Oh, uint32_t* __restrict__ Ol)
{
    extern __shared__ __align__(16) __nv_bfloat16 asmem[];
    const uint32_t smb = smem_u32(asmem);

    const int tid  = threadIdx.x;
    const int wid  = tid >> 5;
    const int lane = tid & 31;
    const int g    = lane >> 2;
    const int tg   = lane & 3;
    const int mt   = (gridDim.x - 1) - blockIdx.x;   // heavy blocks first
    const int m0   = mt * FBM;
    const int h    = blockIdx.y;
    const int kh   = h >> 2;

    const int l7  = lane & 7;
    const int l8  = (lane >> 3) & 1;
    const int l16 = lane >> 4;

    // loader indices: row = c>>4, chunk = c&15 (16 chunks of 8 elems per row)
    const int lr = tid >> 4;       // 0..15
    const int lc = tid & 15;

    // ---- issue Q (once) ----
    #pragma unroll
    for (int i = 0; i < 8; i++) {
        const int row = lr + i * 16;
        const size_t go = (size_t)(m0 + row) * Q_SIZE + h * HD + lc * 8;
        cpa16(smb + (row * KVST + lc * 8) * 2, Qh + go);
        cpa16(smb + (OQL_E + row * KVST + lc * 8) * 2, Ql + go);
    }
    cpa_commit();

    auto issueKV = [&](int j0, int s) {
        const uint32_t sb = smb + (uint32_t)((KVB_E + s * KV_STG) * 2);
        #pragma unroll
        for (int i = 0; i < 4; i++) {
            const int row = lr + i * 16;    // 0..63
            const size_t go = (size_t)(j0 + row) * KV_SIZE + kh * HD + lc * 8;
            const uint32_t so = (row * KVST + lc * 8) * 2;
            cpa16(sb + so, Kh + go);
            cpa16(sb + SK_L * 2 + so, Kl + go);
            cpa16(sb + SV_H * 2 + so, Vh + go);
            cpa16(sb + SV_L * 2 + so, Vl + go);
        }
    };

    issueKV(0, 0);
    cpa_commit();

    float o[16][4];
    #pragma unroll
    for (int n = 0; n < 16; n++)
        #pragma unroll
        for (int q = 0; q < 4; q++) o[n][q] = 0.f;
    float m_0 = -1e30f, m_1 = -1e30f, l_0 = 0.f, l_1 = 0.f;

    const uint32_t qFrag =
        (uint32_t)(((wid * 16 + l7 + l8 * 8) * KVST + l16 * 8) * 2);
    const uint32_t kFrag =
        (uint32_t)(((l7 + l16 * 8) * KVST + l8 * 8) * 2);   // non-trans B
    const uint32_t vFrag =
        (uint32_t)(((l7 + l8 * 8) * KVST + l16 * 8) * 2);   // trans B

    const int ntiles = m0 / FBN + 2;

    for (int jt = 0; jt < ntiles; jt++) {
        if (jt + 1 < ntiles) issueKV((jt + 1) * FBN, (jt + 1) & 1);
        cpa_commit();
        cpa_wait<1>();
        __syncthreads();

        const int j0 = jt * FBN;
        const uint32_t sb = smb + (uint32_t)((KVB_E + (jt & 1) * KV_STG) * 2);
        const uint32_t kB = sb + kFrag;
        const uint32_t vB = sb + SV_H * 2 + vFrag;

        // ---- S = Q K^T (warp: 16 x 64) ----
        float s[8][4];
        #pragma unroll
        for (int n = 0; n < 8; n++)
            #pragma unroll
            for (int q = 0; q < 4; q++) s[n][q] = 0.f;

        #pragma unroll
        for (int kt = 0; kt < 8; kt++) {
            uint32_t ah[4], al[4];
            ldmx4(ah, smb + qFrag + kt * 32);
            ldmx4(al, smb + OQL_E * 2 + qFrag + kt * 32);
            #pragma unroll
            for (int p = 0; p < 4; p++) {
                uint32_t bh[4], bl[4];
                const uint32_t ka = kB + p * (16 * KVST * 2) + kt * 32;
                ldmx4(bh, ka);
                ldmx4(bl, ka + SK_L * 2);
                mma16(s[2 * p],     ah, &bh[0]);
                mma16(s[2 * p],     al, &bh[0]);
                mma16(s[2 * p],     ah, &bl[0]);
                mma16(s[2 * p + 1], ah, &bh[2]);
                mma16(s[2 * p + 1], al, &bh[2]);
                mma16(s[2 * p + 1], ah, &bl[2]);
            }
        }

        // ---- causal mask ----
        const int row0 = m0 + wid * 16 + g;
        const int row1 = row0 + 8;
        if (j0 + FBN - 1 > row0) {
            #pragma unroll
            for (int n = 0; n < 8; n++) {
                int col = j0 + n * 8 + 2 * tg;
                if (col     > row0) s[n][0] = -1e30f;
                if (col + 1 > row0) s[n][1] = -1e30f;
                if (col     > row1) s[n][2] = -1e30f;
                if (col + 1 > row1) s[n][3] = -1e30f;
            }
        }

        // ---- online softmax ----
        float rmax0 = -1e30f, rmax1 = -1e30f;
        #pragma unroll
        for (int n = 0; n < 8; n++) {
            rmax0 = fmaxf(rmax0, fmaxf(s[n][0], s[n][1]));
            rmax1 = fmaxf(rmax1, fmaxf(s[n][2], s[n][3]));
        }
        rmax0 = fmaxf(rmax0, __shfl_xor_sync(0xffffffffu, rmax0, 1));
        rmax0 = fmaxf(rmax0, __shfl_xor_sync(0xffffffffu, rmax0, 2));
        rmax1 = fmaxf(rmax1, __shfl_xor_sync(0xffffffffu, rmax1, 1));
        rmax1 = fmaxf(rmax1, __shfl_xor_sync(0xffffffffu, rmax1, 2));

        float mn0 = fmaxf(m_0, rmax0), mn1 = fmaxf(m_1, rmax1);
        float f0 = __expf(m_0 - mn0), f1 = __expf(m_1 - mn1);
        m_0 = mn0; m_1 = mn1;

        float rs0 = 0.f, rs1 = 0.f;
        #pragma unroll
        for (int n = 0; n < 8; n++) {
            s[n][0] = __expf(s[n][0] - mn0);
            s[n][1] = __expf(s[n][1] - mn0);
            s[n][2] = __expf(s[n][2] - mn1);
            s[n][3] = __expf(s[n][3] - mn1);
            rs0 += s[n][0] + s[n][1];
            rs1 += s[n][2] + s[n][3];
        }
        rs0 += __shfl_xor_sync(0xffffffffu, rs0, 1);
        rs0 += __shfl_xor_sync(0xffffffffu, rs0, 2);
        rs1 += __shfl_xor_sync(0xffffffffu, rs1, 1);
        rs1 += __shfl_xor_sync(0xffffffffu, rs1, 2);
        l_0 = l_0 * f0 + rs0;
        l_1 = l_1 * f1 + rs1;

        #pragma unroll
        for (int n = 0; n < 16; n++) {
            o[n][0] *= f0; o[n][1] *= f0;
            o[n][2] *= f1; o[n][3] *= f1;
        }

        // ---- O += P V ----
        #pragma unroll
        for (int kt = 0; kt < 4; kt++) {
            uint32_t ph[4], pl[4];
            split2(s[2 * kt][0],     s[2 * kt][1],     ph[0], pl[0]);
            split2(s[2 * kt][2],     s[2 * kt][3],     ph[1], pl[1]);
            split2(s[2 * kt + 1][0], s[2 * kt + 1][1], ph[2], pl[2]);
            split2(s[2 * kt + 1][2], s[2 * kt + 1][3], ph[3], pl[3]);
            #pragma unroll
            for (int p = 0; p < 8; p++) {
                uint32_t bh[4], bl[4];
                const uint32_t va = vB + kt * (16 * KVST * 2) + p * 32;
                ldmx4t(bh, va);
                ldmx4t(bl, va + (SV_L - SV_H) * 2);
                mma16(o[2 * p],     ph, &bh[0]);
                mma16(o[2 * p],     pl, &bh[0]);
                mma16(o[2 * p],     ph, &bl[0]);
                mma16(o[2 * p + 1], ph, &bh[2]);
                mma16(o[2 * p + 1], pl, &bh[2]);
                mma16(o[2 * p + 1], ph, &bl[2]);
            }
        }
        __syncthreads();
    }

    // ---- epilogue: write bf16 hi/lo for O-proj GEMM ----
    const float il0 = 1.0f / l_0;
    const float il1 = 1.0f / l_1;
    const int row0 = m0 + wid * 16 + g;
    #pragma unroll
    for (int n = 0; n < 16; n++) {
        const int col = n * 8 + 2 * tg;
        uint32_t uh, ul;
        split2(o[n][0] * il0, o[n][1] * il0, uh, ul);
        int d = ((size_t)row0 * Q_SIZE + h * HD + col) >> 1;
        Oh[d] = uh; Ol[d] = ul;
        split2(o[n][2] * il1, o[n][3] * il1, uh, ul);
        d = ((size_t)(row0 + 8) * Q_SIZE + h * HD + col) >> 1;
        Oh[d] = uh; Ol[d] = ul;
    }
}

// ---------------------------------------------------------------------------
extern "C" void kernel_launch(void* const* d_in, const int* in_sizes, int n_in,
                              void* d_out, int out_size)
{
    const int*   positions = (const int*)d_in[0];
    const float* hidden    = (const float*)d_in[1];
    const float* w_qkv     = (const float*)d_in[2];
    const float* w_o       = (const float*)d_in[3];
    float* out = (float*)d_out;

    float* qkv = nullptr;
    uint32_t *hid_h, *hid_l, *wqkv_h, *wqkv_l, *wo_h, *wo_l;
    uint32_t *qh, *ql, *kh, *kl, *vh, *vl, *ah, *al;
    cudaGetSymbolAddress((void**)&qkv,    g_qkv);
    cudaGetSymbolAddress((void**)&hid_h,  g_hid_h);
    cudaGetSymbolAddress((void**)&hid_l,  g_hid_l);
    cudaGetSymbolAddress((void**)&wqkv_h, g_wqkv_h);
    cudaGetSymbolAddress((void**)&wqkv_l, g_wqkv_l);
    cudaGetSymbolAddress((void**)&wo_h,   g_wo_h);
    cudaGetSymbolAddress((void**)&wo_l,   g_wo_l);
    cudaGetSymbolAddress((void**)&qh, g_qh);
    cudaGetSymbolAddress((void**)&ql, g_ql);
    cudaGetSymbolAddress((void**)&kh, g_kh);
    cudaGetSymbolAddress((void**)&kl, g_kl);
    cudaGetSymbolAddress((void**)&vh, g_vh);
    cudaGetSymbolAddress((void**)&vl, g_vl);
    cudaGetSymbolAddress((void**)&ah, g_ah);
    cudaGetSymbolAddress((void**)&al, g_al);

    const int GSM = 2 * STG_ELEMS * 2;  // 75776
    cudaFuncSetAttribute(gemm_pre,
                         cudaFuncAttributeMaxDynamicSharedMemorySize, GSM);
    cudaFuncSetAttribute(attn_tc2_kernel,
                         cudaFuncAttributeMaxDynamicSharedMemorySize,
                         ATT_SMEM_BYTES);

    // 0) split conversions
    convert_split<<<2048, 256>>>((const float4*)hidden,
                                 (uint2*)hid_h, (uint2*)hid_l,
                                 T_SEQ * HIDDEN / 4);
    convert_split<<<4096, 256>>>((const float4*)w_qkv,
                                 (uint2*)wqkv_h, (uint2*)wqkv_l,
                                 HIDDEN * QKV_N / 4);
    convert_split<<<4096, 256>>>((const float4*)w_o,
                                 (uint2*)wo_h, (uint2*)wo_l,
                                 HIDDEN * HIDDEN / 4);

    // 1) QKV projection
    gemm_pre<<<dim3(QKV_N / 128, T_SEQ / 128), 256, GSM>>>(
        (const __nv_bfloat16*)hid_h, (const __nv_bfloat16*)hid_l,
        (const __nv_bfloat16*)wqkv_h, (const __nv_bfloat16*)wqkv_l,
        qkv, T_SEQ, QKV_N, HIDDEN);

    // 2) RoPE + split to bf16
    rope_split_kernel<<<T_SEQ, 256>>>(qkv, positions, qh, ql, kh, kl, vh, vl);

    // 3) Flash attention (tensor cores)
    attn_tc2_kernel<<<dim3(T_SEQ / FBM, NH), 256, ATT_SMEM_BYTES>>>(
        (const __nv_bfloat16*)qh, (const __nv_bfloat16*)ql,
        (const __nv_bfloat16*)kh, (const __nv_bfloat16*)kl,
        (const __nv_bfloat16*)vh, (const __nv_bfloat16*)vl,
        ah, al);

    // 4) Output projection
    gemm_pre<<<dim3(HIDDEN / 128, T_SEQ / 128), 256, GSM>>>(
        (const __nv_bfloat16*)ah, (const __nv_bfloat16*)al,
        (const __nv_bfloat16*)wo_h, (const __nv_bfloat16*)wo_l,
        out, T_SEQ, HIDDEN, HIDDEN);
}

// round 7
// speedup vs baseline: 6.9610x; 1.0112x over previous
#include <cuda_runtime.h>
#include <cuda_bf16.h>
#include <math.h>
#include <stdint.h>

#define T_SEQ  2048
#define HIDDEN 4096
#define NH     32
#define NKV    8
#define HD     128
#define Q_SIZE  (NH * HD)              // 4096
#define KV_SIZE (NKV * HD)             // 1024
#define QKV_N   (Q_SIZE + 2 * KV_SIZE) // 6144
#define SCALE   0.08838834764831845f   // 128^-0.5

// ---------------------------------------------------------------------------
// Global scratch (u32 = packed bf16x2). No cudaMalloc allowed.
// ---------------------------------------------------------------------------
__device__ float    g_qkv[(size_t)T_SEQ * QKV_N];              // fp32 QKV
__device__ uint32_t g_hid_h[(size_t)T_SEQ * HIDDEN / 2];
__device__ uint32_t g_hid_l[(size_t)T_SEQ * HIDDEN / 2];
__device__ uint32_t g_wqkv_h[(size_t)HIDDEN * QKV_N / 2];
__device__ uint32_t g_wqkv_l[(size_t)HIDDEN * QKV_N / 2];
__device__ uint32_t g_wo_h[(size_t)HIDDEN * HIDDEN / 2];
__device__ uint32_t g_wo_l[(size_t)HIDDEN * HIDDEN / 2];
__device__ uint32_t g_qh[(size_t)T_SEQ * Q_SIZE / 2];
__device__ uint32_t g_ql[(size_t)T_SEQ * Q_SIZE / 2];
__device__ uint32_t g_kh[(size_t)T_SEQ * KV_SIZE / 2];
__device__ uint32_t g_kl[(size_t)T_SEQ * KV_SIZE / 2];
__device__ uint32_t g_vh[(size_t)T_SEQ * KV_SIZE / 2];
__device__ uint32_t g_vl[(size_t)T_SEQ * KV_SIZE / 2];
__device__ uint32_t g_ah[(size_t)T_SEQ * Q_SIZE / 2];
__device__ uint32_t g_al[(size_t)T_SEQ * Q_SIZE / 2];

// ---------------------------------------------------------------------------
// Helpers
// ---------------------------------------------------------------------------
__device__ __forceinline__ uint32_t smem_u32(const void* p) {
    uint32_t a;
    asm("{ .reg .u64 t; cvta.to.shared.u64 t, %1; cvt.u32.u64 %0, t; }"
        : "=r"(a) : "l"(p));
    return a;
}
__device__ __forceinline__ void mma16(float* c, const uint32_t* a,
                                      const uint32_t* b) {
    asm volatile(
        "mma.sync.aligned.m16n8k16.row.col.f32.bf16.bf16.f32 "
        "{%0,%1,%2,%3}, {%4,%5,%6,%7}, {%8,%9}, {%0,%1,%2,%3};"
        : "+f"(c[0]), "+f"(c[1]), "+f"(c[2]), "+f"(c[3])
        : "r"(a[0]), "r"(a[1]), "r"(a[2]), "r"(a[3]), "r"(b[0]), "r"(b[1]));
}
__device__ __forceinline__ void ldmx4(uint32_t* r, uint32_t addr) {
    asm volatile(
        "ldmatrix.sync.aligned.m8n8.x4.shared.b16 {%0,%1,%2,%3}, [%4];"
        : "=r"(r[0]), "=r"(r[1]), "=r"(r[2]), "=r"(r[3]) : "r"(addr));
}
__device__ __forceinline__ void ldmx4t(uint32_t* r, uint32_t addr) {
    asm volatile(
        "ldmatrix.sync.aligned.m8n8.x4.trans.shared.b16 {%0,%1,%2,%3}, [%4];"
        : "=r"(r[0]), "=r"(r[1]), "=r"(r[2]), "=r"(r[3]) : "r"(addr));
}
__device__ __forceinline__ void split2(float x, float y,
                                       uint32_t& hi, uint32_t& lo) {
    __nv_bfloat162 h = __floats2bfloat162_rn(x, y);
    float hx = __bfloat162float(h.x);
    float hy = __bfloat162float(h.y);
    __nv_bfloat162 l = __floats2bfloat162_rn(x - hx, y - hy);
    hi = *(uint32_t*)&h;
    lo = *(uint32_t*)&l;
}
__device__ __forceinline__ void cpa16(uint32_t dst, const void* src) {
    asm volatile("cp.async.cg.shared.global [%0], [%1], 16;"
                 :: "r"(dst), "l"(src));
}
__device__ __forceinline__ void cpa_commit() {
    asm volatile("cp.async.commit_group;");
}
template <int N>
__device__ __forceinline__ void cpa_wait() {
    asm volatile("cp.async.wait_group %0;" :: "n"(N));
}

// ---------------------------------------------------------------------------
// fp32 -> bf16 hi/lo split conversion (grid-stride, float4 granularity)
// ---------------------------------------------------------------------------
__global__ __launch_bounds__(256) void convert_split(
    const float4* __restrict__ src, uint2* __restrict__ dh,
    uint2* __restrict__ dl, int n4)
{
    for (int i = blockIdx.x * blockDim.x + threadIdx.x; i < n4;
         i += gridDim.x * blockDim.x) {
        float4 v = src[i];
        uint32_t h0, l0, h1, l1;
        split2(v.x, v.y, h0, l0);
        split2(v.z, v.w, h1, l1);
        dh[i] = make_uint2(h0, h1);
        dl[i] = make_uint2(l0, l1);
    }
}

// ---------------------------------------------------------------------------
// RoPE + split to bf16 hi/lo. One block per token.
// ---------------------------------------------------------------------------
__global__ __launch_bounds__(256) void rope_split_kernel(
    const float* __restrict__ qkv, const int* __restrict__ positions,
    uint32_t* __restrict__ qh, uint32_t* __restrict__ ql,
    uint32_t* __restrict__ kh, uint32_t* __restrict__ kl,
    uint32_t* __restrict__ vh, uint32_t* __restrict__ vl)
{
    __shared__ float s_if[64];
    const int t = blockIdx.x;
    if (threadIdx.x < 64) {
        double e = (double)(2 * threadIdx.x) / (double)HD;
        s_if[threadIdx.x] = (float)pow(500000.0, -e);
    }
    __syncthreads();

    const float p = (float)positions[t];
    const size_t base = (size_t)t * QKV_N;

    for (int idx = threadIdx.x; idx < QKV_N / 2; idx += blockDim.x) {
        uint32_t uh, ul;
        if (idx < (NH + NKV) * 64) {
            const int head = idx >> 6;
            const int i = idx & 63;
            float s, c;
            sincosf(p * s_if[i], &s, &c);
            if (head < NH) {
                float2 x = *(const float2*)&qkv[base + head * HD + 2 * i];
                float o1 = (x.x * c - x.y * s) * SCALE;
                float o2 = (x.y * c + x.x * s) * SCALE;
                split2(o1, o2, uh, ul);
                int d = (t * Q_SIZE + head * HD + 2 * i) >> 1;
                qh[d] = uh; ql[d] = ul;
            } else {
                const int kk = head - NH;
                float2 x = *(const float2*)&qkv[base + Q_SIZE + kk * HD + 2 * i];
                float o1 = x.x * c - x.y * s;
                float o2 = x.y * c + x.x * s;
                split2(o1, o2, uh, ul);
                int d = (t * KV_SIZE + kk * HD + 2 * i) >> 1;
                kh[d] = uh; kl[d] = ul;
            }
        } else {
            const int off = idx - (NH + NKV) * 64;
            float2 x = *(const float2*)&qkv[base + Q_SIZE + KV_SIZE + 2 * off];
            split2(x.x, x.y, uh, ul);
            int d = (t * KV_SIZE + 2 * off) >> 1;
            vh[d] = uh; vl[d] = ul;
        }
    }
}

// ---------------------------------------------------------------------------
// BF16(3x) GEMM, pre-split inputs, 3-stage cp.async, ONE barrier per k-iter.
// C[M,N] = (Ah+Al)[M,K] @ (Bh+Bl)[K,N].  CTA 128x128, BK=32, 256 thr.
// ---------------------------------------------------------------------------
#define BK  32
#define AST 40
#define BST 136
#define STG_A_L 5120            // elem offsets within a stage
#define STG_B_H 10240
#define STG_B_L 14592
#define STG_ELEMS 18944         // per stage (37888 B)
#define NSTG 3

__global__ __launch_bounds__(256, 2) void gemm_pre(
    const __nv_bfloat16* __restrict__ Ah, const __nv_bfloat16* __restrict__ Al,
    const __nv_bfloat16* __restrict__ Bh, const __nv_bfloat16* __restrict__ Bl,
    float* __restrict__ C, int M, int N, int K)
{
    extern __shared__ __align__(16) __nv_bfloat16 sm[];
    const uint32_t smb = smem_u32(sm);

    const int tid  = threadIdx.x;
    const int wid  = tid >> 5;
    const int lane = tid & 31;
    const int g    = lane >> 2;
    const int tg   = lane & 3;
    const int wm   = (wid >> 2) * 64;
    const int wn   = (wid & 3) * 32;
    const int m0 = blockIdx.y * 128;
    const int n0 = blockIdx.x * 128;

    const int l7  = lane & 7;
    const int l8  = (lane >> 3) & 1;
    const int l16 = lane >> 4;
    const uint32_t aFrag = (uint32_t)(((wm + l7 + l8 * 8) * AST + l16 * 8) * 2);
    const uint32_t bFrag = (uint32_t)(STG_B_H * 2) +
        (uint32_t)(((l7 + l8 * 8) * BST + wn + l16 * 8) * 2);

    const int ar = tid >> 2, ac = tid & 3;
    const int br = tid >> 4, bc = tid & 15;

    float acc[4][4][4];
    #pragma unroll
    for (int i = 0; i < 4; i++)
        #pragma unroll
        for (int j = 0; j < 4; j++)
            #pragma unroll
            for (int q = 0; q < 4; q++) acc[i][j][q] = 0.f;

    const int KT = K / BK;

    auto issue = [&](int kt, int s) {
        const int kk = kt * BK;
        const uint32_t sb = smb + (uint32_t)(s * STG_ELEMS * 2);
        #pragma unroll
        for (int i = 0; i < 2; i++) {
            const int row = ar + i * 64;
            cpa16(sb + (row * AST + ac * 8) * 2,
                  Ah + (size_t)(m0 + row) * K + kk + ac * 8);
            cpa16(sb + (STG_A_L + row * AST + ac * 8) * 2,
                  Al + (size_t)(m0 + row) * K + kk + ac * 8);
        }
        #pragma unroll
        for (int i = 0; i < 2; i++) {
            const int row = br + i * 16;
            cpa16(sb + (STG_B_H + row * BST + bc * 8) * 2,
                  Bh + (size_t)(kk + row) * N + n0 + bc * 8);
            cpa16(sb + (STG_B_L + row * BST + bc * 8) * 2,
                  Bl + (size_t)(kk + row) * N + n0 + bc * 8);
        }
    };

    // prologue: stages 0 and 1 in flight
    issue(0, 0); cpa_commit();
    issue(1, 1); cpa_commit();

    int stage = 0;
    for (int kt = 0; kt < KT; kt++) {
        cpa_wait<1>();        // stage kt complete (kt+1 may be in flight)
        __syncthreads();      // all warps done with stage (kt-1)%3 AND see kt

        // write stage (kt+2)%3 == (kt-1)%3, consumed at iteration kt-1
        if (kt + 2 < KT) {
            int s2 = stage + 2; if (s2 >= NSTG) s2 -= NSTG;
            issue(kt + 2, s2);
        }
        cpa_commit();         // uniform group accounting (empty ok)

        const uint32_t sb = smb + (uint32_t)(stage * STG_ELEMS * 2);
        const uint32_t aA = sb + aFrag;
        const uint32_t bA = sb + bFrag;
        #pragma unroll
        for (int ks = 0; ks < 2; ks++) {
            uint32_t ah[4][4], al[4][4];
            #pragma unroll
            for (int mt = 0; mt < 4; mt++) {
                const uint32_t a = aA + mt * (16 * AST * 2) + ks * 32;
                ldmx4(ah[mt], a);
                ldmx4(al[mt], a + STG_A_L * 2);
            }
            uint32_t bh[2][4], bl[2][4];
            #pragma unroll
            for (int pp = 0; pp < 2; pp++) {
                const uint32_t b = bA + ks * (16 * BST * 2) + pp * 32;
                ldmx4t(bh[pp], b);
                ldmx4t(bl[pp], b + (STG_B_L - STG_B_H) * 2);
            }
            #pragma unroll
            for (int mt = 0; mt < 4; mt++)
                #pragma unroll
                for (int nt = 0; nt < 4; nt++) {
                    const uint32_t* bhf = &bh[nt >> 1][(nt & 1) * 2];
                    const uint32_t* blf = &bl[nt >> 1][(nt & 1) * 2];
                    mma16(acc[mt][nt], ah[mt], bhf);
                    mma16(acc[mt][nt], al[mt], bhf);
                    mma16(acc[mt][nt], ah[mt], blf);
                }
        }
        if (++stage == NSTG) stage = 0;
    }

    #pragma unroll
    for (int mt = 0; mt < 4; mt++) {
        const int row = m0 + wm + mt * 16 + g;
        #pragma unroll
        for (int nt = 0; nt < 4; nt++) {
            const int col = n0 + wn + nt * 8 + tg * 2;
            *(float2*)&C[(size_t)row * N + col] =
                make_float2(acc[mt][nt][0], acc[mt][nt][1]);
            *(float2*)&C[(size_t)(row + 8) * N + col] =
                make_float2(acc[mt][nt][2], acc[mt][nt][3]);
        }
    }
}

// ---------------------------------------------------------------------------
// Tensor-core causal GQA flash attention (unchanged from R6; ~290us).
// ---------------------------------------------------------------------------
#define FBM 128
#define FBN 64
#define KVST 136
#define OQL_E   17408
#define KVB_E   34816
#define KV_STG  34816
#define SK_L    8704
#define SV_H    17408
#define SV_L    26112
#define ATT_SMEM_BYTES ((KVB_E + 2 * KV_STG) * 2)   // 208896

__global__ __launch_bounds__(256, 1) void attn_tc2_kernel(
    const __nv_bfloat16* __restrict__ Qh, const __nv_bfloat16* __restrict__ Ql,
    const __nv_bfloat16* __restrict__ Kh, const __nv_bfloat16* __restrict__ Kl,
    const __nv_bfloat16* __restrict__ Vh, const __nv_bfloat16* __restrict__ Vl,
    uint32_t* __restrict__ Oh, uint32_t* __restrict__ Ol)
{
    extern __shared__ __align__(16) __nv_bfloat16 asmem[];
    const uint32_t smb = smem_u32(asmem);

    const int tid  = threadIdx.x;
    const int wid  = tid >> 5;
    const int lane = tid & 31;
    const int g    = lane >> 2;
    const int tg   = lane & 3;
    const int mt   = (gridDim.x - 1) - blockIdx.x;
    const int m0   = mt * FBM;
    const int h    = blockIdx.y;
    const int kh   = h >> 2;

    const int l7  = lane & 7;
    const int l8  = (lane >> 3) & 1;
    const int l16 = lane >> 4;

    const int lr = tid >> 4;
    const int lc = tid & 15;

    #pragma unroll
    for (int i = 0; i < 8; i++) {
        const int row = lr + i * 16;
        const size_t go = (size_t)(m0 + row) * Q_SIZE + h * HD + lc * 8;
        cpa16(smb + (row * KVST + lc * 8) * 2, Qh + go);
        cpa16(smb + (OQL_E + row * KVST + lc * 8) * 2, Ql + go);
    }
    cpa_commit();

    auto issueKV = [&](int j0, int s) {
        const uint32_t sb = smb + (uint32_t)((KVB_E + s * KV_STG) * 2);
        #pragma unroll
        for (int i = 0; i < 4; i++) {
            const int row = lr + i * 16;
            const size_t go = (size_t)(j0 + row) * KV_SIZE + kh * HD + lc * 8;
            const uint32_t so = (row * KVST + lc * 8) * 2;
            cpa16(sb + so, Kh + go);
            cpa16(sb + SK_L * 2 + so, Kl + go);
            cpa16(sb + SV_H * 2 + so, Vh + go);
            cpa16(sb + SV_L * 2 + so, Vl + go);
        }
    };

    issueKV(0, 0);
    cpa_commit();

    float o[16][4];
    #pragma unroll
    for (int n = 0; n < 16; n++)
        #pragma unroll
        for (int q = 0; q < 4; q++) o[n][q] = 0.f;
    float m_0 = -1e30f, m_1 = -1e30f, l_0 = 0.f, l_1 = 0.f;

    const uint32_t qFrag =
        (uint32_t)(((wid * 16 + l7 + l8 * 8) * KVST + l16 * 8) * 2);
    const uint32_t kFrag =
        (uint32_t)(((l7 + l16 * 8) * KVST + l8 * 8) * 2);
    const uint32_t vFrag =
        (uint32_t)(((l7 + l8 * 8) * KVST + l16 * 8) * 2);

    const int ntiles = m0 / FBN + 2;

    for (int jt = 0; jt < ntiles; jt++) {
        if (jt + 1 < ntiles) issueKV((jt + 1) * FBN, (jt + 1) & 1);
        cpa_commit();
        cpa_wait<1>();
        __syncthreads();

        const int j0 = jt * FBN;
        const uint32_t sb = smb + (uint32_t)((KVB_E + (jt & 1) * KV_STG) * 2);
        const uint32_t kB = sb + kFrag;
        const uint32_t vB = sb + SV_H * 2 + vFrag;

        float s[8][4];
        #pragma unroll
        for (int n = 0; n < 8; n++)
            #pragma unroll
            for (int q = 0; q < 4; q++) s[n][q] = 0.f;

        #pragma unroll
        for (int kt = 0; kt < 8; kt++) {
            uint32_t ah[4], al[4];
            ldmx4(ah, smb + qFrag + kt * 32);
            ldmx4(al, smb + OQL_E * 2 + qFrag + kt * 32);
            #pragma unroll
            for (int p = 0; p < 4; p++) {
                uint32_t bh[4], bl[4];
                const uint32_t ka = kB + p * (16 * KVST * 2) + kt * 32;
                ldmx4(bh, ka);
                ldmx4(bl, ka + SK_L * 2);
                mma16(s[2 * p],     ah, &bh[0]);
                mma16(s[2 * p],     al, &bh[0]);
                mma16(s[2 * p],     ah, &bl[0]);
                mma16(s[2 * p + 1], ah, &bh[2]);
                mma16(s[2 * p + 1], al, &bh[2]);
                mma16(s[2 * p + 1], ah, &bl[2]);
            }
        }

        const int row0 = m0 + wid * 16 + g;
        const int row1 = row0 + 8;
        if (j0 + FBN - 1 > row0) {
            #pragma unroll
            for (int n = 0; n < 8; n++) {
                int col = j0 + n * 8 + 2 * tg;
                if (col     > row0) s[n][0] = -1e30f;
                if (col + 1 > row0) s[n][1] = -1e30f;
                if (col     > row1) s[n][2] = -1e30f;
                if (col + 1 > row1) s[n][3] = -1e30f;
            }
        }

        float rmax0 = -1e30f, rmax1 = -1e30f;
        #pragma unroll
        for (int n = 0; n < 8; n++) {
            rmax0 = fmaxf(rmax0, fmaxf(s[n][0], s[n][1]));
            rmax1 = fmaxf(rmax1, fmaxf(s[n][2], s[n][3]));
        }
        rmax0 = fmaxf(rmax0, __shfl_xor_sync(0xffffffffu, rmax0, 1));
        rmax0 = fmaxf(rmax0, __shfl_xor_sync(0xffffffffu, rmax0, 2));
        rmax1 = fmaxf(rmax1, __shfl_xor_sync(0xffffffffu, rmax1, 1));
        rmax1 = fmaxf(rmax1, __shfl_xor_sync(0xffffffffu, rmax1, 2));

        float mn0 = fmaxf(m_0, rmax0), mn1 = fmaxf(m_1, rmax1);
        float f0 = __expf(m_0 - mn0), f1 = __expf(m_1 - mn1);
        m_0 = mn0; m_1 = mn1;

        float rs0 = 0.f, rs1 = 0.f;
        #pragma unroll
        for (int n = 0; n < 8; n++) {
            s[n][0] = __expf(s[n][0] - mn0);
            s[n][1] = __expf(s[n][1] - mn0);
            s[n][2] = __expf(s[n][2] - mn1);
            s[n][3] = __expf(s[n][3] - mn1);
            rs0 += s[n][0] + s[n][1];
            rs1 += s[n][2] + s[n][3];
        }
        rs0 += __shfl_xor_sync(0xffffffffu, rs0, 1);
        rs0 += __shfl_xor_sync(0xffffffffu, rs0, 2);
        rs1 += __shfl_xor_sync(0xffffffffu, rs1, 1);
        rs1 += __shfl_xor_sync(0xffffffffu, rs1, 2);
        l_0 = l_0 * f0 + rs0;
        l_1 = l_1 * f1 + rs1;

        #pragma unroll
        for (int n = 0; n < 16; n++) {
            o[n][0] *= f0; o[n][1] *= f0;
            o[n][2] *= f1; o[n][3] *= f1;
        }

        #pragma unroll
        for (int kt = 0; kt < 4; kt++) {
            uint32_t ph[4], pl[4];
            split2(s[2 * kt][0],     s[2 * kt][1],     ph[0], pl[0]);
            split2(s[2 * kt][2],     s[2 * kt][3],     ph[1], pl[1]);
            split2(s[2 * kt + 1][0], s[2 * kt + 1][1], ph[2], pl[2]);
            split2(s[2 * kt + 1][2], s[2 * kt + 1][3], ph[3], pl[3]);
            #pragma unroll
            for (int p = 0; p < 8; p++) {
                uint32_t bh[4], bl[4];
                const uint32_t va = vB + kt * (16 * KVST * 2) + p * 32;
                ldmx4t(bh, va);
                ldmx4t(bl, va + (SV_L - SV_H) * 2);
                mma16(o[2 * p],     ph, &bh[0]);
                mma16(o[2 * p],     pl, &bh[0]);
                mma16(o[2 * p],     ph, &bl[0]);
                mma16(o[2 * p + 1], ph, &bh[2]);
                mma16(o[2 * p + 1], pl, &bh[2]);
                mma16(o[2 * p + 1], ph, &bl[2]);
            }
        }
        __syncthreads();
    }

    const float il0 = 1.0f / l_0;
    const float il1 = 1.0f / l_1;
    const int row0 = m0 + wid * 16 + g;
    #pragma unroll
    for (int n = 0; n < 16; n++) {
        const int col = n * 8 + 2 * tg;
        uint32_t uh, ul;
        split2(o[n][0] * il0, o[n][1] * il0, uh, ul);
        int d = ((size_t)row0 * Q_SIZE + h * HD + col) >> 1;
        Oh[d] = uh; Ol[d] = ul;
        split2(o[n][2] * il1, o[n][3] * il1, uh, ul);
        d = ((size_t)(row0 + 8) * Q_SIZE + h * HD + col) >> 1;
        Oh[d] = uh; Ol[d] = ul;
    }
}

// ---------------------------------------------------------------------------
extern "C" void kernel_launch(void* const* d_in, const int* in_sizes, int n_in,
                              void* d_out, int out_size)
{
    const int*   positions = (const int*)d_in[0];
    const float* hidden    = (const float*)d_in[1];
    const float* w_qkv     = (const float*)d_in[2];
    const float* w_o       = (const float*)d_in[3];
    float* out = (float*)d_out;

    float* qkv = nullptr;
    uint32_t *hid_h, *hid_l, *wqkv_h, *wqkv_l, *wo_h, *wo_l;
    uint32_t *qh, *ql, *kh, *kl, *vh, *vl, *ah, *al;
    cudaGetSymbolAddress((void**)&qkv,    g_qkv);
    cudaGetSymbolAddress((void**)&hid_h,  g_hid_h);
    cudaGetSymbolAddress((void**)&hid_l,  g_hid_l);
    cudaGetSymbolAddress((void**)&wqkv_h, g_wqkv_h);
    cudaGetSymbolAddress((void**)&wqkv_l, g_wqkv_l);
    cudaGetSymbolAddress((void**)&wo_h,   g_wo_h);
    cudaGetSymbolAddress((void**)&wo_l,   g_wo_l);
    cudaGetSymbolAddress((void**)&qh, g_qh);
    cudaGetSymbolAddress((void**)&ql, g_ql);
    cudaGetSymbolAddress((void**)&kh, g_kh);
    cudaGetSymbolAddress((void**)&kl, g_kl);
    cudaGetSymbolAddress((void**)&vh, g_vh);
    cudaGetSymbolAddress((void**)&vl, g_vl);
    cudaGetSymbolAddress((void**)&ah, g_ah);
    cudaGetSymbolAddress((void**)&al, g_al);

    const int GSM = NSTG * STG_ELEMS * 2;   // 113664
    cudaFuncSetAttribute(gemm_pre,
                         cudaFuncAttributeMaxDynamicSharedMemorySize, GSM);
    cudaFuncSetAttribute(attn_tc2_kernel,
                         cudaFuncAttributeMaxDynamicSharedMemorySize,
                         ATT_SMEM_BYTES);

    // 0) split conversions
    convert_split<<<2048, 256>>>((const float4*)hidden,
                                 (uint2*)hid_h, (uint2*)hid_l,
                                 T_SEQ * HIDDEN / 4);
    convert_split<<<4096, 256>>>((const float4*)w_qkv,
                                 (uint2*)wqkv_h, (uint2*)wqkv_l,
                                 HIDDEN * QKV_N / 4);
    convert_split<<<4096, 256>>>((const float4*)w_o,
                                 (uint2*)wo_h, (uint2*)wo_l,
                                 HIDDEN * HIDDEN / 4);

    // 1) QKV projection
    gemm_pre<<<dim3(QKV_N / 128, T_SEQ / 128), 256, GSM>>>(
        (const __nv_bfloat16*)hid_h, (const __nv_bfloat16*)hid_l,
        (const __nv_bfloat16*)wqkv_h, (const __nv_bfloat16*)wqkv_l,
        qkv, T_SEQ, QKV_N, HIDDEN);

    // 2) RoPE + split to bf16
    rope_split_kernel<<<T_SEQ, 256>>>(qkv, positions, qh, ql, kh, kl, vh, vl);

    // 3) Flash attention (tensor cores)
    attn_tc2_kernel<<<dim3(T_SEQ / FBM, NH), 256, ATT_SMEM_BYTES>>>(
        (const __nv_bfloat16*)qh, (const __nv_bfloat16*)ql,
        (const __nv_bfloat16*)kh, (const __nv_bfloat16*)kl,
        (const __nv_bfloat16*)vh, (const __nv_bfloat16*)vl,
        ah, al);

    // 4) Output projection
    gemm_pre<<<dim3(HIDDEN / 128, T_SEQ / 128), 256, GSM>>>(
        (const __nv_bfloat16*)ah, (const __nv_bfloat16*)al,
        (const __nv_bfloat16*)wo_h, (const __nv_bfloat16*)wo_l,
        out, T_SEQ, HIDDEN, HIDDEN);
}

// round 8
// speedup vs baseline: 8.9475x; 1.2854x over previous
#include <cuda_runtime.h>
#include <cuda_bf16.h>
#include <cuda_fp16.h>
#include <math.h>
#include <stdint.h>

#define T_SEQ  2048
#define HIDDEN 4096
#define NH     32
#define NKV    8
#define HD     128
#define Q_SIZE  (NH * HD)              // 4096
#define KV_SIZE (NKV * HD)             // 1024
#define QKV_N   (Q_SIZE + 2 * KV_SIZE) // 6144
#define SCALE   0.08838834764831845f   // 128^-0.5

// ---------------------------------------------------------------------------
// Global scratch (u32 = packed 16-bit pair). No cudaMalloc allowed.
// ---------------------------------------------------------------------------
__device__ float    g_qkv[(size_t)T_SEQ * QKV_N];              // fp32 QKV
__device__ uint32_t g_hid_h[(size_t)T_SEQ * HIDDEN / 2];       // fp16
__device__ uint32_t g_hid_l[(size_t)T_SEQ * HIDDEN / 2];       // fp16
__device__ uint32_t g_wqkv[(size_t)HIDDEN * QKV_N / 2];        // fp16
__device__ uint32_t g_wo[(size_t)HIDDEN * HIDDEN / 2];         // fp16
__device__ uint32_t g_qh[(size_t)T_SEQ * Q_SIZE / 2];          // bf16 (attn)
__device__ uint32_t g_ql[(size_t)T_SEQ * Q_SIZE / 2];
__device__ uint32_t g_kh[(size_t)T_SEQ * KV_SIZE / 2];
__device__ uint32_t g_kl[(size_t)T_SEQ * KV_SIZE / 2];
__device__ uint32_t g_vh[(size_t)T_SEQ * KV_SIZE / 2];
__device__ uint32_t g_vl[(size_t)T_SEQ * KV_SIZE / 2];
__device__ uint32_t g_ah[(size_t)T_SEQ * Q_SIZE / 2];          // fp16 (O-proj A)
__device__ uint32_t g_al[(size_t)T_SEQ * Q_SIZE / 2];

// ---------------------------------------------------------------------------
// Helpers
// ---------------------------------------------------------------------------
__device__ __forceinline__ uint32_t smem_u32(const void* p) {
    uint32_t a;
    asm("{ .reg .u64 t; cvta.to.shared.u64 t, %1; cvt.u32.u64 %0, t; }"
        : "=r"(a) : "l"(p));
    return a;
}
// bf16 MMA (attention)
__device__ __forceinline__ void mma16(float* c, const uint32_t* a,
                                      const uint32_t* b) {
    asm volatile(
        "mma.sync.aligned.m16n8k16.row.col.f32.bf16.bf16.f32 "
        "{%0,%1,%2,%3}, {%4,%5,%6,%7}, {%8,%9}, {%0,%1,%2,%3};"
        : "+f"(c[0]), "+f"(c[1]), "+f"(c[2]), "+f"(c[3])
        : "r"(a[0]), "r"(a[1]), "r"(a[2]), "r"(a[3]), "r"(b[0]), "r"(b[1]));
}
// fp16 MMA (GEMMs)
__device__ __forceinline__ void mma16h(float* c, const uint32_t* a,
                                       const uint32_t* b) {
    asm volatile(
        "mma.sync.aligned.m16n8k16.row.col.f32.f16.f16.f32 "
        "{%0,%1,%2,%3}, {%4,%5,%6,%7}, {%8,%9}, {%0,%1,%2,%3};"
        : "+f"(c[0]), "+f"(c[1]), "+f"(c[2]), "+f"(c[3])
        : "r"(a[0]), "r"(a[1]), "r"(a[2]), "r"(a[3]), "r"(b[0]), "r"(b[1]));
}
__device__ __forceinline__ void ldmx4(uint32_t* r, uint32_t addr) {
    asm volatile(
        "ldmatrix.sync.aligned.m8n8.x4.shared.b16 {%0,%1,%2,%3}, [%4];"
        : "=r"(r[0]), "=r"(r[1]), "=r"(r[2]), "=r"(r[3]) : "r"(addr));
}
__device__ __forceinline__ void ldmx4t(uint32_t* r, uint32_t addr) {
    asm volatile(
        "ldmatrix.sync.aligned.m8n8.x4.trans.shared.b16 {%0,%1,%2,%3}, [%4];"
        : "=r"(r[0]), "=r"(r[1]), "=r"(r[2]), "=r"(r[3]) : "r"(addr));
}
// bf16 hi/lo split
__device__ __forceinline__ void split2(float x, float y,
                                       uint32_t& hi, uint32_t& lo) {
    __nv_bfloat162 h = __floats2bfloat162_rn(x, y);
    float hx = __bfloat162float(h.x);
    float hy = __bfloat162float(h.y);
    __nv_bfloat162 l = __floats2bfloat162_rn(x - hx, y - hy);
    hi = *(uint32_t*)&h;
    lo = *(uint32_t*)&l;
}
// fp16 hi/lo split
__device__ __forceinline__ void split2h(float x, float y,
                                        uint32_t& hi, uint32_t& lo) {
    __half2 h = __floats2half2_rn(x, y);
    float hx = __half2float(__low2half(h));
    float hy = __half2float(__high2half(h));
    __half2 l = __floats2half2_rn(x - hx, y - hy);
    hi = *(uint32_t*)&h;
    lo = *(uint32_t*)&l;
}
__device__ __forceinline__ void cpa16(uint32_t dst, const void* src) {
    asm volatile("cp.async.cg.shared.global [%0], [%1], 16;"
                 :: "r"(dst), "l"(src));
}
__device__ __forceinline__ void cpa_commit() {
    asm volatile("cp.async.commit_group;");
}
template <int N>
__device__ __forceinline__ void cpa_wait() {
    asm volatile("cp.async.wait_group %0;" :: "n"(N));
}

// ---------------------------------------------------------------------------
// fp32 -> fp16 hi/lo split (activations)
// ---------------------------------------------------------------------------
__global__ __launch_bounds__(256) void convert_split_h(
    const float4* __restrict__ src, uint2* __restrict__ dh,
    uint2* __restrict__ dl, int n4)
{
    for (int i = blockIdx.x * blockDim.x + threadIdx.x; i < n4;
         i += gridDim.x * blockDim.x) {
        float4 v = src[i];
        uint32_t h0, l0, h1, l1;
        split2h(v.x, v.y, h0, l0);
        split2h(v.z, v.w, h1, l1);
        dh[i] = make_uint2(h0, h1);
        dl[i] = make_uint2(l0, l1);
    }
}

// fp32 -> fp16 single rounding (weights)
__global__ __launch_bounds__(256) void convert_h(
    const float4* __restrict__ src, uint2* __restrict__ dh, int n4)
{
    for (int i = blockIdx.x * blockDim.x + threadIdx.x; i < n4;
         i += gridDim.x * blockDim.x) {
        float4 v = src[i];
        __half2 a = __floats2half2_rn(v.x, v.y);
        __half2 b = __floats2half2_rn(v.z, v.w);
        dh[i] = make_uint2(*(uint32_t*)&a, *(uint32_t*)&b);
    }
}

// ---------------------------------------------------------------------------
// RoPE + split to bf16 hi/lo (for attention). One block per token.
// ---------------------------------------------------------------------------
__global__ __launch_bounds__(256) void rope_split_kernel(
    const float* __restrict__ qkv, const int* __restrict__ positions,
    uint32_t* __restrict__ qh, uint32_t* __restrict__ ql,
    uint32_t* __restrict__ kh, uint32_t* __restrict__ kl,
    uint32_t* __restrict__ vh, uint32_t* __restrict__ vl)
{
    __shared__ float s_if[64];
    const int t = blockIdx.x;
    if (threadIdx.x < 64) {
        double e = (double)(2 * threadIdx.x) / (double)HD;
        s_if[threadIdx.x] = (float)pow(500000.0, -e);
    }
    __syncthreads();

    const float p = (float)positions[t];
    const size_t base = (size_t)t * QKV_N;

    for (int idx = threadIdx.x; idx < QKV_N / 2; idx += blockDim.x) {
        uint32_t uh, ul;
        if (idx < (NH + NKV) * 64) {
            const int head = idx >> 6;
            const int i = idx & 63;
            float s, c;
            sincosf(p * s_if[i], &s, &c);
            if (head < NH) {
                float2 x = *(const float2*)&qkv[base + head * HD + 2 * i];
                float o1 = (x.x * c - x.y * s) * SCALE;
                float o2 = (x.y * c + x.x * s) * SCALE;
                split2(o1, o2, uh, ul);
                int d = (t * Q_SIZE + head * HD + 2 * i) >> 1;
                qh[d] = uh; ql[d] = ul;
            } else {
                const int kk = head - NH;
                float2 x = *(const float2*)&qkv[base + Q_SIZE + kk * HD + 2 * i];
                float o1 = x.x * c - x.y * s;
                float o2 = x.y * c + x.x * s;
                split2(o1, o2, uh, ul);
                int d = (t * KV_SIZE + kk * HD + 2 * i) >> 1;
                kh[d] = uh; kl[d] = ul;
            }
        } else {
            const int off = idx - (NH + NKV) * 64;
            float2 x = *(const float2*)&qkv[base + Q_SIZE + KV_SIZE + 2 * off];
            split2(x.x, x.y, uh, ul);
            int d = (t * KV_SIZE + 2 * off) >> 1;
            vh[d] = uh; vl[d] = ul;
        }
    }
}

// ---------------------------------------------------------------------------
// FP16 2-term GEMM: C[M,N] = (Ah+Al)[M,K] @ Bh[K,N].
// CTA 128x128, BK=32, 256 thr, 3-stage cp.async, one barrier/k-iter.
// Per ks: 8 ldmx4 (A hi/lo) + 2 ldmx4t (B) + 32 MMAs (was 48 with bf16x3).
// ---------------------------------------------------------------------------
#define BK  32
#define AST 40
#define BST 136
#define STG_A_L 5120            // elem offsets within a stage
#define STG_B   10240
#define STG_ELEMS 14592         // per stage (29184 B)
#define NSTG 3

__global__ __launch_bounds__(256, 2) void gemm_fp16(
    const __half* __restrict__ Ah, const __half* __restrict__ Al,
    const __half* __restrict__ Bh,
    float* __restrict__ C, int M, int N, int K)
{
    extern __shared__ __align__(16) __half sm[];
    const uint32_t smb = smem_u32(sm);

    const int tid  = threadIdx.x;
    const int wid  = tid >> 5;
    const int lane = tid & 31;
    const int g    = lane >> 2;
    const int tg   = lane & 3;
    const int wm   = (wid >> 2) * 64;
    const int wn   = (wid & 3) * 32;
    const int m0 = blockIdx.y * 128;
    const int n0 = blockIdx.x * 128;

    const int l7  = lane & 7;
    const int l8  = (lane >> 3) & 1;
    const int l16 = lane >> 4;
    const uint32_t aFrag = (uint32_t)(((wm + l7 + l8 * 8) * AST + l16 * 8) * 2);
    const uint32_t bFrag = (uint32_t)(STG_B * 2) +
        (uint32_t)(((l7 + l8 * 8) * BST + wn + l16 * 8) * 2);

    const int ar = tid >> 2, ac = tid & 3;
    const int br = tid >> 4, bc = tid & 15;

    float acc[4][4][4];
    #pragma unroll
    for (int i = 0; i < 4; i++)
        #pragma unroll
        for (int j = 0; j < 4; j++)
            #pragma unroll
            for (int q = 0; q < 4; q++) acc[i][j][q] = 0.f;

    const int KT = K / BK;

    auto issue = [&](int kt, int s) {
        const int kk = kt * BK;
        const uint32_t sb = smb + (uint32_t)(s * STG_ELEMS * 2);
        #pragma unroll
        for (int i = 0; i < 2; i++) {
            const int row = ar + i * 64;
            cpa16(sb + (row * AST + ac * 8) * 2,
                  Ah + (size_t)(m0 + row) * K + kk + ac * 8);
            cpa16(sb + (STG_A_L + row * AST + ac * 8) * 2,
                  Al + (size_t)(m0 + row) * K + kk + ac * 8);
        }
        #pragma unroll
        for (int i = 0; i < 2; i++) {
            const int row = br + i * 16;
            cpa16(sb + (STG_B + row * BST + bc * 8) * 2,
                  Bh + (size_t)(kk + row) * N + n0 + bc * 8);
        }
    };

    issue(0, 0); cpa_commit();
    issue(1, 1); cpa_commit();

    int stage = 0;
    for (int kt = 0; kt < KT; kt++) {
        cpa_wait<1>();
        __syncthreads();

        if (kt + 2 < KT) {
            int s2 = stage + 2; if (s2 >= NSTG) s2 -= NSTG;
            issue(kt + 2, s2);
        }
        cpa_commit();

        const uint32_t sb = smb + (uint32_t)(stage * STG_ELEMS * 2);
        const uint32_t aA = sb + aFrag;
        const uint32_t bA = sb + bFrag;
        #pragma unroll
        for (int ks = 0; ks < 2; ks++) {
            uint32_t ah[4][4], al[4][4];
            #pragma unroll
            for (int mt = 0; mt < 4; mt++) {
                const uint32_t a = aA + mt * (16 * AST * 2) + ks * 32;
                ldmx4(ah[mt], a);
                ldmx4(al[mt], a + STG_A_L * 2);
            }
            uint32_t bh[2][4];
            #pragma unroll
            for (int pp = 0; pp < 2; pp++) {
                const uint32_t b = bA + ks * (16 * BST * 2) + pp * 32;
                ldmx4t(bh[pp], b);
            }
            #pragma unroll
            for (int mt = 0; mt < 4; mt++)
                #pragma unroll
                for (int nt = 0; nt < 4; nt++) {
                    const uint32_t* bhf = &bh[nt >> 1][(nt & 1) * 2];
                    mma16h(acc[mt][nt], ah[mt], bhf);
                    mma16h(acc[mt][nt], al[mt], bhf);
                }
        }
        if (++stage == NSTG) stage = 0;
    }

    #pragma unroll
    for (int mt = 0; mt < 4; mt++) {
        const int row = m0 + wm + mt * 16 + g;
        #pragma unroll
        for (int nt = 0; nt < 4; nt++) {
            const int col = n0 + wn + nt * 8 + tg * 2;
            *(float2*)&C[(size_t)row * N + col] =
                make_float2(acc[mt][nt][0], acc[mt][nt][1]);
            *(float2*)&C[(size_t)(row + 8) * N + col] =
                make_float2(acc[mt][nt][2], acc[mt][nt][3]);
        }
    }
}

// ---------------------------------------------------------------------------
// Tensor-core causal GQA flash attention (bf16x3, unchanged math).
// Epilogue now emits fp16 hi/lo for the O-projection GEMM.
// ---------------------------------------------------------------------------
#define FBM 128
#define FBN 64
#define KVST 136
#define OQL_E   17408
#define KVB_E   34816
#define KV_STG  34816
#define SK_L    8704
#define SV_H    17408
#define SV_L    26112
#define ATT_SMEM_BYTES ((KVB_E + 2 * KV_STG) * 2)   // 208896

__global__ __launch_bounds__(256, 1) void attn_tc2_kernel(
    const __nv_bfloat16* __restrict__ Qh, const __nv_bfloat16* __restrict__ Ql,
    const __nv_bfloat16* __restrict__ Kh, const __nv_bfloat16* __restrict__ Kl,
    const __nv_bfloat16* __restrict__ Vh, const __nv_bfloat16* __restrict__ Vl,
    uint32_t* __restrict__ Oh, uint32_t* __restrict__ Ol)
{
    extern __shared__ __align__(16) __nv_bfloat16 asmem[];
    const uint32_t smb = smem_u32(asmem);

    const int tid  = threadIdx.x;
    const int wid  = tid >> 5;
    const int lane = tid & 31;
    const int g    = lane >> 2;
    const int tg   = lane & 3;
    const int mt   = (gridDim.x - 1) - blockIdx.x;
    const int m0   = mt * FBM;
    const int h    = blockIdx.y;
    const int kh   = h >> 2;

    const int l7  = lane & 7;
    const int l8  = (lane >> 3) & 1;
    const int l16 = lane >> 4;

    const int lr = tid >> 4;
    const int lc = tid & 15;

    #pragma unroll
    for (int i = 0; i < 8; i++) {
        const int row = lr + i * 16;
        const size_t go = (size_t)(m0 + row) * Q_SIZE + h * HD + lc * 8;
        cpa16(smb + (row * KVST + lc * 8) * 2, Qh + go);
        cpa16(smb + (OQL_E + row * KVST + lc * 8) * 2, Ql + go);
    }
    cpa_commit();

    auto issueKV = [&](int j0, int s) {
        const uint32_t sb = smb + (uint32_t)((KVB_E + s * KV_STG) * 2);
        #pragma unroll
        for (int i = 0; i < 4; i++) {
            const int row = lr + i * 16;
            const size_t go = (size_t)(j0 + row) * KV_SIZE + kh * HD + lc * 8;
            const uint32_t so = (row * KVST + lc * 8) * 2;
            cpa16(sb + so, Kh + go);
            cpa16(sb + SK_L * 2 + so, Kl + go);
            cpa16(sb + SV_H * 2 + so, Vh + go);
            cpa16(sb + SV_L * 2 + so, Vl + go);
        }
    };

    issueKV(0, 0);
    cpa_commit();

    float o[16][4];
    #pragma unroll
    for (int n = 0; n < 16; n++)
        #pragma unroll
        for (int q = 0; q < 4; q++) o[n][q] = 0.f;
    float m_0 = -1e30f, m_1 = -1e30f, l_0 = 0.f, l_1 = 0.f;

    const uint32_t qFrag =
        (uint32_t)(((wid * 16 + l7 + l8 * 8) * KVST + l16 * 8) * 2);
    const uint32_t kFrag =
        (uint32_t)(((l7 + l16 * 8) * KVST + l8 * 8) * 2);
    const uint32_t vFrag =
        (uint32_t)(((l7 + l8 * 8) * KVST + l16 * 8) * 2);

    const int ntiles = m0 / FBN + 2;

    for (int jt = 0; jt < ntiles; jt++) {
        if (jt + 1 < ntiles) issueKV((jt + 1) * FBN, (jt + 1) & 1);
        cpa_commit();
        cpa_wait<1>();
        __syncthreads();

        const int j0 = jt * FBN;
        const uint32_t sb = smb + (uint32_t)((KVB_E + (jt & 1) * KV_STG) * 2);
        const uint32_t kB = sb + kFrag;
        const uint32_t vB = sb + SV_H * 2 + vFrag;

        float s[8][4];
        #pragma unroll
        for (int n = 0; n < 8; n++)
            #pragma unroll
            for (int q = 0; q < 4; q++) s[n][q] = 0.f;

        #pragma unroll
        for (int kt = 0; kt < 8; kt++) {
            uint32_t ah[4], al[4];
            ldmx4(ah, smb + qFrag + kt * 32);
            ldmx4(al, smb + OQL_E * 2 + qFrag + kt * 32);
            #pragma unroll
            for (int p = 0; p < 4; p++) {
                uint32_t bh[4], bl[4];
                const uint32_t ka = kB + p * (16 * KVST * 2) + kt * 32;
                ldmx4(bh, ka);
                ldmx4(bl, ka + SK_L * 2);
                mma16(s[2 * p],     ah, &bh[0]);
                mma16(s[2 * p],     al, &bh[0]);
                mma16(s[2 * p],     ah, &bl[0]);
                mma16(s[2 * p + 1], ah, &bh[2]);
                mma16(s[2 * p + 1], al, &bh[2]);
                mma16(s[2 * p + 1], ah, &bl[2]);
            }
        }

        const int row0 = m0 + wid * 16 + g;
        const int row1 = row0 + 8;
        if (j0 + FBN - 1 > row0) {
            #pragma unroll
            for (int n = 0; n < 8; n++) {
                int col = j0 + n * 8 + 2 * tg;
                if (col     > row0) s[n][0] = -1e30f;
                if (col + 1 > row0) s[n][1] = -1e30f;
                if (col     > row1) s[n][2] = -1e30f;
                if (col + 1 > row1) s[n][3] = -1e30f;
            }
        }

        float rmax0 = -1e30f, rmax1 = -1e30f;
        #pragma unroll
        for (int n = 0; n < 8; n++) {
            rmax0 = fmaxf(rmax0, fmaxf(s[n][0], s[n][1]));
            rmax1 = fmaxf(rmax1, fmaxf(s[n][2], s[n][3]));
        }
        rmax0 = fmaxf(rmax0, __shfl_xor_sync(0xffffffffu, rmax0, 1));
        rmax0 = fmaxf(rmax0, __shfl_xor_sync(0xffffffffu, rmax0, 2));
        rmax1 = fmaxf(rmax1, __shfl_xor_sync(0xffffffffu, rmax1, 1));
        rmax1 = fmaxf(rmax1, __shfl_xor_sync(0xffffffffu, rmax1, 2));

        float mn0 = fmaxf(m_0, rmax0), mn1 = fmaxf(m_1, rmax1);
        float f0 = __expf(m_0 - mn0), f1 = __expf(m_1 - mn1);
        m_0 = mn0; m_1 = mn1;

        float rs0 = 0.f, rs1 = 0.f;
        #pragma unroll
        for (int n = 0; n < 8; n++) {
            s[n][0] = __expf(s[n][0] - mn0);
            s[n][1] = __expf(s[n][1] - mn0);
            s[n][2] = __expf(s[n][2] - mn1);
            s[n][3] = __expf(s[n][3] - mn1);
            rs0 += s[n][0] + s[n][1];
            rs1 += s[n][2] + s[n][3];
        }
        rs0 += __shfl_xor_sync(0xffffffffu, rs0, 1);
        rs0 += __shfl_xor_sync(0xffffffffu, rs0, 2);
        rs1 += __shfl_xor_sync(0xffffffffu, rs1, 1);
        rs1 += __shfl_xor_sync(0xffffffffu, rs1, 2);
        l_0 = l_0 * f0 + rs0;
        l_1 = l_1 * f1 + rs1;

        #pragma unroll
        for (int n = 0; n < 16; n++) {
            o[n][0] *= f0; o[n][1] *= f0;
            o[n][2] *= f1; o[n][3] *= f1;
        }

        #pragma unroll
        for (int kt = 0; kt < 4; kt++) {
            uint32_t ph[4], pl[4];
            split2(s[2 * kt][0],     s[2 * kt][1],     ph[0], pl[0]);
            split2(s[2 * kt][2],     s[2 * kt][3],     ph[1], pl[1]);
            split2(s[2 * kt + 1][0], s[2 * kt + 1][1], ph[2], pl[2]);
            split2(s[2 * kt + 1][2], s[2 * kt + 1][3], ph[3], pl[3]);
            #pragma unroll
            for (int p = 0; p < 8; p++) {
                uint32_t bh[4], bl[4];
                const uint32_t va = vB + kt * (16 * KVST * 2) + p * 32;
                ldmx4t(bh, va);
                ldmx4t(bl, va + (SV_L - SV_H) * 2);
                mma16(o[2 * p],     ph, &bh[0]);
                mma16(o[2 * p],     pl, &bh[0]);
                mma16(o[2 * p],     ph, &bl[0]);
                mma16(o[2 * p + 1], ph, &bh[2]);
                mma16(o[2 * p + 1], pl, &bh[2]);
                mma16(o[2 * p + 1], ph, &bl[2]);
            }
        }
        __syncthreads();
    }

    // epilogue: fp16 hi/lo for the O-projection
    const float il0 = 1.0f / l_0;
    const float il1 = 1.0f / l_1;
    const int row0 = m0 + wid * 16 + g;
    #pragma unroll
    for (int n = 0; n < 16; n++) {
        const int col = n * 8 + 2 * tg;
        uint32_t uh, ul;
        split2h(o[n][0] * il0, o[n][1] * il0, uh, ul);
        int d = ((size_t)row0 * Q_SIZE + h * HD + col) >> 1;
        Oh[d] = uh; Ol[d] = ul;
        split2h(o[n][2] * il1, o[n][3] * il1, uh, ul);
        d = ((size_t)(row0 + 8) * Q_SIZE + h * HD + col) >> 1;
        Oh[d] = uh; Ol[d] = ul;
    }
}

// ---------------------------------------------------------------------------
extern "C" void kernel_launch(void* const* d_in, const int* in_sizes, int n_in,
                              void* d_out, int out_size)
{
    const int*   positions = (const int*)d_in[0];
    const float* hidden    = (const float*)d_in[1];
    const float* w_qkv     = (const float*)d_in[2];
    const float* w_o       = (const float*)d_in[3];
    float* out = (float*)d_out;

    float* qkv = nullptr;
    uint32_t *hid_h, *hid_l, *wqkv, *wo;
    uint32_t *qh, *ql, *kh, *kl, *vh, *vl, *ah, *al;
    cudaGetSymbolAddress((void**)&qkv,   g_qkv);
    cudaGetSymbolAddress((void**)&hid_h, g_hid_h);
    cudaGetSymbolAddress((void**)&hid_l, g_hid_l);
    cudaGetSymbolAddress((void**)&wqkv,  g_wqkv);
    cudaGetSymbolAddress((void**)&wo,    g_wo);
    cudaGetSymbolAddress((void**)&qh, g_qh);
    cudaGetSymbolAddress((void**)&ql, g_ql);
    cudaGetSymbolAddress((void**)&kh, g_kh);
    cudaGetSymbolAddress((void**)&kl, g_kl);
    cudaGetSymbolAddress((void**)&vh, g_vh);
    cudaGetSymbolAddress((void**)&vl, g_vl);
    cudaGetSymbolAddress((void**)&ah, g_ah);
    cudaGetSymbolAddress((void**)&al, g_al);

    const int GSM = NSTG * STG_ELEMS * 2;   // 87552
    cudaFuncSetAttribute(gemm_fp16,
                         cudaFuncAttributeMaxDynamicSharedMemorySize, GSM);
    cudaFuncSetAttribute(attn_tc2_kernel,
                         cudaFuncAttributeMaxDynamicSharedMemorySize,
                         ATT_SMEM_BYTES);

    // 0) conversions
    convert_split_h<<<2048, 256>>>((const float4*)hidden,
                                   (uint2*)hid_h, (uint2*)hid_l,
                                   T_SEQ * HIDDEN / 4);
    convert_h<<<4096, 256>>>((const float4*)w_qkv, (uint2*)wqkv,
                             HIDDEN * QKV_N / 4);
    convert_h<<<4096, 256>>>((const float4*)w_o, (uint2*)wo,
                             HIDDEN * HIDDEN / 4);

    // 1) QKV projection (fp16 2-term)
    gemm_fp16<<<dim3(QKV_N / 128, T_SEQ / 128), 256, GSM>>>(
        (const __half*)hid_h, (const __half*)hid_l, (const __half*)wqkv,
        qkv, T_SEQ, QKV_N, HIDDEN);

    // 2) RoPE + split to bf16
    rope_split_kernel<<<T_SEQ, 256>>>(qkv, positions, qh, ql, kh, kl, vh, vl);

    // 3) Flash attention (bf16x3 tensor cores)
    attn_tc2_kernel<<<dim3(T_SEQ / FBM, NH), 256, ATT_SMEM_BYTES>>>(
        (const __nv_bfloat16*)qh, (const __nv_bfloat16*)ql,
        (const __nv_bfloat16*)kh, (const __nv_bfloat16*)kl,
        (const __nv_bfloat16*)vh, (const __nv_bfloat16*)vl,
        ah, al);

    // 4) Output projection (fp16 2-term)
    gemm_fp16<<<dim3(HIDDEN / 128, T_SEQ / 128), 256, GSM>>>(
        (const __half*)ah, (const __half*)al, (const __half*)wo,
        out, T_SEQ, HIDDEN, HIDDEN);
}

// round 9
// speedup vs baseline: 13.5375x; 1.5130x over previous
#include <cuda_runtime.h>
#include <cuda_bf16.h>
#include <cuda_fp16.h>
#include <math.h>
#include <stdint.h>

#define T_SEQ  2048
#define HIDDEN 4096
#define NH     32
#define NKV    8
#define HD     128
#define Q_SIZE  (NH * HD)              // 4096
#define KV_SIZE (NKV * HD)             // 1024
#define QKV_N   (Q_SIZE + 2 * KV_SIZE) // 6144
#define SCALE   0.08838834764831845f   // 128^-0.5

// ---------------------------------------------------------------------------
// Global scratch. No cudaMalloc allowed.
// ---------------------------------------------------------------------------
__device__ float    g_qkv[(size_t)T_SEQ * QKV_N];              // fp32 QKV
__device__ uint32_t g_hid[(size_t)T_SEQ * HIDDEN / 2];         // fp16
__device__ uint32_t g_wqkv[(size_t)HIDDEN * QKV_N / 2];        // fp16
__device__ uint32_t g_wo[(size_t)HIDDEN * HIDDEN / 2];         // fp16
__device__ uint32_t g_qh[(size_t)T_SEQ * Q_SIZE / 2];          // bf16 (attn)
__device__ uint32_t g_ql[(size_t)T_SEQ * Q_SIZE / 2];
__device__ uint32_t g_kh[(size_t)T_SEQ * KV_SIZE / 2];
__device__ uint32_t g_kl[(size_t)T_SEQ * KV_SIZE / 2];
__device__ uint32_t g_vh[(size_t)T_SEQ * KV_SIZE / 2];
__device__ uint32_t g_vl[(size_t)T_SEQ * KV_SIZE / 2];
__device__ uint32_t g_ao[(size_t)T_SEQ * Q_SIZE / 2];          // fp16 attn out

// ---------------------------------------------------------------------------
// Helpers
// ---------------------------------------------------------------------------
__device__ __forceinline__ uint32_t smem_u32(const void* p) {
    uint32_t a;
    asm("{ .reg .u64 t; cvta.to.shared.u64 t, %1; cvt.u32.u64 %0, t; }"
        : "=r"(a) : "l"(p));
    return a;
}
// bf16 MMA (attention)
__device__ __forceinline__ void mma16(float* c, const uint32_t* a,
                                      const uint32_t* b) {
    asm volatile(
        "mma.sync.aligned.m16n8k16.row.col.f32.bf16.bf16.f32 "
        "{%0,%1,%2,%3}, {%4,%5,%6,%7}, {%8,%9}, {%0,%1,%2,%3};"
        : "+f"(c[0]), "+f"(c[1]), "+f"(c[2]), "+f"(c[3])
        : "r"(a[0]), "r"(a[1]), "r"(a[2]), "r"(a[3]), "r"(b[0]), "r"(b[1]));
}
// fp16 MMA (GEMMs)
__device__ __forceinline__ void mma16h(float* c, const uint32_t* a,
                                       const uint32_t* b) {
    asm volatile(
        "mma.sync.aligned.m16n8k16.row.col.f32.f16.f16.f32 "
        "{%0,%1,%2,%3}, {%4,%5,%6,%7}, {%8,%9}, {%0,%1,%2,%3};"
        : "+f"(c[0]), "+f"(c[1]), "+f"(c[2]), "+f"(c[3])
        : "r"(a[0]), "r"(a[1]), "r"(a[2]), "r"(a[3]), "r"(b[0]), "r"(b[1]));
}
__device__ __forceinline__ void ldmx4(uint32_t* r, uint32_t addr) {
    asm volatile(
        "ldmatrix.sync.aligned.m8n8.x4.shared.b16 {%0,%1,%2,%3}, [%4];"
        : "=r"(r[0]), "=r"(r[1]), "=r"(r[2]), "=r"(r[3]) : "r"(addr));
}
__device__ __forceinline__ void ldmx4t(uint32_t* r, uint32_t addr) {
    asm volatile(
        "ldmatrix.sync.aligned.m8n8.x4.trans.shared.b16 {%0,%1,%2,%3}, [%4];"
        : "=r"(r[0]), "=r"(r[1]), "=r"(r[2]), "=r"(r[3]) : "r"(addr));
}
// bf16 hi/lo split (attention inputs / P fragments)
__device__ __forceinline__ void split2(float x, float y,
                                       uint32_t& hi, uint32_t& lo) {
    __nv_bfloat162 h = __floats2bfloat162_rn(x, y);
    float hx = __bfloat162float(h.x);
    float hy = __bfloat162float(h.y);
    __nv_bfloat162 l = __floats2bfloat162_rn(x - hx, y - hy);
    hi = *(uint32_t*)&h;
    lo = *(uint32_t*)&l;
}
__device__ __forceinline__ void cpa16(uint32_t dst, const void* src) {
    asm volatile("cp.async.cg.shared.global [%0], [%1], 16;"
                 :: "r"(dst), "l"(src));
}
__device__ __forceinline__ void cpa_commit() {
    asm volatile("cp.async.commit_group;");
}
template <int N>
__device__ __forceinline__ void cpa_wait() {
    asm volatile("cp.async.wait_group %0;" :: "n"(N));
}

// ---------------------------------------------------------------------------
// fp32 -> fp16 (single rounding)
// ---------------------------------------------------------------------------
__global__ __launch_bounds__(256) void convert_h(
    const float4* __restrict__ src, uint2* __restrict__ dh, int n4)
{
    for (int i = blockIdx.x * blockDim.x + threadIdx.x; i < n4;
         i += gridDim.x * blockDim.x) {
        float4 v = src[i];
        __half2 a = __floats2half2_rn(v.x, v.y);
        __half2 b = __floats2half2_rn(v.z, v.w);
        dh[i] = make_uint2(*(uint32_t*)&a, *(uint32_t*)&b);
    }
}

// ---------------------------------------------------------------------------
// RoPE + split to bf16 hi/lo (for attention). One block per token.
// ---------------------------------------------------------------------------
__global__ __launch_bounds__(256) void rope_split_kernel(
    const float* __restrict__ qkv, const int* __restrict__ positions,
    uint32_t* __restrict__ qh, uint32_t* __restrict__ ql,
    uint32_t* __restrict__ kh, uint32_t* __restrict__ kl,
    uint32_t* __restrict__ vh, uint32_t* __restrict__ vl)
{
    __shared__ float s_if[64];
    const int t = blockIdx.x;
    if (threadIdx.x < 64) {
        double e = (double)(2 * threadIdx.x) / (double)HD;
        s_if[threadIdx.x] = (float)pow(500000.0, -e);
    }
    __syncthreads();

    const float p = (float)positions[t];
    const size_t base = (size_t)t * QKV_N;

    for (int idx = threadIdx.x; idx < QKV_N / 2; idx += blockDim.x) {
        uint32_t uh, ul;
        if (idx < (NH + NKV) * 64) {
            const int head = idx >> 6;
            const int i = idx & 63;
            float s, c;
            sincosf(p * s_if[i], &s, &c);
            if (head < NH) {
                float2 x = *(const float2*)&qkv[base + head * HD + 2 * i];
                float o1 = (x.x * c - x.y * s) * SCALE;
                float o2 = (x.y * c + x.x * s) * SCALE;
                split2(o1, o2, uh, ul);
                int d = (t * Q_SIZE + head * HD + 2 * i) >> 1;
                qh[d] = uh; ql[d] = ul;
            } else {
                const int kk = head - NH;
                float2 x = *(const float2*)&qkv[base + Q_SIZE + kk * HD + 2 * i];
                float o1 = x.x * c - x.y * s;
                float o2 = x.y * c + x.x * s;
                split2(o1, o2, uh, ul);
                int d = (t * KV_SIZE + kk * HD + 2 * i) >> 1;
                kh[d] = uh; kl[d] = ul;
            }
        } else {
            const int off = idx - (NH + NKV) * 64;
            float2 x = *(const float2*)&qkv[base + Q_SIZE + KV_SIZE + 2 * off];
            split2(x.x, x.y, uh, ul);
            int d = (t * KV_SIZE + 2 * off) >> 1;
            vh[d] = uh; vl[d] = ul;
        }
    }
}

// ---------------------------------------------------------------------------
// Pure FP16 GEMM: C[M,N] = A[M,K] @ B[K,N].
// CTA 128x128, BK=64, 256 thr, 3-stage cp.async, one barrier per kt,
// A fragments register-double-buffered across the 4 k16 steps.
// ---------------------------------------------------------------------------
#define GBK 64
#define AST 72                  // A row stride (elems): 64 + 8 pad
#define BST 136                 // B k-row stride (elems): 128 + 8 pad
#define STG_B   (128 * AST)     // 9216 elems
#define STG_ELEMS (128 * AST + GBK * BST)   // 17920 elems = 35840 B
#define NSTG 3

__global__ __launch_bounds__(256, 2) void gemm_fp16(
    const __half* __restrict__ A, const __half* __restrict__ B,
    float* __restrict__ C, int M, int N, int K)
{
    extern __shared__ __align__(16) __half sm[];
    const uint32_t smb = smem_u32(sm);

    const int tid  = threadIdx.x;
    const int wid  = tid >> 5;
    const int lane = tid & 31;
    const int g    = lane >> 2;
    const int tg   = lane & 3;
    const int wm   = (wid >> 2) * 64;
    const int wn   = (wid & 3) * 32;
    const int m0 = blockIdx.y * 128;
    const int n0 = blockIdx.x * 128;

    const int l7  = lane & 7;
    const int l8  = (lane >> 3) & 1;
    const int l16 = lane >> 4;
    const uint32_t aFrag = (uint32_t)(((wm + l7 + l8 * 8) * AST + l16 * 8) * 2);
    const uint32_t bFrag = (uint32_t)(STG_B * 2) +
        (uint32_t)(((l7 + l8 * 8) * BST + wn + l16 * 8) * 2);

    // loaders: A row=tid>>3 (+32*i), col chunk=(tid&7)*8; B row=tid>>4 (+16*i)
    const int a_row = tid >> 3, a_c8 = (tid & 7) * 8;
    const int b_row = tid >> 4, b_c8 = (tid & 15) * 8;

    float acc[4][4][4];
    #pragma unroll
    for (int i = 0; i < 4; i++)
        #pragma unroll
        for (int j = 0; j < 4; j++)
            #pragma unroll
            for (int q = 0; q < 4; q++) acc[i][j][q] = 0.f;

    const int KT = K / GBK;

    auto issue = [&](int kt, int s) {
        const int kk = kt * GBK;
        const uint32_t sb = smb + (uint32_t)(s * STG_ELEMS * 2);
        #pragma unroll
        for (int i = 0; i < 4; i++) {
            const int row = a_row + i * 32;
            cpa16(sb + (row * AST + a_c8) * 2,
                  A + (size_t)(m0 + row) * K + kk + a_c8);
        }
        #pragma unroll
        for (int i = 0; i < 4; i++) {
            const int row = b_row + i * 16;
            cpa16(sb + (STG_B + row * BST + b_c8) * 2,
                  B + (size_t)(kk + row) * N + n0 + b_c8);
        }
    };

    issue(0, 0); cpa_commit();
    issue(1, 1); cpa_commit();

    int stage = 0;
    for (int kt = 0; kt < KT; kt++) {
        cpa_wait<1>();
        __syncthreads();

        if (kt + 2 < KT) {
            int s2 = stage + 2; if (s2 >= NSTG) s2 -= NSTG;
            issue(kt + 2, s2);
        }
        cpa_commit();

        const uint32_t sb = smb + (uint32_t)(stage * STG_ELEMS * 2);
        const uint32_t aA = sb + aFrag;
        const uint32_t bA = sb + bFrag;

        // preload A fragments for ks=0
        uint32_t aF[2][4][4];
        #pragma unroll
        for (int mt = 0; mt < 4; mt++)
            ldmx4(aF[0][mt], aA + mt * (16 * AST * 2));

        #pragma unroll
        for (int ks = 0; ks < 4; ks++) {
            const int cur = ks & 1;
            // B fragments for this ks (needed soon)
            uint32_t bh[2][4];
            #pragma unroll
            for (int pp = 0; pp < 2; pp++)
                ldmx4t(bh[pp], bA + ks * (16 * BST * 2) + pp * 32);
            // A fragments for next ks (hides ldsm latency under MMAs)
            if (ks < 3) {
                #pragma unroll
                for (int mt = 0; mt < 4; mt++)
                    ldmx4(aF[cur ^ 1][mt],
                          aA + mt * (16 * AST * 2) + (ks + 1) * 32);
            }
            #pragma unroll
            for (int mt = 0; mt < 4; mt++)
                #pragma unroll
                for (int nt = 0; nt < 4; nt++)
                    mma16h(acc[mt][nt], aF[cur][mt],
                           &bh[nt >> 1][(nt & 1) * 2]);
        }
        if (++stage == NSTG) stage = 0;
    }

    #pragma unroll
    for (int mt = 0; mt < 4; mt++) {
        const int row = m0 + wm + mt * 16 + g;
        #pragma unroll
        for (int nt = 0; nt < 4; nt++) {
            const int col = n0 + wn + nt * 8 + tg * 2;
            *(float2*)&C[(size_t)row * N + col] =
                make_float2(acc[mt][nt][0], acc[mt][nt][1]);
            *(float2*)&C[(size_t)(row + 8) * N + col] =
                make_float2(acc[mt][nt][2], acc[mt][nt][3]);
        }
    }
}

// ---------------------------------------------------------------------------
// Tensor-core causal GQA flash attention (bf16x3, unchanged math).
// Epilogue emits single fp16 for the O-projection.
// ---------------------------------------------------------------------------
#define FBM 128
#define FBN 64
#define KVST 136
#define OQL_E   17408
#define KVB_E   34816
#define KV_STG  34816
#define SK_L    8704
#define SV_H    17408
#define SV_L    26112
#define ATT_SMEM_BYTES ((KVB_E + 2 * KV_STG) * 2)   // 208896

__global__ __launch_bounds__(256, 1) void attn_tc2_kernel(
    const __nv_bfloat16* __restrict__ Qh, const __nv_bfloat16* __restrict__ Ql,
    const __nv_bfloat16* __restrict__ Kh, const __nv_bfloat16* __restrict__ Kl,
    const __nv_bfloat16* __restrict__ Vh, const __nv_bfloat16* __restrict__ Vl,
    uint32_t* __restrict__ Oo)
{
    extern __shared__ __align__(16) __nv_bfloat16 asmem[];
    const uint32_t smb = smem_u32(asmem);

    const int tid  = threadIdx.x;
    const int wid  = tid >> 5;
    const int lane = tid & 31;
    const int g    = lane >> 2;
    const int tg   = lane & 3;
    const int mt   = (gridDim.x - 1) - blockIdx.x;
    const int m0   = mt * FBM;
    const int h    = blockIdx.y;
    const int kh   = h >> 2;

    const int l7  = lane & 7;
    const int l8  = (lane >> 3) & 1;
    const int l16 = lane >> 4;

    const int lr = tid >> 4;
    const int lc = tid & 15;

    #pragma unroll
    for (int i = 0; i < 8; i++) {
        const int row = lr + i * 16;
        const size_t go = (size_t)(m0 + row) * Q_SIZE + h * HD + lc * 8;
        cpa16(smb + (row * KVST + lc * 8) * 2, Qh + go);
        cpa16(smb + (OQL_E + row * KVST + lc * 8) * 2, Ql + go);
    }
    cpa_commit();

    auto issueKV = [&](int j0, int s) {
        const uint32_t sb = smb + (uint32_t)((KVB_E + s * KV_STG) * 2);
        #pragma unroll
        for (int i = 0; i < 4; i++) {
            const int row = lr + i * 16;
            const size_t go = (size_t)(j0 + row) * KV_SIZE + kh * HD + lc * 8;
            const uint32_t so = (row * KVST + lc * 8) * 2;
            cpa16(sb + so, Kh + go);
            cpa16(sb + SK_L * 2 + so, Kl + go);
            cpa16(sb + SV_H * 2 + so, Vh + go);
            cpa16(sb + SV_L * 2 + so, Vl + go);
        }
    };

    issueKV(0, 0);
    cpa_commit();

    float o[16][4];
    #pragma unroll
    for (int n = 0; n < 16; n++)
        #pragma unroll
        for (int q = 0; q < 4; q++) o[n][q] = 0.f;
    float m_0 = -1e30f, m_1 = -1e30f, l_0 = 0.f, l_1 = 0.f;

    const uint32_t qFrag =
        (uint32_t)(((wid * 16 + l7 + l8 * 8) * KVST + l16 * 8) * 2);
    const uint32_t kFrag =
        (uint32_t)(((l7 + l16 * 8) * KVST + l8 * 8) * 2);
    const uint32_t vFrag =
        (uint32_t)(((l7 + l8 * 8) * KVST + l16 * 8) * 2);

    const int ntiles = m0 / FBN + 2;

    for (int jt = 0; jt < ntiles; jt++) {
        if (jt + 1 < ntiles) issueKV((jt + 1) * FBN, (jt + 1) & 1);
        cpa_commit();
        cpa_wait<1>();
        __syncthreads();

        const int j0 = jt * FBN;
        const uint32_t sb = smb + (uint32_t)((KVB_E + (jt & 1) * KV_STG) * 2);
        const uint32_t kB = sb + kFrag;
        const uint32_t vB = sb + SV_H * 2 + vFrag;

        float s[8][4];
        #pragma unroll
        for (int n = 0; n < 8; n++)
            #pragma unroll
            for (int q = 0; q < 4; q++) s[n][q] = 0.f;

        #pragma unroll
        for (int kt = 0; kt < 8; kt++) {
            uint32_t ah[4], al[4];
            ldmx4(ah, smb + qFrag + kt * 32);
            ldmx4(al, smb + OQL_E * 2 + qFrag + kt * 32);
            #pragma unroll
            for (int p = 0; p < 4; p++) {
                uint32_t bh[4], bl[4];
                const uint32_t ka = kB + p * (16 * KVST * 2) + kt * 32;
                ldmx4(bh, ka);
                ldmx4(bl, ka + SK_L * 2);
                mma16(s[2 * p],     ah, &bh[0]);
                mma16(s[2 * p],     al, &bh[0]);
                mma16(s[2 * p],     ah, &bl[0]);
                mma16(s[2 * p + 1], ah, &bh[2]);
                mma16(s[2 * p + 1], al, &bh[2]);
                mma16(s[2 * p + 1], ah, &bl[2]);
            }
        }

        const int row0 = m0 + wid * 16 + g;
        const int row1 = row0 + 8;
        if (j0 + FBN - 1 > row0) {
            #pragma unroll
            for (int n = 0; n < 8; n++) {
                int col = j0 + n * 8 + 2 * tg;
                if (col     > row0) s[n][0] = -1e30f;
                if (col + 1 > row0) s[n][1] = -1e30f;
                if (col     > row1) s[n][2] = -1e30f;
                if (col + 1 > row1) s[n][3] = -1e30f;
            }
        }

        float rmax0 = -1e30f, rmax1 = -1e30f;
        #pragma unroll
        for (int n = 0; n < 8; n++) {
            rmax0 = fmaxf(rmax0, fmaxf(s[n][0], s[n][1]));
            rmax1 = fmaxf(rmax1, fmaxf(s[n][2], s[n][3]));
        }
        rmax0 = fmaxf(rmax0, __shfl_xor_sync(0xffffffffu, rmax0, 1));
        rmax0 = fmaxf(rmax0, __shfl_xor_sync(0xffffffffu, rmax0, 2));
        rmax1 = fmaxf(rmax1, __shfl_xor_sync(0xffffffffu, rmax1, 1));
        rmax1 = fmaxf(rmax1, __shfl_xor_sync(0xffffffffu, rmax1, 2));

        float mn0 = fmaxf(m_0, rmax0), mn1 = fmaxf(m_1, rmax1);
        float f0 = __expf(m_0 - mn0), f1 = __expf(m_1 - mn1);
        m_0 = mn0; m_1 = mn1;

        float rs0 = 0.f, rs1 = 0.f;
        #pragma unroll
        for (int n = 0; n < 8; n++) {
            s[n][0] = __expf(s[n][0] - mn0);
            s[n][1] = __expf(s[n][1] - mn0);
            s[n][2] = __expf(s[n][2] - mn1);
            s[n][3] = __expf(s[n][3] - mn1);
            rs0 += s[n][0] + s[n][1];
            rs1 += s[n][2] + s[n][3];
        }
        rs0 += __shfl_xor_sync(0xffffffffu, rs0, 1);
        rs0 += __shfl_xor_sync(0xffffffffu, rs0, 2);
        rs1 += __shfl_xor_sync(0xffffffffu, rs1, 1);
        rs1 += __shfl_xor_sync(0xffffffffu, rs1, 2);
        l_0 = l_0 * f0 + rs0;
        l_1 = l_1 * f1 + rs1;

        #pragma unroll
        for (int n = 0; n < 16; n++) {
            o[n][0] *= f0; o[n][1] *= f0;
            o[n][2] *= f1; o[n][3] *= f1;
        }

        #pragma unroll
        for (int kt = 0; kt < 4; kt++) {
            uint32_t ph[4], pl[4];
            split2(s[2 * kt][0],     s[2 * kt][1],     ph[0], pl[0]);
            split2(s[2 * kt][2],     s[2 * kt][3],     ph[1], pl[1]);
            split2(s[2 * kt + 1][0], s[2 * kt + 1][1], ph[2], pl[2]);
            split2(s[2 * kt + 1][2], s[2 * kt + 1][3], ph[3], pl[3]);
            #pragma unroll
            for (int p = 0; p < 8; p++) {
                uint32_t bh[4], bl[4];
                const uint32_t va = vB + kt * (16 * KVST * 2) + p * 32;
                ldmx4t(bh, va);
                ldmx4t(bl, va + (SV_L - SV_H) * 2);
                mma16(o[2 * p],     ph, &bh[0]);
                mma16(o[2 * p],     pl, &bh[0]);
                mma16(o[2 * p],     ph, &bl[0]);
                mma16(o[2 * p + 1], ph, &bh[2]);
                mma16(o[2 * p + 1], pl, &bh[2]);
                mma16(o[2 * p + 1], ph, &bl[2]);
            }
        }
        __syncthreads();
    }

    // epilogue: single fp16 output for the O-projection
    const float il0 = 1.0f / l_0;
    const float il1 = 1.0f / l_1;
    const int row0 = m0 + wid * 16 + g;
    #pragma unroll
    for (int n = 0; n < 16; n++) {
        const int col = n * 8 + 2 * tg;
        __half2 h0 = __floats2half2_rn(o[n][0] * il0, o[n][1] * il0);
        Oo[((size_t)row0 * Q_SIZE + h * HD + col) >> 1] = *(uint32_t*)&h0;
        __half2 h1 = __floats2half2_rn(o[n][2] * il1, o[n][3] * il1);
        Oo[((size_t)(row0 + 8) * Q_SIZE + h * HD + col) >> 1] = *(uint32_t*)&h1;
    }
}

// ---------------------------------------------------------------------------
extern "C" void kernel_launch(void* const* d_in, const int* in_sizes, int n_in,
                              void* d_out, int out_size)
{
    const int*   positions = (const int*)d_in[0];
    const float* hidden    = (const float*)d_in[1];
    const float* w_qkv     = (const float*)d_in[2];
    const float* w_o       = (const float*)d_in[3];
    float* out = (float*)d_out;

    float* qkv = nullptr;
    uint32_t *hid, *wqkv, *wo;
    uint32_t *qh, *ql, *kh, *kl, *vh, *vl, *ao;
    cudaGetSymbolAddress((void**)&qkv,  g_qkv);
    cudaGetSymbolAddress((void**)&hid,  g_hid);
    cudaGetSymbolAddress((void**)&wqkv, g_wqkv);
    cudaGetSymbolAddress((void**)&wo,   g_wo);
    cudaGetSymbolAddress((void**)&qh, g_qh);
    cudaGetSymbolAddress((void**)&ql, g_ql);
    cudaGetSymbolAddress((void**)&kh, g_kh);
    cudaGetSymbolAddress((void**)&kl, g_kl);
    cudaGetSymbolAddress((void**)&vh, g_vh);
    cudaGetSymbolAddress((void**)&vl, g_vl);
    cudaGetSymbolAddress((void**)&ao, g_ao);

    const int GSM = NSTG * STG_ELEMS * 2;   // 107520
    cudaFuncSetAttribute(gemm_fp16,
                         cudaFuncAttributeMaxDynamicSharedMemorySize, GSM);
    cudaFuncSetAttribute(attn_tc2_kernel,
                         cudaFuncAttributeMaxDynamicSharedMemorySize,
                         ATT_SMEM_BYTES);

    // 0) conversions to fp16
    convert_h<<<2048, 256>>>((const float4*)hidden, (uint2*)hid,
                             T_SEQ * HIDDEN / 4);
    convert_h<<<4096, 256>>>((const float4*)w_qkv, (uint2*)wqkv,
                             HIDDEN * QKV_N / 4);
    convert_h<<<4096, 256>>>((const float4*)w_o, (uint2*)wo,
                             HIDDEN * HIDDEN / 4);

    // 1) QKV projection (fp16)
    gemm_fp16<<<dim3(QKV_N / 128, T_SEQ / 128), 256, GSM>>>(
        (const __half*)hid, (const __half*)wqkv, qkv, T_SEQ, QKV_N, HIDDEN);

    // 2) RoPE + split to bf16
    rope_split_kernel<<<T_SEQ, 256>>>(qkv, positions, qh, ql, kh, kl, vh, vl);

    // 3) Flash attention (bf16x3 tensor cores)
    attn_tc2_kernel<<<dim3(T_SEQ / FBM, NH), 256, ATT_SMEM_BYTES>>>(
        (const __nv_bfloat16*)qh, (const __nv_bfloat16*)ql,
        (const __nv_bfloat16*)kh, (const __nv_bfloat16*)kl,
        (const __nv_bfloat16*)vh, (const __nv_bfloat16*)vl,
        ao);

    // 4) Output projection (fp16)
    gemm_fp16<<<dim3(HIDDEN / 128, T_SEQ / 128), 256, GSM>>>(
        (const __half*)ao, (const __half*)wo, out, T_SEQ, HIDDEN, HIDDEN);
}

// round 11
// speedup vs baseline: 14.0051x; 1.0345x over previous
#include <cuda_runtime.h>
#include <cuda_bf16.h>
#include <cuda_fp16.h>
#include <math.h>
#include <stdint.h>

#define T_SEQ  2048
#define HIDDEN 4096
#define NH     32
#define NKV    8
#define HD     128
#define Q_SIZE  (NH * HD)              // 4096
#define KV_SIZE (NKV * HD)             // 1024
#define QKV_N   (Q_SIZE + 2 * KV_SIZE) // 6144
#define SCALE   0.08838834764831845f   // 128^-0.5

// ---------------------------------------------------------------------------
// Global scratch. No cudaMalloc allowed.
// ---------------------------------------------------------------------------
__device__ float    g_qkv[(size_t)T_SEQ * QKV_N];              // fp32 QKV
__device__ uint32_t g_hid[(size_t)T_SEQ * HIDDEN / 2];         // fp16
__device__ uint32_t g_wqkv[(size_t)HIDDEN * QKV_N / 2];        // fp16
__device__ uint32_t g_wo[(size_t)HIDDEN * HIDDEN / 2];         // fp16
__device__ uint32_t g_qh[(size_t)T_SEQ * Q_SIZE / 2];          // bf16 (attn)
__device__ uint32_t g_ql[(size_t)T_SEQ * Q_SIZE / 2];
__device__ uint32_t g_kh[(size_t)T_SEQ * KV_SIZE / 2];
__device__ uint32_t g_kl[(size_t)T_SEQ * KV_SIZE / 2];
__device__ uint32_t g_vh[(size_t)T_SEQ * KV_SIZE / 2];
__device__ uint32_t g_vl[(size_t)T_SEQ * KV_SIZE / 2];
__device__ uint32_t g_ao[(size_t)T_SEQ * Q_SIZE / 2];          // fp16 attn out

// ---------------------------------------------------------------------------
// Helpers
// ---------------------------------------------------------------------------
__device__ __forceinline__ uint32_t smem_u32(const void* p) {
    uint32_t a;
    asm("{ .reg .u64 t; cvta.to.shared.u64 t, %1; cvt.u32.u64 %0, t; }"
        : "=r"(a) : "l"(p));
    return a;
}
// bf16 MMA (attention)
__device__ __forceinline__ void mma16(float* c, const uint32_t* a,
                                      const uint32_t* b) {
    asm volatile(
        "mma.sync.aligned.m16n8k16.row.col.f32.bf16.bf16.f32 "
        "{%0,%1,%2,%3}, {%4,%5,%6,%7}, {%8,%9}, {%0,%1,%2,%3};"
        : "+f"(c[0]), "+f"(c[1]), "+f"(c[2]), "+f"(c[3])
        : "r"(a[0]), "r"(a[1]), "r"(a[2]), "r"(a[3]), "r"(b[0]), "r"(b[1]));
}
// fp16 MMA (GEMMs)
__device__ __forceinline__ void mma16h(float* c, const uint32_t* a,
                                       const uint32_t* b) {
    asm volatile(
        "mma.sync.aligned.m16n8k16.row.col.f32.f16.f16.f32 "
        "{%0,%1,%2,%3}, {%4,%5,%6,%7}, {%8,%9}, {%0,%1,%2,%3};"
        : "+f"(c[0]), "+f"(c[1]), "+f"(c[2]), "+f"(c[3])
        : "r"(a[0]), "r"(a[1]), "r"(a[2]), "r"(a[3]), "r"(b[0]), "r"(b[1]));
}
__device__ __forceinline__ void ldmx4(uint32_t* r, uint32_t addr) {
    asm volatile(
        "ldmatrix.sync.aligned.m8n8.x4.shared.b16 {%0,%1,%2,%3}, [%4];"
        : "=r"(r[0]), "=r"(r[1]), "=r"(r[2]), "=r"(r[3]) : "r"(addr));
}
__device__ __forceinline__ void ldmx4t(uint32_t* r, uint32_t addr) {
    asm volatile(
        "ldmatrix.sync.aligned.m8n8.x4.trans.shared.b16 {%0,%1,%2,%3}, [%4];"
        : "=r"(r[0]), "=r"(r[1]), "=r"(r[2]), "=r"(r[3]) : "r"(addr));
}
// bf16 hi/lo split
__device__ __forceinline__ void split2(float x, float y,
                                       uint32_t& hi, uint32_t& lo) {
    __nv_bfloat162 h = __floats2bfloat162_rn(x, y);
    float hx = __bfloat162float(h.x);
    float hy = __bfloat162float(h.y);
    __nv_bfloat162 l = __floats2bfloat162_rn(x - hx, y - hy);
    hi = *(uint32_t*)&h;
    lo = *(uint32_t*)&l;
}
__device__ __forceinline__ void cpa16(uint32_t dst, const void* src) {
    asm volatile("cp.async.cg.shared.global [%0], [%1], 16;"
                 :: "r"(dst), "l"(src));
}
__device__ __forceinline__ void cpa_commit() {
    asm volatile("cp.async.commit_group;");
}
template <int N>
__device__ __forceinline__ void cpa_wait() {
    asm volatile("cp.async.wait_group %0;" :: "n"(N));
}

// ---------------------------------------------------------------------------
// fp32 -> fp16 (single rounding)
// ---------------------------------------------------------------------------
__global__ __launch_bounds__(256) void convert_h(
    const float4* __restrict__ src, uint2* __restrict__ dh, int n4)
{
    for (int i = blockIdx.x * blockDim.x + threadIdx.x; i < n4;
         i += gridDim.x * blockDim.x) {
        float4 v = src[i];
        __half2 a = __floats2half2_rn(v.x, v.y);
        __half2 b = __floats2half2_rn(v.z, v.w);
        dh[i] = make_uint2(*(uint32_t*)&a, *(uint32_t*)&b);
    }
}

// ---------------------------------------------------------------------------
// RoPE + split to bf16 hi/lo (Q, K, and V — V MUST be hi/lo; single bf16
// V measured at ~1.6e-3 output error in R10).
// ---------------------------------------------------------------------------
__global__ __launch_bounds__(256) void rope_split_kernel(
    const float* __restrict__ qkv, const int* __restrict__ positions,
    uint32_t* __restrict__ qh, uint32_t* __restrict__ ql,
    uint32_t* __restrict__ kh, uint32_t* __restrict__ kl,
    uint32_t* __restrict__ vh, uint32_t* __restrict__ vl)
{
    __shared__ float s_if[64];
    const int t = blockIdx.x;
    if (threadIdx.x < 64) {
        double e = (double)(2 * threadIdx.x) / (double)HD;
        s_if[threadIdx.x] = (float)pow(500000.0, -e);
    }
    __syncthreads();

    const float p = (float)positions[t];
    const size_t base = (size_t)t * QKV_N;

    for (int idx = threadIdx.x; idx < QKV_N / 2; idx += blockDim.x) {
        uint32_t uh, ul;
        if (idx < (NH + NKV) * 64) {
            const int head = idx >> 6;
            const int i = idx & 63;
            float s, c;
            sincosf(p * s_if[i], &s, &c);
            if (head < NH) {
                float2 x = *(const float2*)&qkv[base + head * HD + 2 * i];
                float o1 = (x.x * c - x.y * s) * SCALE;
                float o2 = (x.y * c + x.x * s) * SCALE;
                split2(o1, o2, uh, ul);
                int d = (t * Q_SIZE + head * HD + 2 * i) >> 1;
                qh[d] = uh; ql[d] = ul;
            } else {
                const int kk = head - NH;
                float2 x = *(const float2*)&qkv[base + Q_SIZE + kk * HD + 2 * i];
                float o1 = x.x * c - x.y * s;
                float o2 = x.y * c + x.x * s;
                split2(o1, o2, uh, ul);
                int d = (t * KV_SIZE + kk * HD + 2 * i) >> 1;
                kh[d] = uh; kl[d] = ul;
            }
        } else {
            const int off = idx - (NH + NKV) * 64;
            float2 x = *(const float2*)&qkv[base + Q_SIZE + KV_SIZE + 2 * off];
            split2(x.x, x.y, uh, ul);
            int d = (t * KV_SIZE + 2 * off) >> 1;
            vh[d] = uh; vl[d] = ul;
        }
    }
}

// ---------------------------------------------------------------------------
// Pure FP16 GEMM: C[M,N] = A[M,K] @ B[K,N].
// CTA 128x128, 128 threads (4 warps), warp tile 64x64 (smem reads halved:
// A/B each duplicated only 2x across warps). BK=64, 3-stage cp.async.
// ---------------------------------------------------------------------------
#define GBK 64
#define AST 72                  // A row stride (elems): 64 + 8 pad
#define BST 136                 // B k-row stride (elems): 128 + 8 pad
#define STG_B   (128 * AST)     // 9216 elems
#define STG_ELEMS (128 * AST + GBK * BST)   // 17920 elems = 35840 B
#define NSTG 3

__global__ __launch_bounds__(128, 2) void gemm_fp16(
    const __half* __restrict__ A, const __half* __restrict__ B,
    float* __restrict__ C, int M, int N, int K)
{
    extern __shared__ __align__(16) __half sm[];
    const uint32_t smb = smem_u32(sm);

    const int tid  = threadIdx.x;
    const int wid  = tid >> 5;
    const int lane = tid & 31;
    const int g    = lane >> 2;
    const int tg   = lane & 3;
    const int wm   = (wid >> 1) * 64;     // 2x2 warp grid, 64x64 tiles
    const int wn   = (wid & 1) * 64;
    const int m0 = blockIdx.y * 128;
    const int n0 = blockIdx.x * 128;

    const int l7  = lane & 7;
    const int l8  = (lane >> 3) & 1;
    const int l16 = lane >> 4;
    const uint32_t aFrag = (uint32_t)(((wm + l7 + l8 * 8) * AST + l16 * 8) * 2);
    const uint32_t bFrag = (uint32_t)(STG_B * 2) +
        (uint32_t)(((l7 + l8 * 8) * BST + wn + l16 * 8) * 2);

    float acc[4][8][4];
    #pragma unroll
    for (int i = 0; i < 4; i++)
        #pragma unroll
        for (int j = 0; j < 8; j++)
            #pragma unroll
            for (int q = 0; q < 4; q++) acc[i][j][q] = 0.f;

    const int KT = K / GBK;

    auto issue = [&](int kt, int s) {
        const int kk = kt * GBK;
        const uint32_t sb = smb + (uint32_t)(s * STG_ELEMS * 2);
        #pragma unroll
        for (int i = 0; i < 8; i++) {
            const int c = tid + i * 128;
            const int row = c >> 3, c8 = (c & 7) * 8;
            cpa16(sb + (row * AST + c8) * 2,
                  A + (size_t)(m0 + row) * K + kk + c8);
        }
        #pragma unroll
        for (int i = 0; i < 8; i++) {
            const int c = tid + i * 128;
            const int row = c >> 4, c8 = (c & 15) * 8;
            cpa16(sb + (STG_B + row * BST + c8) * 2,
                  B + (size_t)(kk + row) * N + n0 + c8);
        }
    };

    issue(0, 0); cpa_commit();
    issue(1, 1); cpa_commit();

    int stage = 0;
    for (int kt = 0; kt < KT; kt++) {
        cpa_wait<1>();
        __syncthreads();

        if (kt + 2 < KT) {
            int s2 = stage + 2; if (s2 >= NSTG) s2 -= NSTG;
            issue(kt + 2, s2);
        }
        cpa_commit();

        const uint32_t sb = smb + (uint32_t)(stage * STG_ELEMS * 2);
        const uint32_t aA = sb + aFrag;
        const uint32_t bA = sb + bFrag;

        uint32_t aF[2][4][4];
        #pragma unroll
        for (int mt = 0; mt < 4; mt++)
            ldmx4(aF[0][mt], aA + mt * (16 * AST * 2));

        #pragma unroll
        for (int ks = 0; ks < 4; ks++) {
            const int cur = ks & 1;
            uint32_t bh[4][4];
            #pragma unroll
            for (int pp = 0; pp < 4; pp++)
                ldmx4t(bh[pp], bA + ks * (16 * BST * 2) + pp * 32);
            if (ks < 3) {
                #pragma unroll
                for (int mt = 0; mt < 4; mt++)
                    ldmx4(aF[cur ^ 1][mt],
                          aA + mt * (16 * AST * 2) + (ks + 1) * 32);
            }
            #pragma unroll
            for (int mt = 0; mt < 4; mt++)
                #pragma unroll
                for (int nt = 0; nt < 8; nt++)
                    mma16h(acc[mt][nt], aF[cur][mt],
                           &bh[nt >> 1][(nt & 1) * 2]);
        }
        if (++stage == NSTG) stage = 0;
    }

    #pragma unroll
    for (int mt = 0; mt < 4; mt++) {
        const int row = m0 + wm + mt * 16 + g;
        #pragma unroll
        for (int nt = 0; nt < 8; nt++) {
            const int col = n0 + wn + nt * 8 + tg * 2;
            *(float2*)&C[(size_t)row * N + col] =
                make_float2(acc[mt][nt][0], acc[mt][nt][1]);
            *(float2*)&C[(size_t)(row + 8) * N + col] =
                make_float2(acc[mt][nt][2], acc[mt][nt][3]);
        }
    }
}

// ---------------------------------------------------------------------------
// Tensor-core causal GQA flash attention (bf16x3 S and PV — proven at
// rel_err 5.5e-4). fp16 epilogue for the O-projection.
// ---------------------------------------------------------------------------
#define FBM 128
#define FBN 64
#define KVST 136
#define OQL_E   17408
#define KVB_E   34816
#define KV_STG  34816                   // per stage: Kh, Kl, Vh, Vl
#define SK_L    8704
#define SV_H    17408
#define SV_L    26112
#define ATT_SMEM_BYTES ((KVB_E + 2 * KV_STG) * 2)   // 208896

__global__ __launch_bounds__(256, 1) void attn_tc2_kernel(
    const __nv_bfloat16* __restrict__ Qh, const __nv_bfloat16* __restrict__ Ql,
    const __nv_bfloat16* __restrict__ Kh, const __nv_bfloat16* __restrict__ Kl,
    const __nv_bfloat16* __restrict__ Vh, const __nv_bfloat16* __restrict__ Vl,
    uint32_t* __restrict__ Oo)
{
    extern __shared__ __align__(16) __nv_bfloat16 asmem[];
    const uint32_t smb = smem_u32(asmem);

    const int tid  = threadIdx.x;
    const int wid  = tid >> 5;
    const int lane = tid & 31;
    const int g    = lane >> 2;
    const int tg   = lane & 3;
    const int mt   = (gridDim.x - 1) - blockIdx.x;
    const int m0   = mt * FBM;
    const int h    = blockIdx.y;
    const int kh   = h >> 2;

    const int l7  = lane & 7;
    const int l8  = (lane >> 3) & 1;
    const int l16 = lane >> 4;

    const int lr = tid >> 4;
    const int lc = tid & 15;

    #pragma unroll
    for (int i = 0; i < 8; i++) {
        const int row = lr + i * 16;
        const size_t go = (size_t)(m0 + row) * Q_SIZE + h * HD + lc * 8;
        cpa16(smb + (row * KVST + lc * 8) * 2, Qh + go);
        cpa16(smb + (OQL_E + row * KVST + lc * 8) * 2, Ql + go);
    }
    cpa_commit();

    auto issueKV = [&](int j0, int s) {
        const uint32_t sb = smb + (uint32_t)((KVB_E + s * KV_STG) * 2);
        #pragma unroll
        for (int i = 0; i < 4; i++) {
            const int row = lr + i * 16;
            const size_t go = (size_t)(j0 + row) * KV_SIZE + kh * HD + lc * 8;
            const uint32_t so = (row * KVST + lc * 8) * 2;
            cpa16(sb + so, Kh + go);
            cpa16(sb + SK_L * 2 + so, Kl + go);
            cpa16(sb + SV_H * 2 + so, Vh + go);
            cpa16(sb + SV_L * 2 + so, Vl + go);
        }
    };

    issueKV(0, 0);
    cpa_commit();

    float o[16][4];
    #pragma unroll
    for (int n = 0; n < 16; n++)
        #pragma unroll
        for (int q = 0; q < 4; q++) o[n][q] = 0.f;
    float m_0 = -1e30f, m_1 = -1e30f, l_0 = 0.f, l_1 = 0.f;

    const uint32_t qFrag =
        (uint32_t)(((wid * 16 + l7 + l8 * 8) * KVST + l16 * 8) * 2);
    const uint32_t kFrag =
        (uint32_t)(((l7 + l16 * 8) * KVST + l8 * 8) * 2);
    const uint32_t vFrag =
        (uint32_t)(((l7 + l8 * 8) * KVST + l16 * 8) * 2);

    const int ntiles = m0 / FBN + 2;

    for (int jt = 0; jt < ntiles; jt++) {
        if (jt + 1 < ntiles) issueKV((jt + 1) * FBN, (jt + 1) & 1);
        cpa_commit();
        cpa_wait<1>();
        __syncthreads();

        const int j0 = jt * FBN;
        const uint32_t sb = smb + (uint32_t)((KVB_E + (jt & 1) * KV_STG) * 2);
        const uint32_t kB = sb + kFrag;
        const uint32_t vB = sb + SV_H * 2 + vFrag;

        float s[8][4];
        #pragma unroll
        for (int n = 0; n < 8; n++)
            #pragma unroll
            for (int q = 0; q < 4; q++) s[n][q] = 0.f;

        #pragma unroll
        for (int kt = 0; kt < 8; kt++) {
            uint32_t ah[4], al[4];
            ldmx4(ah, smb + qFrag + kt * 32);
            ldmx4(al, smb + OQL_E * 2 + qFrag + kt * 32);
            #pragma unroll
            for (int p = 0; p < 4; p++) {
                uint32_t bh[4], bl[4];
                const uint32_t ka = kB + p * (16 * KVST * 2) + kt * 32;
                ldmx4(bh, ka);
                ldmx4(bl, ka + SK_L * 2);
                mma16(s[2 * p],     ah, &bh[0]);
                mma16(s[2 * p],     al, &bh[0]);
                mma16(s[2 * p],     ah, &bl[0]);
                mma16(s[2 * p + 1], ah, &bh[2]);
                mma16(s[2 * p + 1], al, &bh[2]);
                mma16(s[2 * p + 1], ah, &bl[2]);
            }
        }

        const int row0 = m0 + wid * 16 + g;
        const int row1 = row0 + 8;
        if (j0 + FBN - 1 > row0) {
            #pragma unroll
            for (int n = 0; n < 8; n++) {
                int col = j0 + n * 8 + 2 * tg;
                if (col     > row0) s[n][0] = -1e30f;
                if (col + 1 > row0) s[n][1] = -1e30f;
                if (col     > row1) s[n][2] = -1e30f;
                if (col + 1 > row1) s[n][3] = -1e30f;
            }
        }

        float rmax0 = -1e30f, rmax1 = -1e30f;
        #pragma unroll
        for (int n = 0; n < 8; n++) {
            rmax0 = fmaxf(rmax0, fmaxf(s[n][0], s[n][1]));
            rmax1 = fmaxf(rmax1, fmaxf(s[n][2], s[n][3]));
        }
        rmax0 = fmaxf(rmax0, __shfl_xor_sync(0xffffffffu, rmax0, 1));
        rmax0 = fmaxf(rmax0, __shfl_xor_sync(0xffffffffu, rmax0, 2));
        rmax1 = fmaxf(rmax1, __shfl_xor_sync(0xffffffffu, rmax1, 1));
        rmax1 = fmaxf(rmax1, __shfl_xor_sync(0xffffffffu, rmax1, 2));

        float mn0 = fmaxf(m_0, rmax0), mn1 = fmaxf(m_1, rmax1);
        float f0 = __expf(m_0 - mn0), f1 = __expf(m_1 - mn1);
        m_0 = mn0; m_1 = mn1;

        float rs0 = 0.f, rs1 = 0.f;
        #pragma unroll
        for (int n = 0; n < 8; n++) {
            s[n][0] = __expf(s[n][0] - mn0);
            s[n][1] = __expf(s[n][1] - mn0);
            s[n][2] = __expf(s[n][2] - mn1);
            s[n][3] = __expf(s[n][3] - mn1);
            rs0 += s[n][0] + s[n][1];
            rs1 += s[n][2] + s[n][3];
        }
        rs0 += __shfl_xor_sync(0xffffffffu, rs0, 1);
        rs0 += __shfl_xor_sync(0xffffffffu, rs0, 2);
        rs1 += __shfl_xor_sync(0xffffffffu, rs1, 1);
        rs1 += __shfl_xor_sync(0xffffffffu, rs1, 2);
        l_0 = l_0 * f0 + rs0;
        l_1 = l_1 * f1 + rs1;

        #pragma unroll
        for (int n = 0; n < 16; n++) {
            o[n][0] *= f0; o[n][1] *= f0;
            o[n][2] *= f1; o[n][3] *= f1;
        }

        // O += P V, 3-term: Ph*Vh + Pl*Vh + Ph*Vl
        #pragma unroll
        for (int kt = 0; kt < 4; kt++) {
            uint32_t ph[4], pl[4];
            split2(s[2 * kt][0],     s[2 * kt][1],     ph[0], pl[0]);
            split2(s[2 * kt][2],     s[2 * kt][3],     ph[1], pl[1]);
            split2(s[2 * kt + 1][0], s[2 * kt + 1][1], ph[2], pl[2]);
            split2(s[2 * kt + 1][2], s[2 * kt + 1][3], ph[3], pl[3]);
            #pragma unroll
            for (int p = 0; p < 8; p++) {
                uint32_t bh[4], bl[4];
                const uint32_t va = vB + kt * (16 * KVST * 2) + p * 32;
                ldmx4t(bh, va);
                ldmx4t(bl, va + (SV_L - SV_H) * 2);
                mma16(o[2 * p],     ph, &bh[0]);
                mma16(o[2 * p],     pl, &bh[0]);
                mma16(o[2 * p],     ph, &bl[0]);
                mma16(o[2 * p + 1], ph, &bh[2]);
                mma16(o[2 * p + 1], pl, &bh[2]);
                mma16(o[2 * p + 1], ph, &bl[2]);
            }
        }
        __syncthreads();
    }

    // epilogue: single fp16 output for the O-projection
    const float il0 = 1.0f / l_0;
    const float il1 = 1.0f / l_1;
    const int row0 = m0 + wid * 16 + g;
    #pragma unroll
    for (int n = 0; n < 16; n++) {
        const int col = n * 8 + 2 * tg;
        __half2 h0 = __floats2half2_rn(o[n][0] * il0, o[n][1] * il0);
        Oo[((size_t)row0 * Q_SIZE + h * HD + col) >> 1] = *(uint32_t*)&h0;
        __half2 h1 = __floats2half2_rn(o[n][2] * il1, o[n][3] * il1);
        Oo[((size_t)(row0 + 8) * Q_SIZE + h * HD + col) >> 1] = *(uint32_t*)&h1;
    }
}

// ---------------------------------------------------------------------------
extern "C" void kernel_launch(void* const* d_in, const int* in_sizes, int n_in,
                              void* d_out, int out_size)
{
    const int*   positions = (const int*)d_in[0];
    const float* hidden    = (const float*)d_in[1];
    const float* w_qkv     = (const float*)d_in[2];
    const float* w_o       = (const float*)d_in[3];
    float* out = (float*)d_out;

    float* qkv = nullptr;
    uint32_t *hid, *wqkv, *wo;
    uint32_t *qh, *ql, *kh, *kl, *vh, *vl, *ao;
    cudaGetSymbolAddress((void**)&qkv,  g_qkv);
    cudaGetSymbolAddress((void**)&hid,  g_hid);
    cudaGetSymbolAddress((void**)&wqkv, g_wqkv);
    cudaGetSymbolAddress((void**)&wo,   g_wo);
    cudaGetSymbolAddress((void**)&qh, g_qh);
    cudaGetSymbolAddress((void**)&ql, g_ql);
    cudaGetSymbolAddress((void**)&kh, g_kh);
    cudaGetSymbolAddress((void**)&kl, g_kl);
    cudaGetSymbolAddress((void**)&vh, g_vh);
    cudaGetSymbolAddress((void**)&vl, g_vl);
    cudaGetSymbolAddress((void**)&ao, g_ao);

    const int GSM = NSTG * STG_ELEMS * 2;   // 107520
    cudaFuncSetAttribute(gemm_fp16,
                         cudaFuncAttributeMaxDynamicSharedMemorySize, GSM);
    cudaFuncSetAttribute(attn_tc2_kernel,
                         cudaFuncAttributeMaxDynamicSharedMemorySize,
                         ATT_SMEM_BYTES);

    // 0) conversions to fp16
    convert_h<<<2048, 256>>>((const float4*)hidden, (uint2*)hid,
                             T_SEQ * HIDDEN / 4);
    convert_h<<<4096, 256>>>((const float4*)w_qkv, (uint2*)wqkv,
                             HIDDEN * QKV_N / 4);
    convert_h<<<4096, 256>>>((const float4*)w_o, (uint2*)wo,
                             HIDDEN * HIDDEN / 4);

    // 1) QKV projection (fp16, 64x64 warp tiles)
    gemm_fp16<<<dim3(QKV_N / 128, T_SEQ / 128), 128, GSM>>>(
        (const __half*)hid, (const __half*)wqkv, qkv, T_SEQ, QKV_N, HIDDEN);

    // 2) RoPE + split to bf16 (V hi/lo restored)
    rope_split_kernel<<<T_SEQ, 256>>>(qkv, positions, qh, ql, kh, kl, vh, vl);

    // 3) Flash attention (bf16x3)
    attn_tc2_kernel<<<dim3(T_SEQ / FBM, NH), 256, ATT_SMEM_BYTES>>>(
        (const __nv_bfloat16*)qh, (const __nv_bfloat16*)ql,
        (const __nv_bfloat16*)kh, (const __nv_bfloat16*)kl,
        (const __nv_bfloat16*)vh, (const __nv_bfloat16*)vl,
        ao);

    // 4) Output projection (fp16)
    gemm_fp16<<<dim3(HIDDEN / 128, T_SEQ / 128), 128, GSM>>>(
        (const __half*)ao, (const __half*)wo, out, T_SEQ, HIDDEN, HIDDEN);
}

// round 12
// speedup vs baseline: 14.4734x; 1.0334x over previous
#include <cuda_runtime.h>
#include <cuda_bf16.h>
#include <cuda_fp16.h>
#include <math.h>
#include <stdint.h>

#define T_SEQ  2048
#define HIDDEN 4096
#define NH     32
#define NKV    8
#define HD     128
#define Q_SIZE  (NH * HD)              // 4096
#define KV_SIZE (NKV * HD)             // 1024
#define QKV_N   (Q_SIZE + 2 * KV_SIZE) // 6144
#define SCALE   0.08838834764831845f   // 128^-0.5

// ---------------------------------------------------------------------------
// Global scratch. No cudaMalloc allowed.
// ---------------------------------------------------------------------------
__device__ uint32_t g_hid[(size_t)T_SEQ * HIDDEN / 2];         // fp16
__device__ uint32_t g_wqkv[(size_t)HIDDEN * QKV_N / 2];        // fp16
__device__ uint32_t g_wo[(size_t)HIDDEN * HIDDEN / 2];         // fp16
__device__ uint32_t g_qh[(size_t)T_SEQ * Q_SIZE / 2];          // bf16 (attn)
__device__ uint32_t g_ql[(size_t)T_SEQ * Q_SIZE / 2];
__device__ uint32_t g_kh[(size_t)T_SEQ * KV_SIZE / 2];
__device__ uint32_t g_kl[(size_t)T_SEQ * KV_SIZE / 2];
__device__ uint32_t g_vf[(size_t)T_SEQ * KV_SIZE / 2];         // fp16 V
__device__ uint32_t g_ao[(size_t)T_SEQ * Q_SIZE / 2];          // fp16 attn out

// ---------------------------------------------------------------------------
// Helpers
// ---------------------------------------------------------------------------
__device__ __forceinline__ uint32_t smem_u32(const void* p) {
    uint32_t a;
    asm("{ .reg .u64 t; cvta.to.shared.u64 t, %1; cvt.u32.u64 %0, t; }"
        : "=r"(a) : "l"(p));
    return a;
}
// bf16 MMA (attention S path)
__device__ __forceinline__ void mma16(float* c, const uint32_t* a,
                                      const uint32_t* b) {
    asm volatile(
        "mma.sync.aligned.m16n8k16.row.col.f32.bf16.bf16.f32 "
        "{%0,%1,%2,%3}, {%4,%5,%6,%7}, {%8,%9}, {%0,%1,%2,%3};"
        : "+f"(c[0]), "+f"(c[1]), "+f"(c[2]), "+f"(c[3])
        : "r"(a[0]), "r"(a[1]), "r"(a[2]), "r"(a[3]), "r"(b[0]), "r"(b[1]));
}
// fp16 MMA (GEMMs + attention PV)
__device__ __forceinline__ void mma16h(float* c, const uint32_t* a,
                                       const uint32_t* b) {
    asm volatile(
        "mma.sync.aligned.m16n8k16.row.col.f32.f16.f16.f32 "
        "{%0,%1,%2,%3}, {%4,%5,%6,%7}, {%8,%9}, {%0,%1,%2,%3};"
        : "+f"(c[0]), "+f"(c[1]), "+f"(c[2]), "+f"(c[3])
        : "r"(a[0]), "r"(a[1]), "r"(a[2]), "r"(a[3]), "r"(b[0]), "r"(b[1]));
}
__device__ __forceinline__ void ldmx4(uint32_t* r, uint32_t addr) {
    asm volatile(
        "ldmatrix.sync.aligned.m8n8.x4.shared.b16 {%0,%1,%2,%3}, [%4];"
        : "=r"(r[0]), "=r"(r[1]), "=r"(r[2]), "=r"(r[3]) : "r"(addr));
}
__device__ __forceinline__ void ldmx4t(uint32_t* r, uint32_t addr) {
    asm volatile(
        "ldmatrix.sync.aligned.m8n8.x4.trans.shared.b16 {%0,%1,%2,%3}, [%4];"
        : "=r"(r[0]), "=r"(r[1]), "=r"(r[2]), "=r"(r[3]) : "r"(addr));
}
// bf16 hi/lo split
__device__ __forceinline__ void split2(float x, float y,
                                       uint32_t& hi, uint32_t& lo) {
    __nv_bfloat162 h = __floats2bfloat162_rn(x, y);
    float hx = __bfloat162float(h.x);
    float hy = __bfloat162float(h.y);
    __nv_bfloat162 l = __floats2bfloat162_rn(x - hx, y - hy);
    hi = *(uint32_t*)&h;
    lo = *(uint32_t*)&l;
}
// fp16 hi/lo split (P fragments)
__device__ __forceinline__ void split2h(float x, float y,
                                        uint32_t& hi, uint32_t& lo) {
    __half2 h = __floats2half2_rn(x, y);
    float hx = __half2float(__low2half(h));
    float hy = __half2float(__high2half(h));
    __half2 l = __floats2half2_rn(x - hx, y - hy);
    hi = *(uint32_t*)&h;
    lo = *(uint32_t*)&l;
}
__device__ __forceinline__ void cpa16(uint32_t dst, const void* src) {
    asm volatile("cp.async.cg.shared.global [%0], [%1], 16;"
                 :: "r"(dst), "l"(src));
}
__device__ __forceinline__ void cpa_commit() {
    asm volatile("cp.async.commit_group;");
}
template <int N>
__device__ __forceinline__ void cpa_wait() {
    asm volatile("cp.async.wait_group %0;" :: "n"(N));
}

// ---------------------------------------------------------------------------
// fp32 -> fp16 (single rounding)
// ---------------------------------------------------------------------------
__global__ __launch_bounds__(256) void convert_h(
    const float4* __restrict__ src, uint2* __restrict__ dh, int n4)
{
    for (int i = blockIdx.x * blockDim.x + threadIdx.x; i < n4;
         i += gridDim.x * blockDim.x) {
        float4 v = src[i];
        __half2 a = __floats2half2_rn(v.x, v.y);
        __half2 b = __floats2half2_rn(v.z, v.w);
        dh[i] = make_uint2(*(uint32_t*)&a, *(uint32_t*)&b);
    }
}

// ===========================================================================
// QKV GEMM with fused RoPE epilogue.
// C = hid[M,K] @ wqkv[K,N]; columns <4096 -> rope+scale -> qh/ql (bf16),
// 4096..5119 -> rope -> kh/kl (bf16), >=5120 -> vf (fp16).
// CTA 128x128, 128 threads, 64x64 warp tiles, BK=64, 3-stage cp.async.
// ===========================================================================
#define GBK 64
#define AST 72
#define BST 136
#define STG_B   (128 * AST)     // 9216 elems
#define STG_ELEMS (128 * AST + GBK * BST)   // 17920 elems = 35840 B
#define NSTG 3

__global__ __launch_bounds__(128, 2) void gemm_qkv_fused(
    const __half* __restrict__ A, const __half* __restrict__ B,
    const int* __restrict__ positions,
    uint32_t* __restrict__ qh, uint32_t* __restrict__ ql,
    uint32_t* __restrict__ kh, uint32_t* __restrict__ kl,
    uint32_t* __restrict__ vf)
{
    extern __shared__ __align__(16) __half sm[];
    __shared__ float s_if[64];
    const uint32_t smb = smem_u32(sm);

    const int tid  = threadIdx.x;
    const int wid  = tid >> 5;
    const int lane = tid & 31;
    const int g    = lane >> 2;
    const int tg   = lane & 3;
    const int wm   = (wid >> 1) * 64;
    const int wn   = (wid & 1) * 64;
    const int m0 = blockIdx.y * 128;
    const int n0 = blockIdx.x * 128;
    const int K = HIDDEN, N = QKV_N;

    if (tid < 64) {
        double e = (double)(2 * tid) / (double)HD;
        s_if[tid] = (float)pow(500000.0, -e);
    }

    const int l7  = lane & 7;
    const int l8  = (lane >> 3) & 1;
    const int l16 = lane >> 4;
    const uint32_t aFrag = (uint32_t)(((wm + l7 + l8 * 8) * AST + l16 * 8) * 2);
    const uint32_t bFrag = (uint32_t)(STG_B * 2) +
        (uint32_t)(((l7 + l8 * 8) * BST + wn + l16 * 8) * 2);

    float acc[4][8][4];
    #pragma unroll
    for (int i = 0; i < 4; i++)
        #pragma unroll
        for (int j = 0; j < 8; j++)
            #pragma unroll
            for (int q = 0; q < 4; q++) acc[i][j][q] = 0.f;

    const int KT = K / GBK;

    auto issue = [&](int kt, int s) {
        const int kk = kt * GBK;
        const uint32_t sb = smb + (uint32_t)(s * STG_ELEMS * 2);
        #pragma unroll
        for (int i = 0; i < 8; i++) {
            const int c = tid + i * 128;
            const int row = c >> 3, c8 = (c & 7) * 8;
            cpa16(sb + (row * AST + c8) * 2,
                  A + (size_t)(m0 + row) * K + kk + c8);
        }
        #pragma unroll
        for (int i = 0; i < 8; i++) {
            const int c = tid + i * 128;
            const int row = c >> 4, c8 = (c & 15) * 8;
            cpa16(sb + (STG_B + row * BST + c8) * 2,
                  B + (size_t)(kk + row) * N + n0 + c8);
        }
    };

    issue(0, 0); cpa_commit();
    issue(1, 1); cpa_commit();

    int stage = 0;
    for (int kt = 0; kt < KT; kt++) {
        cpa_wait<1>();
        __syncthreads();

        if (kt + 2 < KT) {
            int s2 = stage + 2; if (s2 >= NSTG) s2 -= NSTG;
            issue(kt + 2, s2);
        }
        cpa_commit();

        const uint32_t sb = smb + (uint32_t)(stage * STG_ELEMS * 2);
        const uint32_t aA = sb + aFrag;
        const uint32_t bA = sb + bFrag;

        uint32_t aF[2][4][4];
        #pragma unroll
        for (int mt = 0; mt < 4; mt++)
            ldmx4(aF[0][mt], aA + mt * (16 * AST * 2));

        #pragma unroll
        for (int ks = 0; ks < 4; ks++) {
            const int cur = ks & 1;
            uint32_t bh[4][4];
            #pragma unroll
            for (int pp = 0; pp < 4; pp++)
                ldmx4t(bh[pp], bA + ks * (16 * BST * 2) + pp * 32);
            if (ks < 3) {
                #pragma unroll
                for (int mt = 0; mt < 4; mt++)
                    ldmx4(aF[cur ^ 1][mt],
                          aA + mt * (16 * AST * 2) + (ks + 1) * 32);
            }
            #pragma unroll
            for (int mt = 0; mt < 4; mt++)
                #pragma unroll
                for (int nt = 0; nt < 8; nt++)
                    mma16h(acc[mt][nt], aF[cur][mt],
                           &bh[nt >> 1][(nt & 1) * 2]);
        }
        if (++stage == NSTG) stage = 0;
    }

    // ---- fused epilogue: rope + precision split, per region ----
    const int region = (n0 >= Q_SIZE + KV_SIZE) ? 2 : (n0 >= Q_SIZE ? 1 : 0);

    #pragma unroll
    for (int mt = 0; mt < 4; mt++) {
        const int rowA = m0 + wm + mt * 16 + g;
        const int rowB = rowA + 8;
        const float pa = (float)positions[rowA];
        const float pb = (float)positions[rowB];
        #pragma unroll
        for (int nt = 0; nt < 8; nt++) {
            const int col = n0 + wn + nt * 8 + tg * 2;
            const float x0a = acc[mt][nt][0], x1a = acc[mt][nt][1];
            const float x0b = acc[mt][nt][2], x1b = acc[mt][nt][3];
            if (region == 2) {
                const int c = col - (Q_SIZE + KV_SIZE);
                __half2 h0 = __floats2half2_rn(x0a, x1a);
                vf[((size_t)rowA * KV_SIZE + c) >> 1] = *(uint32_t*)&h0;
                __half2 h1 = __floats2half2_rn(x0b, x1b);
                vf[((size_t)rowB * KV_SIZE + c) >> 1] = *(uint32_t*)&h1;
            } else {
                const float invf = s_if[(col >> 1) & 63];
                float sa, ca, sb2, cb;
                sincosf(pa * invf, &sa, &ca);
                sincosf(pb * invf, &sb2, &cb);
                float o1 = x0a * ca - x1a * sa;
                float o2 = x1a * ca + x0a * sa;
                float o3 = x0b * cb - x1b * sb2;
                float o4 = x1b * cb + x0b * sb2;
                uint32_t uh, ul;
                if (region == 0) {
                    split2(o1 * SCALE, o2 * SCALE, uh, ul);
                    size_t d = ((size_t)rowA * Q_SIZE + col) >> 1;
                    qh[d] = uh; ql[d] = ul;
                    split2(o3 * SCALE, o4 * SCALE, uh, ul);
                    d = ((size_t)rowB * Q_SIZE + col) >> 1;
                    qh[d] = uh; ql[d] = ul;
                } else {
                    const int c = col - Q_SIZE;
                    split2(o1, o2, uh, ul);
                    size_t d = ((size_t)rowA * KV_SIZE + c) >> 1;
                    kh[d] = uh; kl[d] = ul;
                    split2(o3, o4, uh, ul);
                    d = ((size_t)rowB * KV_SIZE + c) >> 1;
                    kh[d] = uh; kl[d] = ul;
                }
            }
        }
    }
}

// ---------------------------------------------------------------------------
// Pure FP16 GEMM (O-projection): C[M,N] = A[M,K] @ B[K,N], fp32 out.
// ---------------------------------------------------------------------------
__global__ __launch_bounds__(128, 2) void gemm_fp16(
    const __half* __restrict__ A, const __half* __restrict__ B,
    float* __restrict__ C, int M, int N, int K)
{
    extern __shared__ __align__(16) __half sm[];
    const uint32_t smb = smem_u32(sm);

    const int tid  = threadIdx.x;
    const int wid  = tid >> 5;
    const int lane = tid & 31;
    const int g    = lane >> 2;
    const int tg   = lane & 3;
    const int wm   = (wid >> 1) * 64;
    const int wn   = (wid & 1) * 64;
    const int m0 = blockIdx.y * 128;
    const int n0 = blockIdx.x * 128;

    const int l7  = lane & 7;
    const int l8  = (lane >> 3) & 1;
    const int l16 = lane >> 4;
    const uint32_t aFrag = (uint32_t)(((wm + l7 + l8 * 8) * AST + l16 * 8) * 2);
    const uint32_t bFrag = (uint32_t)(STG_B * 2) +
        (uint32_t)(((l7 + l8 * 8) * BST + wn + l16 * 8) * 2);

    float acc[4][8][4];
    #pragma unroll
    for (int i = 0; i < 4; i++)
        #pragma unroll
        for (int j = 0; j < 8; j++)
            #pragma unroll
            for (int q = 0; q < 4; q++) acc[i][j][q] = 0.f;

    const int KT = K / GBK;

    auto issue = [&](int kt, int s) {
        const int kk = kt * GBK;
        const uint32_t sb = smb + (uint32_t)(s * STG_ELEMS * 2);
        #pragma unroll
        for (int i = 0; i < 8; i++) {
            const int c = tid + i * 128;
            const int row = c >> 3, c8 = (c & 7) * 8;
            cpa16(sb + (row * AST + c8) * 2,
                  A + (size_t)(m0 + row) * K + kk + c8);
        }
        #pragma unroll
        for (int i = 0; i < 8; i++) {
            const int c = tid + i * 128;
            const int row = c >> 4, c8 = (c & 15) * 8;
            cpa16(sb + (STG_B + row * BST + c8) * 2,
                  B + (size_t)(kk + row) * N + n0 + c8);
        }
    };

    issue(0, 0); cpa_commit();
    issue(1, 1); cpa_commit();

    int stage = 0;
    for (int kt = 0; kt < KT; kt++) {
        cpa_wait<1>();
        __syncthreads();

        if (kt + 2 < KT) {
            int s2 = stage + 2; if (s2 >= NSTG) s2 -= NSTG;
            issue(kt + 2, s2);
        }
        cpa_commit();

        const uint32_t sb = smb + (uint32_t)(stage * STG_ELEMS * 2);
        const uint32_t aA = sb + aFrag;
        const uint32_t bA = sb + bFrag;

        uint32_t aF[2][4][4];
        #pragma unroll
        for (int mt = 0; mt < 4; mt++)
            ldmx4(aF[0][mt], aA + mt * (16 * AST * 2));

        #pragma unroll
        for (int ks = 0; ks < 4; ks++) {
            const int cur = ks & 1;
            uint32_t bh[4][4];
            #pragma unroll
            for (int pp = 0; pp < 4; pp++)
                ldmx4t(bh[pp], bA + ks * (16 * BST * 2) + pp * 32);
            if (ks < 3) {
                #pragma unroll
                for (int mt = 0; mt < 4; mt++)
                    ldmx4(aF[cur ^ 1][mt],
                          aA + mt * (16 * AST * 2) + (ks + 1) * 32);
            }
            #pragma unroll
            for (int mt = 0; mt < 4; mt++)
                #pragma unroll
                for (int nt = 0; nt < 8; nt++)
                    mma16h(acc[mt][nt], aF[cur][mt],
                           &bh[nt >> 1][(nt & 1) * 2]);
        }
        if (++stage == NSTG) stage = 0;
    }

    #pragma unroll
    for (int mt = 0; mt < 4; mt++) {
        const int row = m0 + wm + mt * 16 + g;
        #pragma unroll
        for (int nt = 0; nt < 8; nt++) {
            const int col = n0 + wn + nt * 8 + tg * 2;
            *(float2*)&C[(size_t)row * N + col] =
                make_float2(acc[mt][nt][0], acc[mt][nt][1]);
            *(float2*)&C[(size_t)(row + 8) * N + col] =
                make_float2(acc[mt][nt][2], acc[mt][nt][3]);
        }
    }
}

// ---------------------------------------------------------------------------
// Tensor-core causal GQA flash attention.
// S = QK^T: bf16x3 (proven). PV: fp16 2-term (Ph+Pl)*Vf.
// ---------------------------------------------------------------------------
#define FBM 128
#define FBN 64
#define KVST 136
#define OQL_E   17408
#define KVB_E   34816
#define KV_STG  26112                   // per stage: Kh, Kl, Vf
#define SK_L    8704
#define SV      17408
#define ATT_SMEM_BYTES ((KVB_E + 2 * KV_STG) * 2)   // 174080

__global__ __launch_bounds__(256, 1) void attn_tc2_kernel(
    const __nv_bfloat16* __restrict__ Qh, const __nv_bfloat16* __restrict__ Ql,
    const __nv_bfloat16* __restrict__ Kh, const __nv_bfloat16* __restrict__ Kl,
    const __half* __restrict__ Vf,
    uint32_t* __restrict__ Oo)
{
    extern __shared__ __align__(16) __nv_bfloat16 asmem[];
    const uint32_t smb = smem_u32(asmem);

    const int tid  = threadIdx.x;
    const int wid  = tid >> 5;
    const int lane = tid & 31;
    const int g    = lane >> 2;
    const int tg   = lane & 3;
    const int mt   = (gridDim.x - 1) - blockIdx.x;
    const int m0   = mt * FBM;
    const int h    = blockIdx.y;
    const int kh   = h >> 2;

    const int l7  = lane & 7;
    const int l8  = (lane >> 3) & 1;
    const int l16 = lane >> 4;

    const int lr = tid >> 4;
    const int lc = tid & 15;

    #pragma unroll
    for (int i = 0; i < 8; i++) {
        const int row = lr + i * 16;
        const size_t go = (size_t)(m0 + row) * Q_SIZE + h * HD + lc * 8;
        cpa16(smb + (row * KVST + lc * 8) * 2, Qh + go);
        cpa16(smb + (OQL_E + row * KVST + lc * 8) * 2, Ql + go);
    }
    cpa_commit();

    auto issueKV = [&](int j0, int s) {
        const uint32_t sb = smb + (uint32_t)((KVB_E + s * KV_STG) * 2);
        #pragma unroll
        for (int i = 0; i < 4; i++) {
            const int row = lr + i * 16;
            const size_t go = (size_t)(j0 + row) * KV_SIZE + kh * HD + lc * 8;
            const uint32_t so = (row * KVST + lc * 8) * 2;
            cpa16(sb + so, Kh + go);
            cpa16(sb + SK_L * 2 + so, Kl + go);
            cpa16(sb + SV * 2 + so, Vf + go);
        }
    };

    issueKV(0, 0);
    cpa_commit();

    float o[16][4];
    #pragma unroll
    for (int n = 0; n < 16; n++)
        #pragma unroll
        for (int q = 0; q < 4; q++) o[n][q] = 0.f;
    float m_0 = -1e30f, m_1 = -1e30f, l_0 = 0.f, l_1 = 0.f;

    const uint32_t qFrag =
        (uint32_t)(((wid * 16 + l7 + l8 * 8) * KVST + l16 * 8) * 2);
    const uint32_t kFrag =
        (uint32_t)(((l7 + l16 * 8) * KVST + l8 * 8) * 2);
    const uint32_t vFrag =
        (uint32_t)(((l7 + l8 * 8) * KVST + l16 * 8) * 2);

    const int ntiles = m0 / FBN + 2;

    for (int jt = 0; jt < ntiles; jt++) {
        if (jt + 1 < ntiles) issueKV((jt + 1) * FBN, (jt + 1) & 1);
        cpa_commit();
        cpa_wait<1>();
        __syncthreads();

        const int j0 = jt * FBN;
        const uint32_t sb = smb + (uint32_t)((KVB_E + (jt & 1) * KV_STG) * 2);
        const uint32_t kB = sb + kFrag;
        const uint32_t vB = sb + SV * 2 + vFrag;

        float s[8][4];
        #pragma unroll
        for (int n = 0; n < 8; n++)
            #pragma unroll
            for (int q = 0; q < 4; q++) s[n][q] = 0.f;

        #pragma unroll
        for (int kt = 0; kt < 8; kt++) {
            uint32_t ah[4], al[4];
            ldmx4(ah, smb + qFrag + kt * 32);
            ldmx4(al, smb + OQL_E * 2 + qFrag + kt * 32);
            #pragma unroll
            for (int p = 0; p < 4; p++) {
                uint32_t bh[4], bl[4];
                const uint32_t ka = kB + p * (16 * KVST * 2) + kt * 32;
                ldmx4(bh, ka);
                ldmx4(bl, ka + SK_L * 2);
                mma16(s[2 * p],     ah, &bh[0]);
                mma16(s[2 * p],     al, &bh[0]);
                mma16(s[2 * p],     ah, &bl[0]);
                mma16(s[2 * p + 1], ah, &bh[2]);
                mma16(s[2 * p + 1], al, &bh[2]);
                mma16(s[2 * p + 1], ah, &bl[2]);
            }
        }

        const int row0 = m0 + wid * 16 + g;
        const int row1 = row0 + 8;
        if (j0 + FBN - 1 > row0) {
            #pragma unroll
            for (int n = 0; n < 8; n++) {
                int col = j0 + n * 8 + 2 * tg;
                if (col     > row0) s[n][0] = -1e30f;
                if (col + 1 > row0) s[n][1] = -1e30f;
                if (col     > row1) s[n][2] = -1e30f;
                if (col + 1 > row1) s[n][3] = -1e30f;
            }
        }

        float rmax0 = -1e30f, rmax1 = -1e30f;
        #pragma unroll
        for (int n = 0; n < 8; n++) {
            rmax0 = fmaxf(rmax0, fmaxf(s[n][0], s[n][1]));
            rmax1 = fmaxf(rmax1, fmaxf(s[n][2], s[n][3]));
        }
        rmax0 = fmaxf(rmax0, __shfl_xor_sync(0xffffffffu, rmax0, 1));
        rmax0 = fmaxf(rmax0, __shfl_xor_sync(0xffffffffu, rmax0, 2));
        rmax1 = fmaxf(rmax1, __shfl_xor_sync(0xffffffffu, rmax1, 1));
        rmax1 = fmaxf(rmax1, __shfl_xor_sync(0xffffffffu, rmax1, 2));

        float mn0 = fmaxf(m_0, rmax0), mn1 = fmaxf(m_1, rmax1);
        float f0 = __expf(m_0 - mn0), f1 = __expf(m_1 - mn1);
        m_0 = mn0; m_1 = mn1;

        float rs0 = 0.f, rs1 = 0.f;
        #pragma unroll
        for (int n = 0; n < 8; n++) {
            s[n][0] = __expf(s[n][0] - mn0);
            s[n][1] = __expf(s[n][1] - mn0);
            s[n][2] = __expf(s[n][2] - mn1);
            s[n][3] = __expf(s[n][3] - mn1);
            rs0 += s[n][0] + s[n][1];
            rs1 += s[n][2] + s[n][3];
        }
        rs0 += __shfl_xor_sync(0xffffffffu, rs0, 1);
        rs0 += __shfl_xor_sync(0xffffffffu, rs0, 2);
        rs1 += __shfl_xor_sync(0xffffffffu, rs1, 1);
        rs1 += __shfl_xor_sync(0xffffffffu, rs1, 2);
        l_0 = l_0 * f0 + rs0;
        l_1 = l_1 * f1 + rs1;

        #pragma unroll
        for (int n = 0; n < 16; n++) {
            o[n][0] *= f0; o[n][1] *= f0;
            o[n][2] *= f1; o[n][3] *= f1;
        }

        // O += P V  (fp16 2-term: (Ph+Pl) x Vf)
        #pragma unroll
        for (int kt = 0; kt < 4; kt++) {
            uint32_t ph[4], pl[4];
            split2h(s[2 * kt][0],     s[2 * kt][1],     ph[0], pl[0]);
            split2h(s[2 * kt][2],     s[2 * kt][3],     ph[1], pl[1]);
            split2h(s[2 * kt + 1][0], s[2 * kt + 1][1], ph[2], pl[2]);
            split2h(s[2 * kt + 1][2], s[2 * kt + 1][3], ph[3], pl[3]);
            #pragma unroll
            for (int p = 0; p < 8; p++) {
                uint32_t bh[4];
                const uint32_t va = vB + kt * (16 * KVST * 2) + p * 32;
                ldmx4t(bh, va);
                mma16h(o[2 * p],     ph, &bh[0]);
                mma16h(o[2 * p],     pl, &bh[0]);
                mma16h(o[2 * p + 1], ph, &bh[2]);
                mma16h(o[2 * p + 1], pl, &bh[2]);
            }
        }
        __syncthreads();
    }

    // epilogue: single fp16 output for the O-projection
    const float il0 = 1.0f / l_0;
    const float il1 = 1.0f / l_1;
    const int row0 = m0 + wid * 16 + g;
    #pragma unroll
    for (int n = 0; n < 16; n++) {
        const int col = n * 8 + 2 * tg;
        __half2 h0 = __floats2half2_rn(o[n][0] * il0, o[n][1] * il0);
        Oo[((size_t)row0 * Q_SIZE + h * HD + col) >> 1] = *(uint32_t*)&h0;
        __half2 h1 = __floats2half2_rn(o[n][2] * il1, o[n][3] * il1);
        Oo[((size_t)(row0 + 8) * Q_SIZE + h * HD + col) >> 1] = *(uint32_t*)&h1;
    }
}

// ---------------------------------------------------------------------------
extern "C" void kernel_launch(void* const* d_in, const int* in_sizes, int n_in,
                              void* d_out, int out_size)
{
    const int*   positions = (const int*)d_in[0];
    const float* hidden    = (const float*)d_in[1];
    const float* w_qkv     = (const float*)d_in[2];
    const float* w_o       = (const float*)d_in[3];
    float* out = (float*)d_out;

    uint32_t *hid, *wqkv, *wo;
    uint32_t *qh, *ql, *kh, *kl, *vf, *ao;
    cudaGetSymbolAddress((void**)&hid,  g_hid);
    cudaGetSymbolAddress((void**)&wqkv, g_wqkv);
    cudaGetSymbolAddress((void**)&wo,   g_wo);
    cudaGetSymbolAddress((void**)&qh, g_qh);
    cudaGetSymbolAddress((void**)&ql, g_ql);
    cudaGetSymbolAddress((void**)&kh, g_kh);
    cudaGetSymbolAddress((void**)&kl, g_kl);
    cudaGetSymbolAddress((void**)&vf, g_vf);
    cudaGetSymbolAddress((void**)&ao, g_ao);

    const int GSM = NSTG * STG_ELEMS * 2;   // 107520
    cudaFuncSetAttribute(gemm_qkv_fused,
                         cudaFuncAttributeMaxDynamicSharedMemorySize, GSM);
    cudaFuncSetAttribute(gemm_fp16,
                         cudaFuncAttributeMaxDynamicSharedMemorySize, GSM);
    cudaFuncSetAttribute(attn_tc2_kernel,
                         cudaFuncAttributeMaxDynamicSharedMemorySize,
                         ATT_SMEM_BYTES);

    // 0) conversions to fp16
    convert_h<<<2048, 256>>>((const float4*)hidden, (uint2*)hid,
                             T_SEQ * HIDDEN / 4);
    convert_h<<<4096, 256>>>((const float4*)w_qkv, (uint2*)wqkv,
                             HIDDEN * QKV_N / 4);
    convert_h<<<4096, 256>>>((const float4*)w_o, (uint2*)wo,
                             HIDDEN * HIDDEN / 4);

    // 1) QKV projection with fused RoPE + precision-split epilogue
    gemm_qkv_fused<<<dim3(QKV_N / 128, T_SEQ / 128), 128, GSM>>>(
        (const __half*)hid, (const __half*)wqkv, positions,
        qh, ql, kh, kl, vf);

    // 2) Flash attention (S: bf16x3, PV: fp16 2-term)
    attn_tc2_kernel<<<dim3(T_SEQ / FBM, NH), 256, ATT_SMEM_BYTES>>>(
        (const __nv_bfloat16*)qh, (const __nv_bfloat16*)ql,
        (const __nv_bfloat16*)kh, (const __nv_bfloat16*)kl,
        (const __half*)vf,
        ao);

    // 3) Output projection (fp16)
    gemm_fp16<<<dim3(HIDDEN / 128, T_SEQ / 128), 128, GSM>>>(
        (const __half*)ao, (const __half*)wo, out, T_SEQ, HIDDEN, HIDDEN);
}

// round 13
// speedup vs baseline: 14.6890x; 1.0149x over previous
#include <cuda_runtime.h>
#include <cuda_bf16.h>
#include <cuda_fp16.h>
#include <math.h>
#include <stdint.h>

#define T_SEQ  2048
#define HIDDEN 4096
#define NH     32
#define NKV    8
#define HD     128
#define Q_SIZE  (NH * HD)              // 4096
#define KV_SIZE (NKV * HD)             // 1024
#define QKV_N   (Q_SIZE + 2 * KV_SIZE) // 6144
#define SCALE   0.08838834764831845f   // 128^-0.5

// ---------------------------------------------------------------------------
// Global scratch. No cudaMalloc allowed.
// ---------------------------------------------------------------------------
__device__ uint32_t g_hid[(size_t)T_SEQ * HIDDEN / 2];         // fp16
__device__ uint32_t g_wqkv[(size_t)HIDDEN * QKV_N / 2];        // fp16
__device__ uint32_t g_wo[(size_t)HIDDEN * HIDDEN / 2];         // fp16
__device__ uint32_t g_qh[(size_t)T_SEQ * Q_SIZE / 2];          // bf16 (attn)
__device__ uint32_t g_ql[(size_t)T_SEQ * Q_SIZE / 2];
__device__ uint32_t g_kh[(size_t)T_SEQ * KV_SIZE / 2];
__device__ uint32_t g_kl[(size_t)T_SEQ * KV_SIZE / 2];
__device__ uint32_t g_vf[(size_t)T_SEQ * KV_SIZE / 2];         // fp16 V
__device__ uint32_t g_ao[(size_t)T_SEQ * Q_SIZE / 2];          // fp16 attn out
__device__ float2   g_rope[(size_t)T_SEQ * 64];                // (cos,sin)

// ---------------------------------------------------------------------------
// Helpers
// ---------------------------------------------------------------------------
__device__ __forceinline__ uint32_t smem_u32(const void* p) {
    uint32_t a;
    asm("{ .reg .u64 t; cvta.to.shared.u64 t, %1; cvt.u32.u64 %0, t; }"
        : "=r"(a) : "l"(p));
    return a;
}
// bf16 MMA (attention S path)
__device__ __forceinline__ void mma16(float* c, const uint32_t* a,
                                      const uint32_t* b) {
    asm volatile(
        "mma.sync.aligned.m16n8k16.row.col.f32.bf16.bf16.f32 "
        "{%0,%1,%2,%3}, {%4,%5,%6,%7}, {%8,%9}, {%0,%1,%2,%3};"
        : "+f"(c[0]), "+f"(c[1]), "+f"(c[2]), "+f"(c[3])
        : "r"(a[0]), "r"(a[1]), "r"(a[2]), "r"(a[3]), "r"(b[0]), "r"(b[1]));
}
// fp16 MMA (GEMMs + attention PV)
__device__ __forceinline__ void mma16h(float* c, const uint32_t* a,
                                       const uint32_t* b) {
    asm volatile(
        "mma.sync.aligned.m16n8k16.row.col.f32.f16.f16.f32 "
        "{%0,%1,%2,%3}, {%4,%5,%6,%7}, {%8,%9}, {%0,%1,%2,%3};"
        : "+f"(c[0]), "+f"(c[1]), "+f"(c[2]), "+f"(c[3])
        : "r"(a[0]), "r"(a[1]), "r"(a[2]), "r"(a[3]), "r"(b[0]), "r"(b[1]));
}
__device__ __forceinline__ void ldmx4(uint32_t* r, uint32_t addr) {
    asm volatile(
        "ldmatrix.sync.aligned.m8n8.x4.shared.b16 {%0,%1,%2,%3}, [%4];"
        : "=r"(r[0]), "=r"(r[1]), "=r"(r[2]), "=r"(r[3]) : "r"(addr));
}
__device__ __forceinline__ void ldmx4t(uint32_t* r, uint32_t addr) {
    asm volatile(
        "ldmatrix.sync.aligned.m8n8.x4.trans.shared.b16 {%0,%1,%2,%3}, [%4];"
        : "=r"(r[0]), "=r"(r[1]), "=r"(r[2]), "=r"(r[3]) : "r"(addr));
}
// bf16 hi/lo split
__device__ __forceinline__ void split2(float x, float y,
                                       uint32_t& hi, uint32_t& lo) {
    __nv_bfloat162 h = __floats2bfloat162_rn(x, y);
    float hx = __bfloat162float(h.x);
    float hy = __bfloat162float(h.y);
    __nv_bfloat162 l = __floats2bfloat162_rn(x - hx, y - hy);
    hi = *(uint32_t*)&h;
    lo = *(uint32_t*)&l;
}
// fp16 hi/lo split (P fragments)
__device__ __forceinline__ void split2h(float x, float y,
                                        uint32_t& hi, uint32_t& lo) {
    __half2 h = __floats2half2_rn(x, y);
    float hx = __half2float(__low2half(h));
    float hy = __half2float(__high2half(h));
    __half2 l = __floats2half2_rn(x - hx, y - hy);
    hi = *(uint32_t*)&h;
    lo = *(uint32_t*)&l;
}
__device__ __forceinline__ void cpa16(uint32_t dst, const void* src) {
    asm volatile("cp.async.cg.shared.global [%0], [%1], 16;"
                 :: "r"(dst), "l"(src));
}
__device__ __forceinline__ void cpa_commit() {
    asm volatile("cp.async.commit_group;");
}
template <int N>
__device__ __forceinline__ void cpa_wait() {
    asm volatile("cp.async.wait_group %0;" :: "n"(N));
}

// ---------------------------------------------------------------------------
// fp32 -> fp16 (single rounding)
// ---------------------------------------------------------------------------
__global__ __launch_bounds__(256) void convert_h(
    const float4* __restrict__ src, uint2* __restrict__ dh, int n4)
{
    for (int i = blockIdx.x * blockDim.x + threadIdx.x; i < n4;
         i += gridDim.x * blockDim.x) {
        float4 v = src[i];
        __half2 a = __floats2half2_rn(v.x, v.y);
        __half2 b = __floats2half2_rn(v.z, v.w);
        dh[i] = make_uint2(*(uint32_t*)&a, *(uint32_t*)&b);
    }
}

// ---------------------------------------------------------------------------
// RoPE cos/sin table: tab[t][i] = (cos, sin)(positions[t] * theta^(-2i/HD)).
// 131k sincosf total (vs 6.3M when fused raw into the GEMM epilogue).
// ---------------------------------------------------------------------------
__global__ __launch_bounds__(256) void rope_table_kernel(
    const int* __restrict__ positions, float2* __restrict__ tab)
{
    const int idx = blockIdx.x * blockDim.x + threadIdx.x;  // t*64 + i
    if (idx >= T_SEQ * 64) return;
    const int t = idx >> 6;
    const int i = idx & 63;
    double e = (double)(2 * i) / (double)HD;
    float invf = (float)pow(500000.0, -e);
    float s, c;
    sincosf((float)positions[t] * invf, &s, &c);
    tab[idx] = make_float2(c, s);
}

// ===========================================================================
// QKV GEMM with fused RoPE epilogue (table-driven).
// C = hid[M,K] @ wqkv[K,N]; cols <4096 -> rope+scale -> qh/ql (bf16),
// 4096..5119 -> rope -> kh/kl (bf16), >=5120 -> vf (fp16).
// CTA 128x128, 128 threads, 64x64 warp tiles, BK=64, 3-stage cp.async.
// ===========================================================================
#define GBK 64
#define AST 72
#define BST 136
#define STG_B   (128 * AST)     // 9216 elems
#define STG_ELEMS (128 * AST + GBK * BST)   // 17920 elems = 35840 B
#define NSTG 3

__global__ __launch_bounds__(128, 2) void gemm_qkv_fused(
    const __half* __restrict__ A, const __half* __restrict__ B,
    const float2* __restrict__ rope_tab,
    uint32_t* __restrict__ qh, uint32_t* __restrict__ ql,
    uint32_t* __restrict__ kh, uint32_t* __restrict__ kl,
    uint32_t* __restrict__ vf)
{
    extern __shared__ __align__(16) __half sm[];
    const uint32_t smb = smem_u32(sm);

    const int tid  = threadIdx.x;
    const int wid  = tid >> 5;
    const int lane = tid & 31;
    const int g    = lane >> 2;
    const int tg   = lane & 3;
    const int wm   = (wid >> 1) * 64;
    const int wn   = (wid & 1) * 64;
    const int m0 = blockIdx.y * 128;
    const int n0 = blockIdx.x * 128;
    const int K = HIDDEN, N = QKV_N;

    const int l7  = lane & 7;
    const int l8  = (lane >> 3) & 1;
    const int l16 = lane >> 4;
    const uint32_t aFrag = (uint32_t)(((wm + l7 + l8 * 8) * AST + l16 * 8) * 2);
    const uint32_t bFrag = (uint32_t)(STG_B * 2) +
        (uint32_t)(((l7 + l8 * 8) * BST + wn + l16 * 8) * 2);

    float acc[4][8][4];
    #pragma unroll
    for (int i = 0; i < 4; i++)
        #pragma unroll
        for (int j = 0; j < 8; j++)
            #pragma unroll
            for (int q = 0; q < 4; q++) acc[i][j][q] = 0.f;

    const int KT = K / GBK;

    auto issue = [&](int kt, int s) {
        const int kk = kt * GBK;
        const uint32_t sb = smb + (uint32_t)(s * STG_ELEMS * 2);
        #pragma unroll
        for (int i = 0; i < 8; i++) {
            const int c = tid + i * 128;
            const int row = c >> 3, c8 = (c & 7) * 8;
            cpa16(sb + (row * AST + c8) * 2,
                  A + (size_t)(m0 + row) * K + kk + c8);
        }
        #pragma unroll
        for (int i = 0; i < 8; i++) {
            const int c = tid + i * 128;
            const int row = c >> 4, c8 = (c & 15) * 8;
            cpa16(sb + (STG_B + row * BST + c8) * 2,
                  B + (size_t)(kk + row) * N + n0 + c8);
        }
    };

    issue(0, 0); cpa_commit();
    issue(1, 1); cpa_commit();

    int stage = 0;
    for (int kt = 0; kt < KT; kt++) {
        cpa_wait<1>();
        __syncthreads();

        if (kt + 2 < KT) {
            int s2 = stage + 2; if (s2 >= NSTG) s2 -= NSTG;
            issue(kt + 2, s2);
        }
        cpa_commit();

        const uint32_t sb = smb + (uint32_t)(stage * STG_ELEMS * 2);
        const uint32_t aA = sb + aFrag;
        const uint32_t bA = sb + bFrag;

        uint32_t aF[2][4][4];
        #pragma unroll
        for (int mt = 0; mt < 4; mt++)
            ldmx4(aF[0][mt], aA + mt * (16 * AST * 2));

        #pragma unroll
        for (int ks = 0; ks < 4; ks++) {
            const int cur = ks & 1;
            uint32_t bh[4][4];
            #pragma unroll
            for (int pp = 0; pp < 4; pp++)
                ldmx4t(bh[pp], bA + ks * (16 * BST * 2) + pp * 32);
            if (ks < 3) {
                #pragma unroll
                for (int mt = 0; mt < 4; mt++)
                    ldmx4(aF[cur ^ 1][mt],
                          aA + mt * (16 * AST * 2) + (ks + 1) * 32);
            }
            #pragma unroll
            for (int mt = 0; mt < 4; mt++)
                #pragma unroll
                for (int nt = 0; nt < 8; nt++)
                    mma16h(acc[mt][nt], aF[cur][mt],
                           &bh[nt >> 1][(nt & 1) * 2]);
        }
        if (++stage == NSTG) stage = 0;
    }

    // ---- fused epilogue: table-driven rope + precision split ----
    const int region = (n0 >= Q_SIZE + KV_SIZE) ? 2 : (n0 >= Q_SIZE ? 1 : 0);

    #pragma unroll
    for (int mt = 0; mt < 4; mt++) {
        const int rowA = m0 + wm + mt * 16 + g;
        const int rowB = rowA + 8;
        #pragma unroll
        for (int nt = 0; nt < 8; nt++) {
            const int col = n0 + wn + nt * 8 + tg * 2;
            const float x0a = acc[mt][nt][0], x1a = acc[mt][nt][1];
            const float x0b = acc[mt][nt][2], x1b = acc[mt][nt][3];
            if (region == 2) {
                const int c = col - (Q_SIZE + KV_SIZE);
                __half2 h0 = __floats2half2_rn(x0a, x1a);
                vf[((size_t)rowA * KV_SIZE + c) >> 1] = *(uint32_t*)&h0;
                __half2 h1 = __floats2half2_rn(x0b, x1b);
                vf[((size_t)rowB * KV_SIZE + c) >> 1] = *(uint32_t*)&h1;
            } else {
                const int fi = (col >> 1) & 63;
                const float2 ta = rope_tab[rowA * 64 + fi];
                const float2 tb = rope_tab[rowB * 64 + fi];
                float o1 = x0a * ta.x - x1a * ta.y;
                float o2 = x1a * ta.x + x0a * ta.y;
                float o3 = x0b * tb.x - x1b * tb.y;
                float o4 = x1b * tb.x + x0b * tb.y;
                uint32_t uh, ul;
                if (region == 0) {
                    split2(o1 * SCALE, o2 * SCALE, uh, ul);
                    size_t d = ((size_t)rowA * Q_SIZE + col) >> 1;
                    qh[d] = uh; ql[d] = ul;
                    split2(o3 * SCALE, o4 * SCALE, uh, ul);
                    d = ((size_t)rowB * Q_SIZE + col) >> 1;
                    qh[d] = uh; ql[d] = ul;
                } else {
                    const int c = col - Q_SIZE;
                    split2(o1, o2, uh, ul);
                    size_t d = ((size_t)rowA * KV_SIZE + c) >> 1;
                    kh[d] = uh; kl[d] = ul;
                    split2(o3, o4, uh, ul);
                    d = ((size_t)rowB * KV_SIZE + c) >> 1;
                    kh[d] = uh; kl[d] = ul;
                }
            }
        }
    }
}

// ---------------------------------------------------------------------------
// Pure FP16 GEMM (O-projection): C[M,N] = A[M,K] @ B[K,N], fp32 out.
// ---------------------------------------------------------------------------
__global__ __launch_bounds__(128, 2) void gemm_fp16(
    const __half* __restrict__ A, const __half* __restrict__ B,
    float* __restrict__ C, int M, int N, int K)
{
    extern __shared__ __align__(16) __half sm[];
    const uint32_t smb = smem_u32(sm);

    const int tid  = threadIdx.x;
    const int wid  = tid >> 5;
    const int lane = tid & 31;
    const int g    = lane >> 2;
    const int tg   = lane & 3;
    const int wm   = (wid >> 1) * 64;
    const int wn   = (wid & 1) * 64;
    const int m0 = blockIdx.y * 128;
    const int n0 = blockIdx.x * 128;

    const int l7  = lane & 7;
    const int l8  = (lane >> 3) & 1;
    const int l16 = lane >> 4;
    const uint32_t aFrag = (uint32_t)(((wm + l7 + l8 * 8) * AST + l16 * 8) * 2);
    const uint32_t bFrag = (uint32_t)(STG_B * 2) +
        (uint32_t)(((l7 + l8 * 8) * BST + wn + l16 * 8) * 2);

    float acc[4][8][4];
    #pragma unroll
    for (int i = 0; i < 4; i++)
        #pragma unroll
        for (int j = 0; j < 8; j++)
            #pragma unroll
            for (int q = 0; q < 4; q++) acc[i][j][q] = 0.f;

    const int KT = K / GBK;

    auto issue = [&](int kt, int s) {
        const int kk = kt * GBK;
        const uint32_t sb = smb + (uint32_t)(s * STG_ELEMS * 2);
        #pragma unroll
        for (int i = 0; i < 8; i++) {
            const int c = tid + i * 128;
            const int row = c >> 3, c8 = (c & 7) * 8;
            cpa16(sb + (row * AST + c8) * 2,
                  A + (size_t)(m0 + row) * K + kk + c8);
        }
        #pragma unroll
        for (int i = 0; i < 8; i++) {
            const int c = tid + i * 128;
            const int row = c >> 4, c8 = (c & 15) * 8;
            cpa16(sb + (STG_B + row * BST + c8) * 2,
                  B + (size_t)(kk + row) * N + n0 + c8);
        }
    };

    issue(0, 0); cpa_commit();
    issue(1, 1); cpa_commit();

    int stage = 0;
    for (int kt = 0; kt < KT; kt++) {
        cpa_wait<1>();
        __syncthreads();

        if (kt + 2 < KT) {
            int s2 = stage + 2; if (s2 >= NSTG) s2 -= NSTG;
            issue(kt + 2, s2);
        }
        cpa_commit();

        const uint32_t sb = smb + (uint32_t)(stage * STG_ELEMS * 2);
        const uint32_t aA = sb + aFrag;
        const uint32_t bA = sb + bFrag;

        uint32_t aF[2][4][4];
        #pragma unroll
        for (int mt = 0; mt < 4; mt++)
            ldmx4(aF[0][mt], aA + mt * (16 * AST * 2));

        #pragma unroll
        for (int ks = 0; ks < 4; ks++) {
            const int cur = ks & 1;
            uint32_t bh[4][4];
            #pragma unroll
            for (int pp = 0; pp < 4; pp++)
                ldmx4t(bh[pp], bA + ks * (16 * BST * 2) + pp * 32);
            if (ks < 3) {
                #pragma unroll
                for (int mt = 0; mt < 4; mt++)
                    ldmx4(aF[cur ^ 1][mt],
                          aA + mt * (16 * AST * 2) + (ks + 1) * 32);
            }
            #pragma unroll
            for (int mt = 0; mt < 4; mt++)
                #pragma unroll
                for (int nt = 0; nt < 8; nt++)
                    mma16h(acc[mt][nt], aF[cur][mt],
                           &bh[nt >> 1][(nt & 1) * 2]);
        }
        if (++stage == NSTG) stage = 0;
    }

    #pragma unroll
    for (int mt = 0; mt < 4; mt++) {
        const int row = m0 + wm + mt * 16 + g;
        #pragma unroll
        for (int nt = 0; nt < 8; nt++) {
            const int col = n0 + wn + nt * 8 + tg * 2;
            *(float2*)&C[(size_t)row * N + col] =
                make_float2(acc[mt][nt][0], acc[mt][nt][1]);
            *(float2*)&C[(size_t)(row + 8) * N + col] =
                make_float2(acc[mt][nt][2], acc[mt][nt][3]);
        }
    }
}

// ---------------------------------------------------------------------------
// Tensor-core causal GQA flash attention.
// S = QK^T: bf16x3 (proven). PV: fp16 2-term (Ph+Pl)*Vf.
// ---------------------------------------------------------------------------
#define FBM 128
#define FBN 64
#define KVST 136
#define OQL_E   17408
#define KVB_E   34816
#define KV_STG  26112                   // per stage: Kh, Kl, Vf
#define SK_L    8704
#define SV      17408
#define ATT_SMEM_BYTES ((KVB_E + 2 * KV_STG) * 2)   // 174080

__global__ __launch_bounds__(256, 1) void attn_tc2_kernel(
    const __nv_bfloat16* __restrict__ Qh, const __nv_bfloat16* __restrict__ Ql,
    const __nv_bfloat16* __restrict__ Kh, const __nv_bfloat16* __restrict__ Kl,
    const __half* __restrict__ Vf,
    uint32_t* __restrict__ Oo)
{
    extern __shared__ __align__(16) __nv_bfloat16 asmem[];
    const uint32_t smb = smem_u32(asmem);

    const int tid  = threadIdx.x;
    const int wid  = tid >> 5;
    const int lane = tid & 31;
    const int g    = lane >> 2;
    const int tg   = lane & 3;
    const int mt   = (gridDim.x - 1) - blockIdx.x;
    const int m0   = mt * FBM;
    const int h    = blockIdx.y;
    const int kh   = h >> 2;

    const int l7  = lane & 7;
    const int l8  = (lane >> 3) & 1;
    const int l16 = lane >> 4;

    const int lr = tid >> 4;
    const int lc = tid & 15;

    #pragma unroll
    for (int i = 0; i < 8; i++) {
        const int row = lr + i * 16;
        const size_t go = (size_t)(m0 + row) * Q_SIZE + h * HD + lc * 8;
        cpa16(smb + (row * KVST + lc * 8) * 2, Qh + go);
        cpa16(smb + (OQL_E + row * KVST + lc * 8) * 2, Ql + go);
    }
    cpa_commit();

    auto issueKV = [&](int j0, int s) {
        const uint32_t sb = smb + (uint32_t)((KVB_E + s * KV_STG) * 2);
        #pragma unroll
        for (int i = 0; i < 4; i++) {
            const int row = lr + i * 16;
            const size_t go = (size_t)(j0 + row) * KV_SIZE + kh * HD + lc * 8;
            const uint32_t so = (row * KVST + lc * 8) * 2;
            cpa16(sb + so, Kh + go);
            cpa16(sb + SK_L * 2 + so, Kl + go);
            cpa16(sb + SV * 2 + so, Vf + go);
        }
    };

    issueKV(0, 0);
    cpa_commit();

    float o[16][4];
    #pragma unroll
    for (int n = 0; n < 16; n++)
        #pragma unroll
        for (int q = 0; q < 4; q++) o[n][q] = 0.f;
    float m_0 = -1e30f, m_1 = -1e30f, l_0 = 0.f, l_1 = 0.f;

    const uint32_t qFrag =
        (uint32_t)(((wid * 16 + l7 + l8 * 8) * KVST + l16 * 8) * 2);
    const uint32_t kFrag =
        (uint32_t)(((l7 + l16 * 8) * KVST + l8 * 8) * 2);
    const uint32_t vFrag =
        (uint32_t)(((l7 + l8 * 8) * KVST + l16 * 8) * 2);

    const int ntiles = m0 / FBN + 2;

    for (int jt = 0; jt < ntiles; jt++) {
        if (jt + 1 < ntiles) issueKV((jt + 1) * FBN, (jt + 1) & 1);
        cpa_commit();
        cpa_wait<1>();
        __syncthreads();

        const int j0 = jt * FBN;
        const uint32_t sb = smb + (uint32_t)((KVB_E + (jt & 1) * KV_STG) * 2);
        const uint32_t kB = sb + kFrag;
        const uint32_t vB = sb + SV * 2 + vFrag;

        float s[8][4];
        #pragma unroll
        for (int n = 0; n < 8; n++)
            #pragma unroll
            for (int q = 0; q < 4; q++) s[n][q] = 0.f;

        #pragma unroll
        for (int kt = 0; kt < 8; kt++) {
            uint32_t ah[4], al[4];
            ldmx4(ah, smb + qFrag + kt * 32);
            ldmx4(al, smb + OQL_E * 2 + qFrag + kt * 32);
            #pragma unroll
            for (int p = 0; p < 4; p++) {
                uint32_t bh[4], bl[4];
                const uint32_t ka = kB + p * (16 * KVST * 2) + kt * 32;
                ldmx4(bh, ka);
                ldmx4(bl, ka + SK_L * 2);
                mma16(s[2 * p],     ah, &bh[0]);
                mma16(s[2 * p],     al, &bh[0]);
                mma16(s[2 * p],     ah, &bl[0]);
                mma16(s[2 * p + 1], ah, &bh[2]);
                mma16(s[2 * p + 1], al, &bh[2]);
                mma16(s[2 * p + 1], ah, &bl[2]);
            }
        }

        const int row0 = m0 + wid * 16 + g;
        const int row1 = row0 + 8;
        if (j0 + FBN - 1 > row0) {
            #pragma unroll
            for (int n = 0; n < 8; n++) {
                int col = j0 + n * 8 + 2 * tg;
                if (col     > row0) s[n][0] = -1e30f;
                if (col + 1 > row0) s[n][1] = -1e30f;
                if (col     > row1) s[n][2] = -1e30f;
                if (col + 1 > row1) s[n][3] = -1e30f;
            }
        }

        float rmax0 = -1e30f, rmax1 = -1e30f;
        #pragma unroll
        for (int n = 0; n < 8; n++) {
            rmax0 = fmaxf(rmax0, fmaxf(s[n][0], s[n][1]));
            rmax1 = fmaxf(rmax1, fmaxf(s[n][2], s[n][3]));
        }
        rmax0 = fmaxf(rmax0, __shfl_xor_sync(0xffffffffu, rmax0, 1));
        rmax0 = fmaxf(rmax0, __shfl_xor_sync(0xffffffffu, rmax0, 2));
        rmax1 = fmaxf(rmax1, __shfl_xor_sync(0xffffffffu, rmax1, 1));
        rmax1 = fmaxf(rmax1, __shfl_xor_sync(0xffffffffu, rmax1, 2));

        float mn0 = fmaxf(m_0, rmax0), mn1 = fmaxf(m_1, rmax1);
        float f0 = __expf(m_0 - mn0), f1 = __expf(m_1 - mn1);
        m_0 = mn0; m_1 = mn1;

        float rs0 = 0.f, rs1 = 0.f;
        #pragma unroll
        for (int n = 0; n < 8; n++) {
            s[n][0] = __expf(s[n][0] - mn0);
            s[n][1] = __expf(s[n][1] - mn0);
            s[n][2] = __expf(s[n][2] - mn1);
            s[n][3] = __expf(s[n][3] - mn1);
            rs0 += s[n][0] + s[n][1];
            rs1 += s[n][2] + s[n][3];
        }
        rs0 += __shfl_xor_sync(0xffffffffu, rs0, 1);
        rs0 += __shfl_xor_sync(0xffffffffu, rs0, 2);
        rs1 += __shfl_xor_sync(0xffffffffu, rs1, 1);
        rs1 += __shfl_xor_sync(0xffffffffu, rs1, 2);
        l_0 = l_0 * f0 + rs0;
        l_1 = l_1 * f1 + rs1;

        #pragma unroll
        for (int n = 0; n < 16; n++) {
            o[n][0] *= f0; o[n][1] *= f0;
            o[n][2] *= f1; o[n][3] *= f1;
        }

        // O += P V  (fp16 2-term: (Ph+Pl) x Vf)
        #pragma unroll
        for (int kt = 0; kt < 4; kt++) {
            uint32_t ph[4], pl[4];
            split2h(s[2 * kt][0],     s[2 * kt][1],     ph[0], pl[0]);
            split2h(s[2 * kt][2],     s[2 * kt][3],     ph[1], pl[1]);
            split2h(s[2 * kt + 1][0], s[2 * kt + 1][1], ph[2], pl[2]);
            split2h(s[2 * kt + 1][2], s[2 * kt + 1][3], ph[3], pl[3]);
            #pragma unroll
            for (int p = 0; p < 8; p++) {
                uint32_t bh[4];
                const uint32_t va = vB + kt * (16 * KVST * 2) + p * 32;
                ldmx4t(bh, va);
                mma16h(o[2 * p],     ph, &bh[0]);
                mma16h(o[2 * p],     pl, &bh[0]);
                mma16h(o[2 * p + 1], ph, &bh[2]);
                mma16h(o[2 * p + 1], pl, &bh[2]);
            }
        }
        __syncthreads();
    }

    // epilogue: single fp16 output for the O-projection
    const float il0 = 1.0f / l_0;
    const float il1 = 1.0f / l_1;
    const int row0 = m0 + wid * 16 + g;
    #pragma unroll
    for (int n = 0; n < 16; n++) {
        const int col = n * 8 + 2 * tg;
        __half2 h0 = __floats2half2_rn(o[n][0] * il0, o[n][1] * il0);
        Oo[((size_t)row0 * Q_SIZE + h * HD + col) >> 1] = *(uint32_t*)&h0;
        __half2 h1 = __floats2half2_rn(o[n][2] * il1, o[n][3] * il1);
        Oo[((size_t)(row0 + 8) * Q_SIZE + h * HD + col) >> 1] = *(uint32_t*)&h1;
    }
}

// ---------------------------------------------------------------------------
extern "C" void kernel_launch(void* const* d_in, const int* in_sizes, int n_in,
                              void* d_out, int out_size)
{
    const int*   positions = (const int*)d_in[0];
    const float* hidden    = (const float*)d_in[1];
    const float* w_qkv     = (const float*)d_in[2];
    const float* w_o       = (const float*)d_in[3];
    float* out = (float*)d_out;

    uint32_t *hid, *wqkv, *wo;
    uint32_t *qh, *ql, *kh, *kl, *vf, *ao;
    float2* rope_tab;
    cudaGetSymbolAddress((void**)&hid,  g_hid);
    cudaGetSymbolAddress((void**)&wqkv, g_wqkv);
    cudaGetSymbolAddress((void**)&wo,   g_wo);
    cudaGetSymbolAddress((void**)&qh, g_qh);
    cudaGetSymbolAddress((void**)&ql, g_ql);
    cudaGetSymbolAddress((void**)&kh, g_kh);
    cudaGetSymbolAddress((void**)&kl, g_kl);
    cudaGetSymbolAddress((void**)&vf, g_vf);
    cudaGetSymbolAddress((void**)&ao, g_ao);
    cudaGetSymbolAddress((void**)&rope_tab, g_rope);

    const int GSM = NSTG * STG_ELEMS * 2;   // 107520
    cudaFuncSetAttribute(gemm_qkv_fused,
                         cudaFuncAttributeMaxDynamicSharedMemorySize, GSM);
    cudaFuncSetAttribute(gemm_fp16,
                         cudaFuncAttributeMaxDynamicSharedMemorySize, GSM);
    cudaFuncSetAttribute(attn_tc2_kernel,
                         cudaFuncAttributeMaxDynamicSharedMemorySize,
                         ATT_SMEM_BYTES);

    // 0) conversions + rope table
    rope_table_kernel<<<(T_SEQ * 64 + 255) / 256, 256>>>(positions, rope_tab);
    convert_h<<<2048, 256>>>((const float4*)hidden, (uint2*)hid,
                             T_SEQ * HIDDEN / 4);
    convert_h<<<4096, 256>>>((const float4*)w_qkv, (uint2*)wqkv,
                             HIDDEN * QKV_N / 4);
    convert_h<<<4096, 256>>>((const float4*)w_o, (uint2*)wo,
                             HIDDEN * HIDDEN / 4);

    // 1) QKV projection with fused (table-driven) RoPE epilogue
    gemm_qkv_fused<<<dim3(QKV_N / 128, T_SEQ / 128), 128, GSM>>>(
        (const __half*)hid, (const __half*)wqkv, rope_tab,
        qh, ql, kh, kl, vf);

    // 2) Flash attention (S: bf16x3, PV: fp16 2-term)
    attn_tc2_kernel<<<dim3(T_SEQ / FBM, NH), 256, ATT_SMEM_BYTES>>>(
        (const __nv_bfloat16*)qh, (const __nv_bfloat16*)ql,
        (const __nv_bfloat16*)kh, (const __nv_bfloat16*)kl,
        (const __half*)vf,
        ao);

    // 3) Output projection (fp16)
    gemm_fp16<<<dim3(HIDDEN / 128, T_SEQ / 128), 128, GSM>>>(
        (const __half*)ao, (const __half*)wo, out, T_SEQ, HIDDEN, HIDDEN);
}

// round 14
// speedup vs baseline: 15.6877x; 1.0680x over previous
#include <cuda_runtime.h>
#include <cuda_bf16.h>
#include <cuda_fp16.h>
#include <math.h>
#include <stdint.h>

#define T_SEQ  2048
#define HIDDEN 4096
#define NH     32
#define NKV    8
#define HD     128
#define Q_SIZE  (NH * HD)              // 4096
#define KV_SIZE (NKV * HD)             // 1024
#define QKV_N   (Q_SIZE + 2 * KV_SIZE) // 6144
#define SCALE   0.08838834764831845f   // 128^-0.5

// ---------------------------------------------------------------------------
// Global scratch. No cudaMalloc allowed.
// ---------------------------------------------------------------------------
__device__ uint32_t g_hid[(size_t)T_SEQ * HIDDEN / 2];         // fp16
__device__ uint32_t g_wqkv[(size_t)HIDDEN * QKV_N / 2];        // fp16
__device__ uint32_t g_wo[(size_t)HIDDEN * HIDDEN / 2];         // fp16
__device__ uint32_t g_qh[(size_t)T_SEQ * Q_SIZE / 2];          // fp16 Q hi
__device__ uint32_t g_ql[(size_t)T_SEQ * Q_SIZE / 2];          // fp16 Q lo
__device__ uint32_t g_kf[(size_t)T_SEQ * KV_SIZE / 2];         // fp16 K
__device__ uint32_t g_vf[(size_t)T_SEQ * KV_SIZE / 2];         // fp16 V
__device__ uint32_t g_ao[(size_t)T_SEQ * Q_SIZE / 2];          // fp16 attn out
__device__ float2   g_rope[(size_t)T_SEQ * 64];                // (cos,sin)

// ---------------------------------------------------------------------------
// Helpers
// ---------------------------------------------------------------------------
__device__ __forceinline__ uint32_t smem_u32(const void* p) {
    uint32_t a;
    asm("{ .reg .u64 t; cvta.to.shared.u64 t, %1; cvt.u32.u64 %0, t; }"
        : "=r"(a) : "l"(p));
    return a;
}
// fp16 MMA (everything)
__device__ __forceinline__ void mma16h(float* c, const uint32_t* a,
                                       const uint32_t* b) {
    asm volatile(
        "mma.sync.aligned.m16n8k16.row.col.f32.f16.f16.f32 "
        "{%0,%1,%2,%3}, {%4,%5,%6,%7}, {%8,%9}, {%0,%1,%2,%3};"
        : "+f"(c[0]), "+f"(c[1]), "+f"(c[2]), "+f"(c[3])
        : "r"(a[0]), "r"(a[1]), "r"(a[2]), "r"(a[3]), "r"(b[0]), "r"(b[1]));
}
__device__ __forceinline__ void ldmx4(uint32_t* r, uint32_t addr) {
    asm volatile(
        "ldmatrix.sync.aligned.m8n8.x4.shared.b16 {%0,%1,%2,%3}, [%4];"
        : "=r"(r[0]), "=r"(r[1]), "=r"(r[2]), "=r"(r[3]) : "r"(addr));
}
__device__ __forceinline__ void ldmx4t(uint32_t* r, uint32_t addr) {
    asm volatile(
        "ldmatrix.sync.aligned.m8n8.x4.trans.shared.b16 {%0,%1,%2,%3}, [%4];"
        : "=r"(r[0]), "=r"(r[1]), "=r"(r[2]), "=r"(r[3]) : "r"(addr));
}
// fp16 hi/lo split
__device__ __forceinline__ void split2h(float x, float y,
                                        uint32_t& hi, uint32_t& lo) {
    __half2 h = __floats2half2_rn(x, y);
    float hx = __half2float(__low2half(h));
    float hy = __half2float(__high2half(h));
    __half2 l = __floats2half2_rn(x - hx, y - hy);
    hi = *(uint32_t*)&h;
    lo = *(uint32_t*)&l;
}
__device__ __forceinline__ void cpa16(uint32_t dst, const void* src) {
    asm volatile("cp.async.cg.shared.global [%0], [%1], 16;"
                 :: "r"(dst), "l"(src));
}
__device__ __forceinline__ void cpa_commit() {
    asm volatile("cp.async.commit_group;");
}
template <int N>
__device__ __forceinline__ void cpa_wait() {
    asm volatile("cp.async.wait_group %0;" :: "n"(N));
}

// ---------------------------------------------------------------------------
// fp32 -> fp16 (single rounding)
// ---------------------------------------------------------------------------
__global__ __launch_bounds__(256) void convert_h(
    const float4* __restrict__ src, uint2* __restrict__ dh, int n4)
{
    for (int i = blockIdx.x * blockDim.x + threadIdx.x; i < n4;
         i += gridDim.x * blockDim.x) {
        float4 v = src[i];
        __half2 a = __floats2half2_rn(v.x, v.y);
        __half2 b = __floats2half2_rn(v.z, v.w);
        dh[i] = make_uint2(*(uint32_t*)&a, *(uint32_t*)&b);
    }
}

// ---------------------------------------------------------------------------
// RoPE cos/sin table
// ---------------------------------------------------------------------------
__global__ __launch_bounds__(256) void rope_table_kernel(
    const int* __restrict__ positions, float2* __restrict__ tab)
{
    const int idx = blockIdx.x * blockDim.x + threadIdx.x;
    if (idx >= T_SEQ * 64) return;
    const int t = idx >> 6;
    const int i = idx & 63;
    double e = (double)(2 * i) / (double)HD;
    float invf = (float)pow(500000.0, -e);
    float s, c;
    sincosf((float)positions[t] * invf, &s, &c);
    tab[idx] = make_float2(c, s);
}

// ===========================================================================
// QKV GEMM with fused RoPE epilogue (table-driven).
// cols <4096 -> rope+scale -> qh/ql (fp16 hi/lo);
// 4096..5119 -> rope -> kf (fp16 single); >=5120 -> vf (fp16 single).
// ===========================================================================
#define GBK 64
#define AST 72
#define BST 136
#define STG_B   (128 * AST)     // 9216 elems
#define STG_ELEMS (128 * AST + GBK * BST)   // 17920 elems = 35840 B
#define NSTG 3

__global__ __launch_bounds__(128, 2) void gemm_qkv_fused(
    const __half* __restrict__ A, const __half* __restrict__ B,
    const float2* __restrict__ rope_tab,
    uint32_t* __restrict__ qh, uint32_t* __restrict__ ql,
    uint32_t* __restrict__ kf, uint32_t* __restrict__ vf)
{
    extern __shared__ __align__(16) __half sm[];
    const uint32_t smb = smem_u32(sm);

    const int tid  = threadIdx.x;
    const int wid  = tid >> 5;
    const int lane = tid & 31;
    const int g    = lane >> 2;
    const int tg   = lane & 3;
    const int wm   = (wid >> 1) * 64;
    const int wn   = (wid & 1) * 64;
    const int m0 = blockIdx.y * 128;
    const int n0 = blockIdx.x * 128;
    const int K = HIDDEN, N = QKV_N;

    const int l7  = lane & 7;
    const int l8  = (lane >> 3) & 1;
    const int l16 = lane >> 4;
    const uint32_t aFrag = (uint32_t)(((wm + l7 + l8 * 8) * AST + l16 * 8) * 2);
    const uint32_t bFrag = (uint32_t)(STG_B * 2) +
        (uint32_t)(((l7 + l8 * 8) * BST + wn + l16 * 8) * 2);

    float acc[4][8][4];
    #pragma unroll
    for (int i = 0; i < 4; i++)
        #pragma unroll
        for (int j = 0; j < 8; j++)
            #pragma unroll
            for (int q = 0; q < 4; q++) acc[i][j][q] = 0.f;

    const int KT = K / GBK;

    auto issue = [&](int kt, int s) {
        const int kk = kt * GBK;
        const uint32_t sb = smb + (uint32_t)(s * STG_ELEMS * 2);
        #pragma unroll
        for (int i = 0; i < 8; i++) {
            const int c = tid + i * 128;
            const int row = c >> 3, c8 = (c & 7) * 8;
            cpa16(sb + (row * AST + c8) * 2,
                  A + (size_t)(m0 + row) * K + kk + c8);
        }
        #pragma unroll
        for (int i = 0; i < 8; i++) {
            const int c = tid + i * 128;
            const int row = c >> 4, c8 = (c & 15) * 8;
            cpa16(sb + (STG_B + row * BST + c8) * 2,
                  B + (size_t)(kk + row) * N + n0 + c8);
        }
    };

    issue(0, 0); cpa_commit();
    issue(1, 1); cpa_commit();

    int stage = 0;
    for (int kt = 0; kt < KT; kt++) {
        cpa_wait<1>();
        __syncthreads();

        if (kt + 2 < KT) {
            int s2 = stage + 2; if (s2 >= NSTG) s2 -= NSTG;
            issue(kt + 2, s2);
        }
        cpa_commit();

        const uint32_t sb = smb + (uint32_t)(stage * STG_ELEMS * 2);
        const uint32_t aA = sb + aFrag;
        const uint32_t bA = sb + bFrag;

        uint32_t aF[2][4][4];
        #pragma unroll
        for (int mt = 0; mt < 4; mt++)
            ldmx4(aF[0][mt], aA + mt * (16 * AST * 2));

        #pragma unroll
        for (int ks = 0; ks < 4; ks++) {
            const int cur = ks & 1;
            uint32_t bh[4][4];
            #pragma unroll
            for (int pp = 0; pp < 4; pp++)
                ldmx4t(bh[pp], bA + ks * (16 * BST * 2) + pp * 32);
            if (ks < 3) {
                #pragma unroll
                for (int mt = 0; mt < 4; mt++)
                    ldmx4(aF[cur ^ 1][mt],
                          aA + mt * (16 * AST * 2) + (ks + 1) * 32);
            }
            #pragma unroll
            for (int mt = 0; mt < 4; mt++)
                #pragma unroll
                for (int nt = 0; nt < 8; nt++)
                    mma16h(acc[mt][nt], aF[cur][mt],
                           &bh[nt >> 1][(nt & 1) * 2]);
        }
        if (++stage == NSTG) stage = 0;
    }

    // ---- fused epilogue: table-driven rope + precision split ----
    const int region = (n0 >= Q_SIZE + KV_SIZE) ? 2 : (n0 >= Q_SIZE ? 1 : 0);

    #pragma unroll
    for (int mt = 0; mt < 4; mt++) {
        const int rowA = m0 + wm + mt * 16 + g;
        const int rowB = rowA + 8;
        #pragma unroll
        for (int nt = 0; nt < 8; nt++) {
            const int col = n0 + wn + nt * 8 + tg * 2;
            const float x0a = acc[mt][nt][0], x1a = acc[mt][nt][1];
            const float x0b = acc[mt][nt][2], x1b = acc[mt][nt][3];
            if (region == 2) {
                const int c = col - (Q_SIZE + KV_SIZE);
                __half2 h0 = __floats2half2_rn(x0a, x1a);
                vf[((size_t)rowA * KV_SIZE + c) >> 1] = *(uint32_t*)&h0;
                __half2 h1 = __floats2half2_rn(x0b, x1b);
                vf[((size_t)rowB * KV_SIZE + c) >> 1] = *(uint32_t*)&h1;
            } else {
                const int fi = (col >> 1) & 63;
                const float2 ta = rope_tab[rowA * 64 + fi];
                const float2 tb = rope_tab[rowB * 64 + fi];
                float o1 = x0a * ta.x - x1a * ta.y;
                float o2 = x1a * ta.x + x0a * ta.y;
                float o3 = x0b * tb.x - x1b * tb.y;
                float o4 = x1b * tb.x + x0b * tb.y;
                if (region == 0) {
                    uint32_t uh, ul;
                    split2h(o1 * SCALE, o2 * SCALE, uh, ul);
                    size_t d = ((size_t)rowA * Q_SIZE + col) >> 1;
                    qh[d] = uh; ql[d] = ul;
                    split2h(o3 * SCALE, o4 * SCALE, uh, ul);
                    d = ((size_t)rowB * Q_SIZE + col) >> 1;
                    qh[d] = uh; ql[d] = ul;
                } else {
                    const int c = col - Q_SIZE;
                    __half2 h0 = __floats2half2_rn(o1, o2);
                    kf[((size_t)rowA * KV_SIZE + c) >> 1] = *(uint32_t*)&h0;
                    __half2 h1 = __floats2half2_rn(o3, o4);
                    kf[((size_t)rowB * KV_SIZE + c) >> 1] = *(uint32_t*)&h1;
                }
            }
        }
    }
}

// ---------------------------------------------------------------------------
// Pure FP16 GEMM (O-projection): C[M,N] = A[M,K] @ B[K,N], fp32 out.
// ---------------------------------------------------------------------------
__global__ __launch_bounds__(128, 2) void gemm_fp16(
    const __half* __restrict__ A, const __half* __restrict__ B,
    float* __restrict__ C, int M, int N, int K)
{
    extern __shared__ __align__(16) __half sm[];
    const uint32_t smb = smem_u32(sm);

    const int tid  = threadIdx.x;
    const int wid  = tid >> 5;
    const int lane = tid & 31;
    const int g    = lane >> 2;
    const int tg   = lane & 3;
    const int wm   = (wid >> 1) * 64;
    const int wn   = (wid & 1) * 64;
    const int m0 = blockIdx.y * 128;
    const int n0 = blockIdx.x * 128;

    const int l7  = lane & 7;
    const int l8  = (lane >> 3) & 1;
    const int l16 = lane >> 4;
    const uint32_t aFrag = (uint32_t)(((wm + l7 + l8 * 8) * AST + l16 * 8) * 2);
    const uint32_t bFrag = (uint32_t)(STG_B * 2) +
        (uint32_t)(((l7 + l8 * 8) * BST + wn + l16 * 8) * 2);

    float acc[4][8][4];
    #pragma unroll
    for (int i = 0; i < 4; i++)
        #pragma unroll
        for (int j = 0; j < 8; j++)
            #pragma unroll
            for (int q = 0; q < 4; q++) acc[i][j][q] = 0.f;

    const int KT = K / GBK;

    auto issue = [&](int kt, int s) {
        const int kk = kt * GBK;
        const uint32_t sb = smb + (uint32_t)(s * STG_ELEMS * 2);
        #pragma unroll
        for (int i = 0; i < 8; i++) {
            const int c = tid + i * 128;
            const int row = c >> 3, c8 = (c & 7) * 8;
            cpa16(sb + (row * AST + c8) * 2,
                  A + (size_t)(m0 + row) * K + kk + c8);
        }
        #pragma unroll
        for (int i = 0; i < 8; i++) {
            const int c = tid + i * 128;
            const int row = c >> 4, c8 = (c & 15) * 8;
            cpa16(sb + (STG_B + row * BST + c8) * 2,
                  B + (size_t)(kk + row) * N + n0 + c8);
        }
    };

    issue(0, 0); cpa_commit();
    issue(1, 1); cpa_commit();

    int stage = 0;
    for (int kt = 0; kt < KT; kt++) {
        cpa_wait<1>();
        __syncthreads();

        if (kt + 2 < KT) {
            int s2 = stage + 2; if (s2 >= NSTG) s2 -= NSTG;
            issue(kt + 2, s2);
        }
        cpa_commit();

        const uint32_t sb = smb + (uint32_t)(stage * STG_ELEMS * 2);
        const uint32_t aA = sb + aFrag;
        const uint32_t bA = sb + bFrag;

        uint32_t aF[2][4][4];
        #pragma unroll
        for (int mt = 0; mt < 4; mt++)
            ldmx4(aF[0][mt], aA + mt * (16 * AST * 2));

        #pragma unroll
        for (int ks = 0; ks < 4; ks++) {
            const int cur = ks & 1;
            uint32_t bh[4][4];
            #pragma unroll
            for (int pp = 0; pp < 4; pp++)
                ldmx4t(bh[pp], bA + ks * (16 * BST * 2) + pp * 32);
            if (ks < 3) {
                #pragma unroll
                for (int mt = 0; mt < 4; mt++)
                    ldmx4(aF[cur ^ 1][mt],
                          aA + mt * (16 * AST * 2) + (ks + 1) * 32);
            }
            #pragma unroll
            for (int mt = 0; mt < 4; mt++)
                #pragma unroll
                for (int nt = 0; nt < 8; nt++)
                    mma16h(acc[mt][nt], aF[cur][mt],
                           &bh[nt >> 1][(nt & 1) * 2]);
        }
        if (++stage == NSTG) stage = 0;
    }

    #pragma unroll
    for (int mt = 0; mt < 4; mt++) {
        const int row = m0 + wm + mt * 16 + g;
        #pragma unroll
        for (int nt = 0; nt < 8; nt++) {
            const int col = n0 + wn + nt * 8 + tg * 2;
            *(float2*)&C[(size_t)row * N + col] =
                make_float2(acc[mt][nt][0], acc[mt][nt][1]);
            *(float2*)&C[(size_t)(row + 8) * N + col] =
                make_float2(acc[mt][nt][2], acc[mt][nt][3]);
        }
    }
}

// ---------------------------------------------------------------------------
// Tensor-core causal GQA flash attention — all fp16.
// S = (Qh+Ql) K^T (2-term). PV = (Ph+Pl) V (2-term).
// ---------------------------------------------------------------------------
#define FBM 128
#define FBN 64
#define KVST 136
#define OQL_E   17408
#define KVB_E   34816
#define KV_STG  17408                   // per stage: Kf, Vf
#define SV      8704
#define ATT_SMEM_BYTES ((KVB_E + 2 * KV_STG) * 2)   // 139264

__global__ __launch_bounds__(256, 1) void attn_tc2_kernel(
    const __half* __restrict__ Qh, const __half* __restrict__ Ql,
    const __half* __restrict__ Kf, const __half* __restrict__ Vf,
    uint32_t* __restrict__ Oo)
{
    extern __shared__ __align__(16) __half asmem[];
    const uint32_t smb = smem_u32(asmem);

    const int tid  = threadIdx.x;
    const int wid  = tid >> 5;
    const int lane = tid & 31;
    const int g    = lane >> 2;
    const int tg   = lane & 3;
    const int mt   = (gridDim.x - 1) - blockIdx.x;
    const int m0   = mt * FBM;
    const int h    = blockIdx.y;
    const int kh   = h >> 2;

    const int l7  = lane & 7;
    const int l8  = (lane >> 3) & 1;
    const int l16 = lane >> 4;

    const int lr = tid >> 4;
    const int lc = tid & 15;

    #pragma unroll
    for (int i = 0; i < 8; i++) {
        const int row = lr + i * 16;
        const size_t go = (size_t)(m0 + row) * Q_SIZE + h * HD + lc * 8;
        cpa16(smb + (row * KVST + lc * 8) * 2, Qh + go);
        cpa16(smb + (OQL_E + row * KVST + lc * 8) * 2, Ql + go);
    }
    cpa_commit();

    auto issueKV = [&](int j0, int s) {
        const uint32_t sb = smb + (uint32_t)((KVB_E + s * KV_STG) * 2);
        #pragma unroll
        for (int i = 0; i < 4; i++) {
            const int row = lr + i * 16;
            const size_t go = (size_t)(j0 + row) * KV_SIZE + kh * HD + lc * 8;
            const uint32_t so = (row * KVST + lc * 8) * 2;
            cpa16(sb + so, Kf + go);
            cpa16(sb + SV * 2 + so, Vf + go);
        }
    };

    issueKV(0, 0);
    cpa_commit();

    float o[16][4];
    #pragma unroll
    for (int n = 0; n < 16; n++)
        #pragma unroll
        for (int q = 0; q < 4; q++) o[n][q] = 0.f;
    float m_0 = -1e30f, m_1 = -1e30f, l_0 = 0.f, l_1 = 0.f;

    const uint32_t qFrag =
        (uint32_t)(((wid * 16 + l7 + l8 * 8) * KVST + l16 * 8) * 2);
    const uint32_t kFrag =
        (uint32_t)(((l7 + l16 * 8) * KVST + l8 * 8) * 2);
    const uint32_t vFrag =
        (uint32_t)(((l7 + l8 * 8) * KVST + l16 * 8) * 2);

    const int ntiles = m0 / FBN + 2;

    for (int jt = 0; jt < ntiles; jt++) {
        if (jt + 1 < ntiles) issueKV((jt + 1) * FBN, (jt + 1) & 1);
        cpa_commit();
        cpa_wait<1>();
        __syncthreads();

        const int j0 = jt * FBN;
        const uint32_t sb = smb + (uint32_t)((KVB_E + (jt & 1) * KV_STG) * 2);
        const uint32_t kB = sb + kFrag;
        const uint32_t vB = sb + SV * 2 + vFrag;

        float s[8][4];
        #pragma unroll
        for (int n = 0; n < 8; n++)
            #pragma unroll
            for (int q = 0; q < 4; q++) s[n][q] = 0.f;

        #pragma unroll
        for (int kt = 0; kt < 8; kt++) {
            uint32_t ah[4], al[4];
            ldmx4(ah, smb + qFrag + kt * 32);
            ldmx4(al, smb + OQL_E * 2 + qFrag + kt * 32);
            #pragma unroll
            for (int p = 0; p < 4; p++) {
                uint32_t bh[4];
                ldmx4(bh, kB + p * (16 * KVST * 2) + kt * 32);
                mma16h(s[2 * p],     ah, &bh[0]);
                mma16h(s[2 * p],     al, &bh[0]);
                mma16h(s[2 * p + 1], ah, &bh[2]);
                mma16h(s[2 * p + 1], al, &bh[2]);
            }
        }

        const int row0 = m0 + wid * 16 + g;
        const int row1 = row0 + 8;
        if (j0 + FBN - 1 > row0) {
            #pragma unroll
            for (int n = 0; n < 8; n++) {
                int col = j0 + n * 8 + 2 * tg;
                if (col     > row0) s[n][0] = -1e30f;
                if (col + 1 > row0) s[n][1] = -1e30f;
                if (col     > row1) s[n][2] = -1e30f;
                if (col + 1 > row1) s[n][3] = -1e30f;
            }
        }

        float rmax0 = -1e30f, rmax1 = -1e30f;
        #pragma unroll
        for (int n = 0; n < 8; n++) {
            rmax0 = fmaxf(rmax0, fmaxf(s[n][0], s[n][1]));
            rmax1 = fmaxf(rmax1, fmaxf(s[n][2], s[n][3]));
        }
        rmax0 = fmaxf(rmax0, __shfl_xor_sync(0xffffffffu, rmax0, 1));
        rmax0 = fmaxf(rmax0, __shfl_xor_sync(0xffffffffu, rmax0, 2));
        rmax1 = fmaxf(rmax1, __shfl_xor_sync(0xffffffffu, rmax1, 1));
        rmax1 = fmaxf(rmax1, __shfl_xor_sync(0xffffffffu, rmax1, 2));

        float mn0 = fmaxf(m_0, rmax0), mn1 = fmaxf(m_1, rmax1);
        float f0 = __expf(m_0 - mn0), f1 = __expf(m_1 - mn1);
        m_0 = mn0; m_1 = mn1;

        float rs0 = 0.f, rs1 = 0.f;
        #pragma unroll
        for (int n = 0; n < 8; n++) {
            s[n][0] = __expf(s[n][0] - mn0);
            s[n][1] = __expf(s[n][1] - mn0);
            s[n][2] = __expf(s[n][2] - mn1);
            s[n][3] = __expf(s[n][3] - mn1);
            rs0 += s[n][0] + s[n][1];
            rs1 += s[n][2] + s[n][3];
        }
        rs0 += __shfl_xor_sync(0xffffffffu, rs0, 1);
        rs0 += __shfl_xor_sync(0xffffffffu, rs0, 2);
        rs1 += __shfl_xor_sync(0xffffffffu, rs1, 1);
        rs1 += __shfl_xor_sync(0xffffffffu, rs1, 2);
        l_0 = l_0 * f0 + rs0;
        l_1 = l_1 * f1 + rs1;

        #pragma unroll
        for (int n = 0; n < 16; n++) {
            o[n][0] *= f0; o[n][1] *= f0;
            o[n][2] *= f1; o[n][3] *= f1;
        }

        // O += P V  (fp16 2-term: (Ph+Pl) x Vf)
        #pragma unroll
        for (int kt = 0; kt < 4; kt++) {
            uint32_t ph[4], pl[4];
            split2h(s[2 * kt][0],     s[2 * kt][1],     ph[0], pl[0]);
            split2h(s[2 * kt][2],     s[2 * kt][3],     ph[1], pl[1]);
            split2h(s[2 * kt + 1][0], s[2 * kt + 1][1], ph[2], pl[2]);
            split2h(s[2 * kt + 1][2], s[2 * kt + 1][3], ph[3], pl[3]);
            #pragma unroll
            for (int p = 0; p < 8; p++) {
                uint32_t bh[4];
                const uint32_t va = vB + kt * (16 * KVST * 2) + p * 32;
                ldmx4t(bh, va);
                mma16h(o[2 * p],     ph, &bh[0]);
                mma16h(o[2 * p],     pl, &bh[0]);
                mma16h(o[2 * p + 1], ph, &bh[2]);
                mma16h(o[2 * p + 1], pl, &bh[2]);
            }
        }
        __syncthreads();
    }

    // epilogue: single fp16 output for the O-projection
    const float il0 = 1.0f / l_0;
    const float il1 = 1.0f / l_1;
    const int row0 = m0 + wid * 16 + g;
    #pragma unroll
    for (int n = 0; n < 16; n++) {
        const int col = n * 8 + 2 * tg;
        __half2 h0 = __floats2half2_rn(o[n][0] * il0, o[n][1] * il0);
        Oo[((size_t)row0 * Q_SIZE + h * HD + col) >> 1] = *(uint32_t*)&h0;
        __half2 h1 = __floats2half2_rn(o[n][2] * il1, o[n][3] * il1);
        Oo[((size_t)(row0 + 8) * Q_SIZE + h * HD + col) >> 1] = *(uint32_t*)&h1;
    }
}

// ---------------------------------------------------------------------------
extern "C" void kernel_launch(void* const* d_in, const int* in_sizes, int n_in,
                              void* d_out, int out_size)
{
    const int*   positions = (const int*)d_in[0];
    const float* hidden    = (const float*)d_in[1];
    const float* w_qkv     = (const float*)d_in[2];
    const float* w_o       = (const float*)d_in[3];
    float* out = (float*)d_out;

    uint32_t *hid, *wqkv, *wo;
    uint32_t *qh, *ql, *kf, *vf, *ao;
    float2* rope_tab;
    cudaGetSymbolAddress((void**)&hid,  g_hid);
    cudaGetSymbolAddress((void**)&wqkv, g_wqkv);
    cudaGetSymbolAddress((void**)&wo,   g_wo);
    cudaGetSymbolAddress((void**)&qh, g_qh);
    cudaGetSymbolAddress((void**)&ql, g_ql);
    cudaGetSymbolAddress((void**)&kf, g_kf);
    cudaGetSymbolAddress((void**)&vf, g_vf);
    cudaGetSymbolAddress((void**)&ao, g_ao);
    cudaGetSymbolAddress((void**)&rope_tab, g_rope);

    const int GSM = NSTG * STG_ELEMS * 2;   // 107520
    cudaFuncSetAttribute(gemm_qkv_fused,
                         cudaFuncAttributeMaxDynamicSharedMemorySize, GSM);
    cudaFuncSetAttribute(gemm_fp16,
                         cudaFuncAttributeMaxDynamicSharedMemorySize, GSM);
    cudaFuncSetAttribute(attn_tc2_kernel,
                         cudaFuncAttributeMaxDynamicSharedMemorySize,
                         ATT_SMEM_BYTES);

    // 0) conversions + rope table
    rope_table_kernel<<<(T_SEQ * 64 + 255) / 256, 256>>>(positions, rope_tab);
    convert_h<<<2048, 256>>>((const float4*)hidden, (uint2*)hid,
                             T_SEQ * HIDDEN / 4);
    convert_h<<<4096, 256>>>((const float4*)w_qkv, (uint2*)wqkv,
                             HIDDEN * QKV_N / 4);
    convert_h<<<4096, 256>>>((const float4*)w_o, (uint2*)wo,
                             HIDDEN * HIDDEN / 4);

    // 1) QKV projection with fused (table-driven) RoPE epilogue
    gemm_qkv_fused<<<dim3(QKV_N / 128, T_SEQ / 128), 128, GSM>>>(
        (const __half*)hid, (const __half*)wqkv, rope_tab,
        qh, ql, kf, vf);

    // 2) Flash attention (all fp16: S 2-term, PV 2-term)
    attn_tc2_kernel<<<dim3(T_SEQ / FBM, NH), 256, ATT_SMEM_BYTES>>>(
        (const __half*)qh, (const __half*)ql,
        (const __half*)kf, (const __half*)vf,
        ao);

    // 3) Output projection (fp16)
    gemm_fp16<<<dim3(HIDDEN / 128, T_SEQ / 128), 128, GSM>>>(
        (const __half*)ao, (const __half*)wo, out, T_SEQ, HIDDEN, HIDDEN);
}

// round 15
// speedup vs baseline: 17.4242x; 1.1107x over previous
#include <cuda_runtime.h>
#include <cuda_bf16.h>
#include <cuda_fp16.h>
#include <math.h>
#include <stdint.h>

#define T_SEQ  2048
#define HIDDEN 4096
#define NH     32
#define NKV    8
#define HD     128
#define Q_SIZE  (NH * HD)              // 4096
#define KV_SIZE (NKV * HD)             // 1024
#define QKV_N   (Q_SIZE + 2 * KV_SIZE) // 6144
#define SCALE   0.08838834764831845f   // 128^-0.5

// ---------------------------------------------------------------------------
// Global scratch. No cudaMalloc allowed.
// ---------------------------------------------------------------------------
__device__ uint32_t g_hid[(size_t)T_SEQ * HIDDEN / 2];         // fp16
__device__ uint32_t g_wqkv[(size_t)HIDDEN * QKV_N / 2];        // fp16
__device__ uint32_t g_wo[(size_t)HIDDEN * HIDDEN / 2];         // fp16
__device__ uint32_t g_qf[(size_t)T_SEQ * Q_SIZE / 2];          // fp16 Q
__device__ uint32_t g_kf[(size_t)T_SEQ * KV_SIZE / 2];         // fp16 K
__device__ uint32_t g_vf[(size_t)T_SEQ * KV_SIZE / 2];         // fp16 V
__device__ uint32_t g_ao[(size_t)T_SEQ * Q_SIZE / 2];          // fp16 attn out
__device__ float2   g_rope[(size_t)T_SEQ * 64];                // (cos,sin)

// ---------------------------------------------------------------------------
// Helpers
// ---------------------------------------------------------------------------
__device__ __forceinline__ uint32_t smem_u32(const void* p) {
    uint32_t a;
    asm("{ .reg .u64 t; cvta.to.shared.u64 t, %1; cvt.u32.u64 %0, t; }"
        : "=r"(a) : "l"(p));
    return a;
}
// fp16 MMA (everything)
__device__ __forceinline__ void mma16h(float* c, const uint32_t* a,
                                       const uint32_t* b) {
    asm volatile(
        "mma.sync.aligned.m16n8k16.row.col.f32.f16.f16.f32 "
        "{%0,%1,%2,%3}, {%4,%5,%6,%7}, {%8,%9}, {%0,%1,%2,%3};"
        : "+f"(c[0]), "+f"(c[1]), "+f"(c[2]), "+f"(c[3])
        : "r"(a[0]), "r"(a[1]), "r"(a[2]), "r"(a[3]), "r"(b[0]), "r"(b[1]));
}
__device__ __forceinline__ void ldmx4(uint32_t* r, uint32_t addr) {
    asm volatile(
        "ldmatrix.sync.aligned.m8n8.x4.shared.b16 {%0,%1,%2,%3}, [%4];"
        : "=r"(r[0]), "=r"(r[1]), "=r"(r[2]), "=r"(r[3]) : "r"(addr));
}
__device__ __forceinline__ void ldmx4t(uint32_t* r, uint32_t addr) {
    asm volatile(
        "ldmatrix.sync.aligned.m8n8.x4.trans.shared.b16 {%0,%1,%2,%3}, [%4];"
        : "=r"(r[0]), "=r"(r[1]), "=r"(r[2]), "=r"(r[3]) : "r"(addr));
}
__device__ __forceinline__ void cpa16(uint32_t dst, const void* src) {
    asm volatile("cp.async.cg.shared.global [%0], [%1], 16;"
                 :: "r"(dst), "l"(src));
}
__device__ __forceinline__ void cpa_commit() {
    asm volatile("cp.async.commit_group;");
}
template <int N>
__device__ __forceinline__ void cpa_wait() {
    asm volatile("cp.async.wait_group %0;" :: "n"(N));
}

// ---------------------------------------------------------------------------
// fp32 -> fp16 (single rounding)
// ---------------------------------------------------------------------------
__global__ __launch_bounds__(256) void convert_h(
    const float4* __restrict__ src, uint2* __restrict__ dh, int n4)
{
    for (int i = blockIdx.x * blockDim.x + threadIdx.x; i < n4;
         i += gridDim.x * blockDim.x) {
        float4 v = src[i];
        __half2 a = __floats2half2_rn(v.x, v.y);
        __half2 b = __floats2half2_rn(v.z, v.w);
        dh[i] = make_uint2(*(uint32_t*)&a, *(uint32_t*)&b);
    }
}

// ---------------------------------------------------------------------------
// RoPE cos/sin table
// ---------------------------------------------------------------------------
__global__ __launch_bounds__(256) void rope_table_kernel(
    const int* __restrict__ positions, float2* __restrict__ tab)
{
    const int idx = blockIdx.x * blockDim.x + threadIdx.x;
    if (idx >= T_SEQ * 64) return;
    const int t = idx >> 6;
    const int i = idx & 63;
    double e = (double)(2 * i) / (double)HD;
    float invf = (float)pow(500000.0, -e);
    float s, c;
    sincosf((float)positions[t] * invf, &s, &c);
    tab[idx] = make_float2(c, s);
}

// ===========================================================================
// QKV GEMM with fused RoPE epilogue (table-driven).
// cols <4096 -> rope+scale -> qf (fp16); 4096..5119 -> rope -> kf (fp16);
// >=5120 -> vf (fp16).
// ===========================================================================
#define GBK 64
#define AST 72
#define BST 136
#define STG_B   (128 * AST)     // 9216 elems
#define STG_ELEMS (128 * AST + GBK * BST)   // 17920 elems = 35840 B
#define NSTG 3

__global__ __launch_bounds__(128, 2) void gemm_qkv_fused(
    const __half* __restrict__ A, const __half* __restrict__ B,
    const float2* __restrict__ rope_tab,
    uint32_t* __restrict__ qf, uint32_t* __restrict__ kf,
    uint32_t* __restrict__ vf)
{
    extern __shared__ __align__(16) __half sm[];
    const uint32_t smb = smem_u32(sm);

    const int tid  = threadIdx.x;
    const int wid  = tid >> 5;
    const int lane = tid & 31;
    const int g    = lane >> 2;
    const int tg   = lane & 3;
    const int wm   = (wid >> 1) * 64;
    const int wn   = (wid & 1) * 64;
    const int m0 = blockIdx.y * 128;
    const int n0 = blockIdx.x * 128;
    const int K = HIDDEN, N = QKV_N;

    const int l7  = lane & 7;
    const int l8  = (lane >> 3) & 1;
    const int l16 = lane >> 4;
    const uint32_t aFrag = (uint32_t)(((wm + l7 + l8 * 8) * AST + l16 * 8) * 2);
    const uint32_t bFrag = (uint32_t)(STG_B * 2) +
        (uint32_t)(((l7 + l8 * 8) * BST + wn + l16 * 8) * 2);

    float acc[4][8][4];
    #pragma unroll
    for (int i = 0; i < 4; i++)
        #pragma unroll
        for (int j = 0; j < 8; j++)
            #pragma unroll
            for (int q = 0; q < 4; q++) acc[i][j][q] = 0.f;

    const int KT = K / GBK;

    auto issue = [&](int kt, int s) {
        const int kk = kt * GBK;
        const uint32_t sb = smb + (uint32_t)(s * STG_ELEMS * 2);
        #pragma unroll
        for (int i = 0; i < 8; i++) {
            const int c = tid + i * 128;
            const int row = c >> 3, c8 = (c & 7) * 8;
            cpa16(sb + (row * AST + c8) * 2,
                  A + (size_t)(m0 + row) * K + kk + c8);
        }
        #pragma unroll
        for (int i = 0; i < 8; i++) {
            const int c = tid + i * 128;
            const int row = c >> 4, c8 = (c & 15) * 8;
            cpa16(sb + (STG_B + row * BST + c8) * 2,
                  B + (size_t)(kk + row) * N + n0 + c8);
        }
    };

    issue(0, 0); cpa_commit();
    issue(1, 1); cpa_commit();

    int stage = 0;
    for (int kt = 0; kt < KT; kt++) {
        cpa_wait<1>();
        __syncthreads();

        if (kt + 2 < KT) {
            int s2 = stage + 2; if (s2 >= NSTG) s2 -= NSTG;
            issue(kt + 2, s2);
        }
        cpa_commit();

        const uint32_t sb = smb + (uint32_t)(stage * STG_ELEMS * 2);
        const uint32_t aA = sb + aFrag;
        const uint32_t bA = sb + bFrag;

        uint32_t aF[2][4][4];
        #pragma unroll
        for (int mt = 0; mt < 4; mt++)
            ldmx4(aF[0][mt], aA + mt * (16 * AST * 2));

        #pragma unroll
        for (int ks = 0; ks < 4; ks++) {
            const int cur = ks & 1;
            uint32_t bh[4][4];
            #pragma unroll
            for (int pp = 0; pp < 4; pp++)
                ldmx4t(bh[pp], bA + ks * (16 * BST * 2) + pp * 32);
            if (ks < 3) {
                #pragma unroll
                for (int mt = 0; mt < 4; mt++)
                    ldmx4(aF[cur ^ 1][mt],
                          aA + mt * (16 * AST * 2) + (ks + 1) * 32);
            }
            #pragma unroll
            for (int mt = 0; mt < 4; mt++)
                #pragma unroll
                for (int nt = 0; nt < 8; nt++)
                    mma16h(acc[mt][nt], aF[cur][mt],
                           &bh[nt >> 1][(nt & 1) * 2]);
        }
        if (++stage == NSTG) stage = 0;
    }

    // ---- fused epilogue: table-driven rope + fp16 stores ----
    const int region = (n0 >= Q_SIZE + KV_SIZE) ? 2 : (n0 >= Q_SIZE ? 1 : 0);

    #pragma unroll
    for (int mt = 0; mt < 4; mt++) {
        const int rowA = m0 + wm + mt * 16 + g;
        const int rowB = rowA + 8;
        #pragma unroll
        for (int nt = 0; nt < 8; nt++) {
            const int col = n0 + wn + nt * 8 + tg * 2;
            const float x0a = acc[mt][nt][0], x1a = acc[mt][nt][1];
            const float x0b = acc[mt][nt][2], x1b = acc[mt][nt][3];
            if (region == 2) {
                const int c = col - (Q_SIZE + KV_SIZE);
                __half2 h0 = __floats2half2_rn(x0a, x1a);
                vf[((size_t)rowA * KV_SIZE + c) >> 1] = *(uint32_t*)&h0;
                __half2 h1 = __floats2half2_rn(x0b, x1b);
                vf[((size_t)rowB * KV_SIZE + c) >> 1] = *(uint32_t*)&h1;
            } else {
                const int fi = (col >> 1) & 63;
                const float2 ta = rope_tab[rowA * 64 + fi];
                const float2 tb = rope_tab[rowB * 64 + fi];
                float o1 = x0a * ta.x - x1a * ta.y;
                float o2 = x1a * ta.x + x0a * ta.y;
                float o3 = x0b * tb.x - x1b * tb.y;
                float o4 = x1b * tb.x + x0b * tb.y;
                if (region == 0) {
                    __half2 h0 = __floats2half2_rn(o1 * SCALE, o2 * SCALE);
                    qf[((size_t)rowA * Q_SIZE + col) >> 1] = *(uint32_t*)&h0;
                    __half2 h1 = __floats2half2_rn(o3 * SCALE, o4 * SCALE);
                    qf[((size_t)rowB * Q_SIZE + col) >> 1] = *(uint32_t*)&h1;
                } else {
                    const int c = col - Q_SIZE;
                    __half2 h0 = __floats2half2_rn(o1, o2);
                    kf[((size_t)rowA * KV_SIZE + c) >> 1] = *(uint32_t*)&h0;
                    __half2 h1 = __floats2half2_rn(o3, o4);
                    kf[((size_t)rowB * KV_SIZE + c) >> 1] = *(uint32_t*)&h1;
                }
            }
        }
    }
}

// ---------------------------------------------------------------------------
// Pure FP16 GEMM (O-projection): C[M,N] = A[M,K] @ B[K,N], fp32 out.
// ---------------------------------------------------------------------------
__global__ __launch_bounds__(128, 2) void gemm_fp16(
    const __half* __restrict__ A, const __half* __restrict__ B,
    float* __restrict__ C, int M, int N, int K)
{
    extern __shared__ __align__(16) __half sm[];
    const uint32_t smb = smem_u32(sm);

    const int tid  = threadIdx.x;
    const int wid  = tid >> 5;
    const int lane = tid & 31;
    const int g    = lane >> 2;
    const int tg   = lane & 3;
    const int wm   = (wid >> 1) * 64;
    const int wn   = (wid & 1) * 64;
    const int m0 = blockIdx.y * 128;
    const int n0 = blockIdx.x * 128;

    const int l7  = lane & 7;
    const int l8  = (lane >> 3) & 1;
    const int l16 = lane >> 4;
    const uint32_t aFrag = (uint32_t)(((wm + l7 + l8 * 8) * AST + l16 * 8) * 2);
    const uint32_t bFrag = (uint32_t)(STG_B * 2) +
        (uint32_t)(((l7 + l8 * 8) * BST + wn + l16 * 8) * 2);

    float acc[4][8][4];
    #pragma unroll
    for (int i = 0; i < 4; i++)
        #pragma unroll
        for (int j = 0; j < 8; j++)
            #pragma unroll
            for (int q = 0; q < 4; q++) acc[i][j][q] = 0.f;

    const int KT = K / GBK;

    auto issue = [&](int kt, int s) {
        const int kk = kt * GBK;
        const uint32_t sb = smb + (uint32_t)(s * STG_ELEMS * 2);
        #pragma unroll
        for (int i = 0; i < 8; i++) {
            const int c = tid + i * 128;
            const int row = c >> 3, c8 = (c & 7) * 8;
            cpa16(sb + (row * AST + c8) * 2,
                  A + (size_t)(m0 + row) * K + kk + c8);
        }
        #pragma unroll
        for (int i = 0; i < 8; i++) {
            const int c = tid + i * 128;
            const int row = c >> 4, c8 = (c & 15) * 8;
            cpa16(sb + (STG_B + row * BST + c8) * 2,
                  B + (size_t)(kk + row) * N + n0 + c8);
        }
    };

    issue(0, 0); cpa_commit();
    issue(1, 1); cpa_commit();

    int stage = 0;
    for (int kt = 0; kt < KT; kt++) {
        cpa_wait<1>();
        __syncthreads();

        if (kt + 2 < KT) {
            int s2 = stage + 2; if (s2 >= NSTG) s2 -= NSTG;
            issue(kt + 2, s2);
        }
        cpa_commit();

        const uint32_t sb = smb + (uint32_t)(stage * STG_ELEMS * 2);
        const uint32_t aA = sb + aFrag;
        const uint32_t bA = sb + bFrag;

        uint32_t aF[2][4][4];
        #pragma unroll
        for (int mt = 0; mt < 4; mt++)
            ldmx4(aF[0][mt], aA + mt * (16 * AST * 2));

        #pragma unroll
        for (int ks = 0; ks < 4; ks++) {
            const int cur = ks & 1;
            uint32_t bh[4][4];
            #pragma unroll
            for (int pp = 0; pp < 4; pp++)
                ldmx4t(bh[pp], bA + ks * (16 * BST * 2) + pp * 32);
            if (ks < 3) {
                #pragma unroll
                for (int mt = 0; mt < 4; mt++)
                    ldmx4(aF[cur ^ 1][mt],
                          aA + mt * (16 * AST * 2) + (ks + 1) * 32);
            }
            #pragma unroll
            for (int mt = 0; mt < 4; mt++)
                #pragma unroll
                for (int nt = 0; nt < 8; nt++)
                    mma16h(acc[mt][nt], aF[cur][mt],
                           &bh[nt >> 1][(nt & 1) * 2]);
        }
        if (++stage == NSTG) stage = 0;
    }

    #pragma unroll
    for (int mt = 0; mt < 4; mt++) {
        const int row = m0 + wm + mt * 16 + g;
        #pragma unroll
        for (int nt = 0; nt < 8; nt++) {
            const int col = n0 + wn + nt * 8 + tg * 2;
            *(float2*)&C[(size_t)row * N + col] =
                make_float2(acc[mt][nt][0], acc[mt][nt][1]);
            *(float2*)&C[(size_t)(row + 8) * N + col] =
                make_float2(acc[mt][nt][2], acc[mt][nt][3]);
        }
    }
}

// ---------------------------------------------------------------------------
// Tensor-core causal GQA flash attention — all fp16, 1-term S and PV.
// ---------------------------------------------------------------------------
#define FBM 128
#define FBN 64
#define KVST 136
#define KVB_E   17408                   // Q only (no lo)
#define KV_STG  17408                   // per stage: Kf, Vf
#define SV      8704
#define ATT_SMEM_BYTES ((KVB_E + 2 * KV_STG) * 2)   // 104448

__global__ __launch_bounds__(256, 1) void attn_tc2_kernel(
    const __half* __restrict__ Qf,
    const __half* __restrict__ Kf, const __half* __restrict__ Vf,
    uint32_t* __restrict__ Oo)
{
    extern __shared__ __align__(16) __half asmem[];
    const uint32_t smb = smem_u32(asmem);

    const int tid  = threadIdx.x;
    const int wid  = tid >> 5;
    const int lane = tid & 31;
    const int g    = lane >> 2;
    const int tg   = lane & 3;
    const int mt   = (gridDim.x - 1) - blockIdx.x;
    const int m0   = mt * FBM;
    const int h    = blockIdx.y;
    const int kh   = h >> 2;

    const int l7  = lane & 7;
    const int l8  = (lane >> 3) & 1;
    const int l16 = lane >> 4;

    const int lr = tid >> 4;
    const int lc = tid & 15;

    #pragma unroll
    for (int i = 0; i < 8; i++) {
        const int row = lr + i * 16;
        const size_t go = (size_t)(m0 + row) * Q_SIZE + h * HD + lc * 8;
        cpa16(smb + (row * KVST + lc * 8) * 2, Qf + go);
    }
    cpa_commit();

    auto issueKV = [&](int j0, int s) {
        const uint32_t sb = smb + (uint32_t)((KVB_E + s * KV_STG) * 2);
        #pragma unroll
        for (int i = 0; i < 4; i++) {
            const int row = lr + i * 16;
            const size_t go = (size_t)(j0 + row) * KV_SIZE + kh * HD + lc * 8;
            const uint32_t so = (row * KVST + lc * 8) * 2;
            cpa16(sb + so, Kf + go);
            cpa16(sb + SV * 2 + so, Vf + go);
        }
    };

    issueKV(0, 0);
    cpa_commit();

    float o[16][4];
    #pragma unroll
    for (int n = 0; n < 16; n++)
        #pragma unroll
        for (int q = 0; q < 4; q++) o[n][q] = 0.f;
    float m_0 = -1e30f, m_1 = -1e30f, l_0 = 0.f, l_1 = 0.f;

    const uint32_t qFrag =
        (uint32_t)(((wid * 16 + l7 + l8 * 8) * KVST + l16 * 8) * 2);
    const uint32_t kFrag =
        (uint32_t)(((l7 + l16 * 8) * KVST + l8 * 8) * 2);
    const uint32_t vFrag =
        (uint32_t)(((l7 + l8 * 8) * KVST + l16 * 8) * 2);

    const int ntiles = m0 / FBN + 2;

    for (int jt = 0; jt < ntiles; jt++) {
        if (jt + 1 < ntiles) issueKV((jt + 1) * FBN, (jt + 1) & 1);
        cpa_commit();
        cpa_wait<1>();
        __syncthreads();

        const int j0 = jt * FBN;
        const uint32_t sb = smb + (uint32_t)((KVB_E + (jt & 1) * KV_STG) * 2);
        const uint32_t kB = sb + kFrag;
        const uint32_t vB = sb + SV * 2 + vFrag;

        float s[8][4];
        #pragma unroll
        for (int n = 0; n < 8; n++)
            #pragma unroll
            for (int q = 0; q < 4; q++) s[n][q] = 0.f;

        #pragma unroll
        for (int kt = 0; kt < 8; kt++) {
            uint32_t ah[4];
            ldmx4(ah, smb + qFrag + kt * 32);
            #pragma unroll
            for (int p = 0; p < 4; p++) {
                uint32_t bh[4];
                ldmx4(bh, kB + p * (16 * KVST * 2) + kt * 32);
                mma16h(s[2 * p],     ah, &bh[0]);
                mma16h(s[2 * p + 1], ah, &bh[2]);
            }
        }

        const int row0 = m0 + wid * 16 + g;
        const int row1 = row0 + 8;
        if (j0 + FBN - 1 > row0) {
            #pragma unroll
            for (int n = 0; n < 8; n++) {
                int col = j0 + n * 8 + 2 * tg;
                if (col     > row0) s[n][0] = -1e30f;
                if (col + 1 > row0) s[n][1] = -1e30f;
                if (col     > row1) s[n][2] = -1e30f;
                if (col + 1 > row1) s[n][3] = -1e30f;
            }
        }

        float rmax0 = -1e30f, rmax1 = -1e30f;
        #pragma unroll
        for (int n = 0; n < 8; n++) {
            rmax0 = fmaxf(rmax0, fmaxf(s[n][0], s[n][1]));
            rmax1 = fmaxf(rmax1, fmaxf(s[n][2], s[n][3]));
        }
        rmax0 = fmaxf(rmax0, __shfl_xor_sync(0xffffffffu, rmax0, 1));
        rmax0 = fmaxf(rmax0, __shfl_xor_sync(0xffffffffu, rmax0, 2));
        rmax1 = fmaxf(rmax1, __shfl_xor_sync(0xffffffffu, rmax1, 1));
        rmax1 = fmaxf(rmax1, __shfl_xor_sync(0xffffffffu, rmax1, 2));

        float mn0 = fmaxf(m_0, rmax0), mn1 = fmaxf(m_1, rmax1);
        float f0 = __expf(m_0 - mn0), f1 = __expf(m_1 - mn1);
        m_0 = mn0; m_1 = mn1;

        float rs0 = 0.f, rs1 = 0.f;
        #pragma unroll
        for (int n = 0; n < 8; n++) {
            s[n][0] = __expf(s[n][0] - mn0);
            s[n][1] = __expf(s[n][1] - mn0);
            s[n][2] = __expf(s[n][2] - mn1);
            s[n][3] = __expf(s[n][3] - mn1);
            rs0 += s[n][0] + s[n][1];
            rs1 += s[n][2] + s[n][3];
        }
        rs0 += __shfl_xor_sync(0xffffffffu, rs0, 1);
        rs0 += __shfl_xor_sync(0xffffffffu, rs0, 2);
        rs1 += __shfl_xor_sync(0xffffffffu, rs1, 1);
        rs1 += __shfl_xor_sync(0xffffffffu, rs1, 2);
        l_0 = l_0 * f0 + rs0;
        l_1 = l_1 * f1 + rs1;

        #pragma unroll
        for (int n = 0; n < 16; n++) {
            o[n][0] *= f0; o[n][1] *= f0;
            o[n][2] *= f1; o[n][3] *= f1;
        }

        // O += P V  (1-term fp16)
        #pragma unroll
        for (int kt = 0; kt < 4; kt++) {
            uint32_t ph[4];
            __half2 t;
            t = __floats2half2_rn(s[2 * kt][0],     s[2 * kt][1]);
            ph[0] = *(uint32_t*)&t;
            t = __floats2half2_rn(s[2 * kt][2],     s[2 * kt][3]);
            ph[1] = *(uint32_t*)&t;
            t = __floats2half2_rn(s[2 * kt + 1][0], s[2 * kt + 1][1]);
            ph[2] = *(uint32_t*)&t;
            t = __floats2half2_rn(s[2 * kt + 1][2], s[2 * kt + 1][3]);
            ph[3] = *(uint32_t*)&t;
            #pragma unroll
            for (int p = 0; p < 8; p++) {
                uint32_t bh[4];
                const uint32_t va = vB + kt * (16 * KVST * 2) + p * 32;
                ldmx4t(bh, va);
                mma16h(o[2 * p],     ph, &bh[0]);
                mma16h(o[2 * p + 1], ph, &bh[2]);
            }
        }
        __syncthreads();
    }

    // epilogue: single fp16 output for the O-projection
    const float il0 = 1.0f / l_0;
    const float il1 = 1.0f / l_1;
    const int row0 = m0 + wid * 16 + g;
    #pragma unroll
    for (int n = 0; n < 16; n++) {
        const int col = n * 8 + 2 * tg;
        __half2 h0 = __floats2half2_rn(o[n][0] * il0, o[n][1] * il0);
        Oo[((size_t)row0 * Q_SIZE + h * HD + col) >> 1] = *(uint32_t*)&h0;
        __half2 h1 = __floats2half2_rn(o[n][2] * il1, o[n][3] * il1);
        Oo[((size_t)(row0 + 8) * Q_SIZE + h * HD + col) >> 1] = *(uint32_t*)&h1;
    }
}

// ---------------------------------------------------------------------------
extern "C" void kernel_launch(void* const* d_in, const int* in_sizes, int n_in,
                              void* d_out, int out_size)
{
    const int*   positions = (const int*)d_in[0];
    const float* hidden    = (const float*)d_in[1];
    const float* w_qkv     = (const float*)d_in[2];
    const float* w_o       = (const float*)d_in[3];
    float* out = (float*)d_out;

    uint32_t *hid, *wqkv, *wo;
    uint32_t *qf, *kf, *vf, *ao;
    float2* rope_tab;
    cudaGetSymbolAddress((void**)&hid,  g_hid);
    cudaGetSymbolAddress((void**)&wqkv, g_wqkv);
    cudaGetSymbolAddress((void**)&wo,   g_wo);
    cudaGetSymbolAddress((void**)&qf, g_qf);
    cudaGetSymbolAddress((void**)&kf, g_kf);
    cudaGetSymbolAddress((void**)&vf, g_vf);
    cudaGetSymbolAddress((void**)&ao, g_ao);
    cudaGetSymbolAddress((void**)&rope_tab, g_rope);

    const int GSM = NSTG * STG_ELEMS * 2;   // 107520
    cudaFuncSetAttribute(gemm_qkv_fused,
                         cudaFuncAttributeMaxDynamicSharedMemorySize, GSM);
    cudaFuncSetAttribute(gemm_fp16,
                         cudaFuncAttributeMaxDynamicSharedMemorySize, GSM);
    cudaFuncSetAttribute(attn_tc2_kernel,
                         cudaFuncAttributeMaxDynamicSharedMemorySize,
                         ATT_SMEM_BYTES);

    // 0) conversions + rope table
    rope_table_kernel<<<(T_SEQ * 64 + 255) / 256, 256>>>(positions, rope_tab);
    convert_h<<<2048, 256>>>((const float4*)hidden, (uint2*)hid,
                             T_SEQ * HIDDEN / 4);
    convert_h<<<4096, 256>>>((const float4*)w_qkv, (uint2*)wqkv,
                             HIDDEN * QKV_N / 4);
    convert_h<<<4096, 256>>>((const float4*)w_o, (uint2*)wo,
                             HIDDEN * HIDDEN / 4);

    // 1) QKV projection with fused (table-driven) RoPE epilogue
    gemm_qkv_fused<<<dim3(QKV_N / 128, T_SEQ / 128), 128, GSM>>>(
        (const __half*)hid, (const __half*)wqkv, rope_tab,
        qf, kf, vf);

    // 2) Flash attention (1-term fp16 S and PV)
    attn_tc2_kernel<<<dim3(T_SEQ / FBM, NH), 256, ATT_SMEM_BYTES>>>(
        (const __half*)qf, (const __half*)kf, (const __half*)vf,
        ao);

    // 3) Output projection (fp16)
    gemm_fp16<<<dim3(HIDDEN / 128, T_SEQ / 128), 128, GSM>>>(
        (const __half*)ao, (const __half*)wo, out, T_SEQ, HIDDEN, HIDDEN);
}